// round 4
// baseline (speedup 1.0000x reference)
#include <cuda_runtime.h>
#include <stdint.h>

#define ND    10000
#define DIM   64
#define SS    16
#define EMAX  1000000
#define NBLK  296
#define NTHR  512
#define NWPB  16                 // warps per block
#define NWARP (NBLK*NWPB)
#define CHUNK 34                 // ceil(ND/NBLK)
#define KEYCAP 160               // per-warp smem key cache (deg ~ 100 +/- 10)

typedef unsigned int u32;
typedef unsigned long long u64;

// ---------------------------------------------------------------- threefry2x32
__host__ __device__ __forceinline__ void threefry(u32 k0, u32 k1, u32 x0, u32 x1,
                                                  u32& o0, u32& o1) {
#ifdef __CUDA_ARCH__
#define TFR(a,b,r) { a += b; b = __funnelshift_l(b, b, r); b ^= a; }
#else
#define TFR(a,b,r) { a += b; b = (b<<r)|(b>>(32-r)); b ^= a; }
#endif
    u32 ks2 = k0 ^ k1 ^ 0x1BD11BDAu;
    x0 += k0; x1 += k1;
    TFR(x0,x1,13); TFR(x0,x1,15); TFR(x0,x1,26); TFR(x0,x1,6);
    x0 += k1; x1 += ks2 + 1u;
    TFR(x0,x1,17); TFR(x0,x1,29); TFR(x0,x1,16); TFR(x0,x1,24);
    x0 += ks2; x1 += k0 + 2u;
    TFR(x0,x1,13); TFR(x0,x1,15); TFR(x0,x1,26); TFR(x0,x1,6);
    x0 += k0; x1 += k1 + 3u;
    TFR(x0,x1,17); TFR(x0,x1,29); TFR(x0,x1,16); TFR(x0,x1,24);
    x0 += k1; x1 += ks2 + 4u;
    TFR(x0,x1,13); TFR(x0,x1,15); TFR(x0,x1,26); TFR(x0,x1,6);
    x0 += ks2; x1 += k0 + 5u;
    o0 = x0; o1 = x1;
#undef TFR
}
__device__ __forceinline__ u32 rbits_stream(u32 kx, u32 ky, int i) {
    u32 a, b; threefry(kx, ky, 0u, (u32)i, a, b);
    return a ^ b;
}

// ---------------------------------------------------------------- scratch
__device__ int   g_deg[ND];
__device__ int   g_cursor[ND];
__device__ int   g_off[ND];
__device__ u64   g_lin[EMAX];        // head(14) | rank(23) | edge(20)
__device__ u64   g_key[EMAX];        // rank(23) | edge(20), CSR-ordered
__device__ int   g_bsum[NBLK];
__device__ float g_neigh[ND*DIM];
__device__ float g_y[ND*DIM];
__device__ float g_psum[NBLK*DIM];
__device__ float g_psq[NBLK*DIM];
__device__ float g_mean[DIM];
__device__ float g_rstd[DIM];
__device__ float g_w2s[DIM];
__device__ float g_b2s;
__device__ u32   g_bar_count;
__device__ u32   g_bar_gen;

// ---------------------------------------------------------------- init kernel
__global__ void init_kernel() {
    int i = blockIdx.x * blockDim.x + threadIdx.x;
    if (i < ND) { g_deg[i] = 0; g_cursor[i] = 0; }
    if (i == ND) { g_bar_count = 0; g_bar_gen = 0; }
}

// ---------------------------------------------------------------- f32x2 helpers
__device__ __forceinline__ u64 pack2(float lo, float hi) {
    u64 r;
    asm("mov.b64 %0, {%1, %2};" : "=l"(r) : "f"(lo), "f"(hi));
    return r;
}
__device__ __forceinline__ void unpack2(u64 v, float& lo, float& hi) {
    asm("mov.b64 {%0, %1}, %2;" : "=f"(lo), "=f"(hi) : "l"(v));
}
__device__ __forceinline__ void fma2(u64& acc, u64 a, u64 b) {
    asm("fma.rn.f32x2 %0, %1, %2, %0;" : "+l"(acc) : "l"(a), "l"(b));
}
__device__ __forceinline__ u64 add2(u64 a, u64 b) {
    u64 r;
    asm("add.rn.f32x2 %0, %1, %2;" : "=l"(r) : "l"(a), "l"(b));
    return r;
}

// ---------------------------------------------------------------- shared layout
#define SH_BYTES (38*1024 + 512)

__global__ void __launch_bounds__(NTHR, 2)
mega_kernel(const int* __restrict__ DKG,
            const float* __restrict__ drug_emb,
            const float* __restrict__ rel_emb,
            const float* __restrict__ tail_emb,
            const float* __restrict__ W1,
            const float* __restrict__ b1,
            const float* __restrict__ W2,
            const float* __restrict__ b2,
            const float* __restrict__ Wc,
            const float* __restrict__ bc,
            const float* __restrict__ gamma,
            const float* __restrict__ beta,
            float* __restrict__ out,
            int E, u32 k1x, u32 k1y, u32 kLx, u32 kLy) {
    __shared__ __align__(16) char sh_raw[SH_BYTES];
    __shared__ u32 s_gen;

    const int tid  = threadIdx.x;
    const int bid  = blockIdx.x;
    const int gtid = bid * NTHR + tid;
    const int nth  = NBLK * NTHR;
    const int lane = tid & 31;
    const int wid  = tid >> 5;

    if (tid == 0) s_gen = 0;

    auto gsync = [&]() {
        __syncthreads();
        if (tid == 0) {
            u32 target = s_gen + 1;
            __threadfence();
            u32 t = atomicAdd(&g_bar_count, 1u);
            if (t == (u32)NBLK - 1) {
                atomicExch(&g_bar_count, 0u);
                __threadfence();
                atomicExch(&g_bar_gen, target);
            } else {
                volatile u32* vg = &g_bar_gen;
                while (*vg < target) { }
            }
            __threadfence();
            s_gen = target;
        }
        __syncthreads();
    };

    // ============ phase 1: histogram + threefry key (overlapped) ============
    if (bid == NBLK - 1) {
        if (tid < DIM) {
            float s = 0.f;
            for (int j = 0; j < DIM; j++) s += W2[tid*DIM + j];
            g_w2s[tid] = s;
        }
        if (tid == DIM) {
            float s = 0.f;
            for (int j = 0; j < DIM; j++) s += b2[j];
            g_b2s = s;
        }
    }
    for (int e = gtid; e < E; e += nth) {
        int h = DKG[3*e];
        u32 bits = rbits_stream(k1x, k1y, e);
        g_lin[e] = ((u64)h << 50) | (((u64)(bits >> 9)) << 20) | (u32)e;
        atomicAdd(&g_deg[h], 1);
    }
    gsync();

    // ============ phase 2: exclusive scan of deg -> off (distributed prefix) ============
    {
        int* s_scan = (int*)sh_raw;              // 64 ints
        int* s_red  = (int*)(sh_raw + 512);      // 512 ints
        const int d0 = bid * CHUNK;
        int myv = 0;
        if (tid < 64) s_scan[tid] = 0;
        __syncthreads();
        if (tid < CHUNK && d0 + tid < ND) { myv = g_deg[d0 + tid]; s_scan[tid] = myv; }
        __syncthreads();
        #pragma unroll
        for (int ofs = 1; ofs < 64; ofs <<= 1) {
            int v = (tid < 64 && tid >= ofs) ? s_scan[tid - ofs] : 0;
            __syncthreads();
            if (tid < 64) s_scan[tid] += v;
            __syncthreads();
        }
        if (tid == 0) g_bsum[bid] = s_scan[63];
        gsync();
        // every block computes its own prefix over g_bsum
        s_red[tid] = (tid < bid) ? g_bsum[tid] : 0;
        __syncthreads();
        #pragma unroll
        for (int ofs = 256; ofs > 0; ofs >>= 1) {
            if (tid < ofs) s_red[tid] += s_red[tid + ofs];
            __syncthreads();
        }
        int prefix = s_red[0];
        __syncthreads();
        if (tid < CHUNK && d0 + tid < ND)
            g_off[d0 + tid] = prefix + s_scan[tid] - myv;
    }
    gsync();

    // ============ phase 3: scatter keys into CSR (pure memory) ============
    for (int e = gtid; e < E; e += nth) {
        u64 v = g_lin[e];
        int h = (int)(v >> 50);
        int pos = g_off[h] + atomicAdd(&g_cursor[h], 1);
        g_key[pos] = v & 0x3FFFFFFFFFFFFULL;
    }
    gsync();

    // ============ phase 4+5+6 fused: select top16 + score + aggregate ============
    {
        u64*   w1p   = (u64*)sh_raw;                         // 2048 u64 = 16KB
        float* b1s   = (float*)(sh_raw + 16384);
        float* w2ss  = (float*)(sh_raw + 16640);
        int*   ssel  = (int*)(sh_raw + 16896) + wid * 16;
        u64*   wkeys = (u64*)(sh_raw + 17920) + wid * KEYCAP;

        for (int i = tid; i < 64*32; i += NTHR) {
            int r = i >> 5, c = i & 31;
            w1p[i] = pack2(W1[r*DIM + c], W1[r*DIM + c + 32]);
        }
        if (tid < DIM)        b1s[tid] = b1[tid];
        else if (tid < 2*DIM) w2ss[tid - DIM] = g_w2s[tid - DIM];
        __syncthreads();
        const float b2s = g_b2s;
        const u64 zero2 = pack2(0.f, 0.f);

        for (int d = bid * NWPB + wid; d < ND; d += NWARP) {
            const int off  = g_off[d];
            const int degd = g_deg[d];
            const int cnt  = (degd < SS) ? degd : SS;

            if (cnt > 0) {
                // ---- selection: top-16 smallest keys, rank-ordered ----
                if (degd <= KEYCAP) {
                    for (int t = lane; t < degd; t += 32) wkeys[t] = g_key[off + t];
                    __syncwarp();
                    for (int t = lane; t < degd; t += 32) {
                        u64 k = wkeys[t];
                        int rank = 0;
                        for (int j = 0; j < degd; j++) rank += (wkeys[j] < k);
                        if (rank < SS) ssel[rank] = (int)(k & 0xFFFFFu);
                    }
                } else {
                    for (int t = lane; t < degd; t += 32) {
                        u64 k = g_key[off + t];
                        int rank = 0;
                        for (int j = 0; j < degd; j++) rank += (g_key[off + j] < k);
                        if (rank < SS) ssel[rank] = (int)(k & 0xFFFFFu);
                    }
                }
                __syncwarp();

                int tail = 0, rel = 0;
                if (lane < cnt) {
                    int e = ssel[lane];
                    tail = DKG[3*e + 1];
                    rel  = DKG[3*e + 2];
                }
                __syncwarp();

                const float de0 = drug_emb[d*DIM + lane];
                const float de1 = drug_emb[d*DIM + 32 + lane];
                const u64 binit = pack2(b1s[lane], b1s[lane + 32]);
                const float w20 = w2ss[lane], w21 = w2ss[lane + 32];

                float myscore = 0.f;
                for (int k = 0; k < cnt; k += 2) {
                    const int kB = (k + 1 < cnt) ? (k + 1) : k;
                    int relA = __shfl_sync(0xffffffffu, rel, k);
                    int relB = __shfl_sync(0xffffffffu, rel, kB);
                    float ha0 = de0 * rel_emb[relA*DIM + lane];
                    float ha1 = de1 * rel_emb[relA*DIM + 32 + lane];
                    float hb0 = de0 * rel_emb[relB*DIM + lane];
                    float hb1 = de1 * rel_emb[relB*DIM + 32 + lane];
                    u64 aA0 = binit, aA1 = zero2, aB0 = binit, aB1 = zero2;
                    #pragma unroll
                    for (int i = 0; i < 32; i += 2) {
                        float va = __shfl_sync(0xffffffffu, ha0, i);
                        float vb = __shfl_sync(0xffffffffu, hb0, i);
                        u64 w = w1p[i*32 + lane];
                        fma2(aA0, pack2(va, va), w);
                        fma2(aB0, pack2(vb, vb), w);
                        va = __shfl_sync(0xffffffffu, ha0, i + 1);
                        vb = __shfl_sync(0xffffffffu, hb0, i + 1);
                        w = w1p[(i + 1)*32 + lane];
                        fma2(aA1, pack2(va, va), w);
                        fma2(aB1, pack2(vb, vb), w);
                    }
                    #pragma unroll
                    for (int i = 0; i < 32; i += 2) {
                        float va = __shfl_sync(0xffffffffu, ha1, i);
                        float vb = __shfl_sync(0xffffffffu, hb1, i);
                        u64 w = w1p[(i + 32)*32 + lane];
                        fma2(aA0, pack2(va, va), w);
                        fma2(aB0, pack2(vb, vb), w);
                        va = __shfl_sync(0xffffffffu, ha1, i + 1);
                        vb = __shfl_sync(0xffffffffu, hb1, i + 1);
                        w = w1p[(i + 33)*32 + lane];
                        fma2(aA1, pack2(va, va), w);
                        fma2(aB1, pack2(vb, vb), w);
                    }
                    float a0, a1, c0, c1;
                    unpack2(add2(aA0, aA1), a0, a1);
                    unpack2(add2(aB0, aB1), c0, c1);
                    float pA = (1.f / (1.f + __expf(-a0))) * w20
                             + (1.f / (1.f + __expf(-a1))) * w21;
                    float pB = (1.f / (1.f + __expf(-c0))) * w20
                             + (1.f / (1.f + __expf(-c1))) * w21;
                    #pragma unroll
                    for (int o = 16; o; o >>= 1) {
                        pA += __shfl_xor_sync(0xffffffffu, pA, o);
                        pB += __shfl_xor_sync(0xffffffffu, pB, o);
                    }
                    if (lane == k) myscore = pA + b2s;
                    if (kB != k && lane == kB) myscore = pB + b2s;
                }

                // ---- aggregation (rank order, then extras) ----
                float acc0 = 0.f, acc1 = 0.f;
                for (int k = 0; k < cnt; k++) {
                    float sc = __shfl_sync(0xffffffffu, myscore, k);
                    int   t  = __shfl_sync(0xffffffffu, tail, k);
                    acc0 = fmaf(sc, tail_emb[t*DIM + lane], acc0);
                    acc1 = fmaf(sc, tail_emb[t*DIM + 32 + lane], acc1);
                }
                if (degd < SS) {
                    for (int s = 0; s < SS - degd; s++) {
                        u32 bits = rbits_stream(kLx, kLy, d*SS + s);
                        int idx = (int)((bits % 2147483647u) % (u32)degd);
                        float sc = __shfl_sync(0xffffffffu, myscore, idx);
                        int   t  = __shfl_sync(0xffffffffu, tail, idx);
                        acc0 = fmaf(sc, tail_emb[t*DIM + lane], acc0);
                        acc1 = fmaf(sc, tail_emb[t*DIM + 32 + lane], acc1);
                    }
                }
                g_neigh[d*DIM + lane]      = acc0;
                g_neigh[d*DIM + 32 + lane] = acc1;
            } else {
                g_neigh[d*DIM + lane]      = 0.f;
                g_neigh[d*DIM + 32 + lane] = 0.f;
            }
        }
    }
    gsync();

    // ============ phase 7: y = [drug_emb, neigh] @ Wc + bc (f32x2, 2 rows/thread) ============
    {
        u64*   wcp = (u64*)sh_raw;                   // 128*32 u64 = 32KB
        float* red = (float*)(sh_raw + 32768);       // 512 floats
        for (int i = tid; i < 2*DIM*32; i += NTHR) {
            int r = i >> 5, c = i & 31;
            wcp[i] = pack2(Wc[r*DIM + c], Wc[r*DIM + c + 32]);
        }
        __syncthreads();
        const int sub = tid >> 5;                    // 0..15
        const int o = lane;
        const u64 bcv = pack2(bc[o], bc[o + 32]);
        float S0 = 0.f, S1 = 0.f, Q0 = 0.f, Q1 = 0.f;
        const int NR32 = (ND + 31) / 32;             // 313
        for (int r32 = bid; r32 < NR32; r32 += NBLK) {
            int row0 = r32*32 + sub;
            int row1 = row0 + 16;
            bool has1 = (row1 < ND);                 // row0 < ND always (r32*32+15 <= 9999)
            const float* de0p = drug_emb + row0*DIM;
            const float* ne0p = g_neigh + row0*DIM;
            const float* de1p = drug_emb + (has1 ? row1 : row0)*DIM;
            const float* ne1p = g_neigh + (has1 ? row1 : row0)*DIM;
            u64 accR0 = bcv, accR1 = bcv;
            #pragma unroll
            for (int i = 0; i < DIM; i++) {
                u64 w = wcp[i*32 + o];
                float v0 = de0p[i], v1 = de1p[i];
                fma2(accR0, pack2(v0, v0), w);
                fma2(accR1, pack2(v1, v1), w);
            }
            #pragma unroll
            for (int i = 0; i < DIM; i++) {
                u64 w = wcp[(DIM + i)*32 + o];
                float v0 = ne0p[i], v1 = ne1p[i];
                fma2(accR0, pack2(v0, v0), w);
                fma2(accR1, pack2(v1, v1), w);
            }
            float y00, y01, y10, y11;
            unpack2(accR0, y00, y01);
            unpack2(accR1, y10, y11);
            g_y[row0*DIM + o]      = y00;
            g_y[row0*DIM + 32 + o] = y01;
            S0 += y00; S1 += y01; Q0 += y00*y00; Q1 += y01*y01;
            if (has1) {
                g_y[row1*DIM + o]      = y10;
                g_y[row1*DIM + 32 + o] = y11;
                S0 += y10; S1 += y11; Q0 += y10*y10; Q1 += y11*y11;
            }
        }
        red[tid] = S0;
        __syncthreads();
        if (tid < 32) { float s = 0.f;
            #pragma unroll
            for (int p = 0; p < 16; p++) s += red[p*32 + lane];
            g_psum[bid*DIM + lane] = s; }
        __syncthreads();
        red[tid] = S1;
        __syncthreads();
        if (tid < 32) { float s = 0.f;
            #pragma unroll
            for (int p = 0; p < 16; p++) s += red[p*32 + lane];
            g_psum[bid*DIM + 32 + lane] = s; }
        __syncthreads();
        red[tid] = Q0;
        __syncthreads();
        if (tid < 32) { float s = 0.f;
            #pragma unroll
            for (int p = 0; p < 16; p++) s += red[p*32 + lane];
            g_psq[bid*DIM + lane] = s; }
        __syncthreads();
        red[tid] = Q1;
        __syncthreads();
        if (tid < 32) { float s = 0.f;
            #pragma unroll
            for (int p = 0; p < 16; p++) s += red[p*32 + lane];
            g_psq[bid*DIM + 32 + lane] = s; }
    }
    gsync();

    // ============ phase 8: final BN stats (block 0) ============
    if (bid == 0) {
        float* ss = (float*)sh_raw;
        float* qq = (float*)(sh_raw + 2048);
        const int col = tid & 63, part = tid >> 6;
        float s = 0.f, q = 0.f;
        for (int b = part; b < NBLK; b += 8) { s += g_psum[b*DIM + col]; q += g_psq[b*DIM + col]; }
        ss[tid] = s; qq[tid] = q;
        __syncthreads();
        if (tid < 64) {
            float S = 0.f, Q = 0.f;
            #pragma unroll
            for (int p = 0; p < 8; p++) { S += ss[p*64 + col]; Q += qq[p*64 + col]; }
            float mean = S / (float)ND;
            float var  = Q / (float)ND - mean * mean;
            g_mean[col] = mean;
            g_rstd[col] = rsqrtf(var + 1e-5f);
        }
    }
    gsync();

    // ============ phase 9: normalize + write out (float4) ============
    {
        const float4* y4 = (const float4*)g_y;
        float4* o4 = (float4*)out;
        for (int t = gtid; t < ND*DIM/4; t += nth) {
            int c = (t*4) & 63;
            float4 v = y4[t];
            float4 r;
            r.x = gamma[c+0] * (v.x - g_mean[c+0]) * g_rstd[c+0] + beta[c+0];
            r.y = gamma[c+1] * (v.y - g_mean[c+1]) * g_rstd[c+1] + beta[c+1];
            r.z = gamma[c+2] * (v.z - g_mean[c+2]) * g_rstd[c+2] + beta[c+2];
            r.w = gamma[c+3] * (v.w - g_mean[c+3]) * g_rstd[c+3] + beta[c+3];
            o4[t] = r;
        }
    }
}

// ---------------------------------------------------------------- host
static void compute_keys(u32& k1x, u32& k1y, u32& kLx, u32& kLy) {
    u32 a, b, c, d, e, f;
    threefry(0u, 42u, 0u, 0u, a, b);   // k1 = split(key(42))[0]
    k1x = a; k1y = b;
    threefry(0u, 42u, 0u, 1u, c, d);   // k2 = split(key(42))[1]
    threefry(c, d, 0u, 1u, e, f);      // split(k2)[1]
    kLx = e; kLy = f;
}

extern "C" void kernel_launch(void* const* d_in, const int* in_sizes, int n_in,
                              void* d_out, int out_size) {
    const float* HF       = (const float*)d_in[0];
    const float* X        = (const float*)d_in[1];
    const float* drug_emb = (const float*)d_in[2];
    const float* rel_emb  = (const float*)d_in[3];
    const float* tail_emb = (const float*)d_in[4];
    const float* W1       = (const float*)d_in[5];
    const float* b1       = (const float*)d_in[6];
    const float* W2       = (const float*)d_in[7];
    const float* b2       = (const float*)d_in[8];
    const float* Wc       = (const float*)d_in[9];
    const float* bc       = (const float*)d_in[10];
    const float* gamma    = (const float*)d_in[11];
    const float* beta     = (const float*)d_in[12];
    const int*   DKG      = (const int*)d_in[13];
    int E    = in_sizes[13] / 3;
    int hf_n = in_sizes[0];
    int x_n  = in_sizes[1];
    float* out = (float*)d_out;

    u32 k1x, k1y, kLx, kLy;
    compute_keys(k1x, k1y, kLx, kLy);

    cudaMemcpyAsync(out, HF, (size_t)hf_n * sizeof(float), cudaMemcpyDeviceToDevice, 0);
    cudaMemcpyAsync(out + hf_n + ND*DIM, X, (size_t)x_n * sizeof(float),
                    cudaMemcpyDeviceToDevice, 0);

    init_kernel<<<(ND + 256)/256, 256>>>();
    mega_kernel<<<NBLK, NTHR>>>(DKG, drug_emb, rel_emb, tail_emb, W1, b1, W2, b2,
                                Wc, bc, gamma, beta, out + hf_n,
                                E, k1x, k1y, kLx, kLy);
}

// round 5
// speedup vs baseline: 1.1999x; 1.1999x over previous
#include <cuda_runtime.h>
#include <stdint.h>

#define ND    10000
#define DIM   64
#define SS    16
#define EMAX  1000000
#define NBLK  296
#define NTHR  512
#define NWPB  16                 // warps per block
#define NWARP (NBLK*NWPB)
#define CAP   192                // per-drug bucket capacity (deg ~ Poisson(100))
#define KEYCAP 192               // per-warp smem key cache
#define OVFCAP 8192

typedef unsigned int u32;
typedef unsigned long long u64;

// ---------------------------------------------------------------- threefry2x32
__host__ __device__ __forceinline__ void threefry(u32 k0, u32 k1, u32 x0, u32 x1,
                                                  u32& o0, u32& o1) {
#ifdef __CUDA_ARCH__
#define TFR(a,b,r) { a += b; b = __funnelshift_l(b, b, r); b ^= a; }
#else
#define TFR(a,b,r) { a += b; b = (b<<r)|(b>>(32-r)); b ^= a; }
#endif
    u32 ks2 = k0 ^ k1 ^ 0x1BD11BDAu;
    x0 += k0; x1 += k1;
    TFR(x0,x1,13); TFR(x0,x1,15); TFR(x0,x1,26); TFR(x0,x1,6);
    x0 += k1; x1 += ks2 + 1u;
    TFR(x0,x1,17); TFR(x0,x1,29); TFR(x0,x1,16); TFR(x0,x1,24);
    x0 += ks2; x1 += k0 + 2u;
    TFR(x0,x1,13); TFR(x0,x1,15); TFR(x0,x1,26); TFR(x0,x1,6);
    x0 += k0; x1 += k1 + 3u;
    TFR(x0,x1,17); TFR(x0,x1,29); TFR(x0,x1,16); TFR(x0,x1,24);
    x0 += k1; x1 += ks2 + 4u;
    TFR(x0,x1,13); TFR(x0,x1,15); TFR(x0,x1,26); TFR(x0,x1,6);
    x0 += ks2; x1 += k0 + 5u;
    o0 = x0; o1 = x1;
#undef TFR
}
__device__ __forceinline__ u32 rbits_stream(u32 kx, u32 ky, int i) {
    u32 a, b; threefry(kx, ky, 0u, (u32)i, a, b);
    return a ^ b;
}

// ---------------------------------------------------------------- scratch
__device__ int   g_cursor[ND];
__device__ u64   g_bucket[(size_t)ND*CAP];   // rank(23)|edge(20)
__device__ int   g_ovfCnt;
__device__ u64   g_ovf[OVFCAP];              // d(14) << 43 | rank23|edge20
__device__ float g_neigh[ND*DIM];
__device__ float g_y[ND*DIM];
__device__ float g_psum[NBLK*DIM];
__device__ float g_psq[NBLK*DIM];
__device__ float g_w2s[DIM];
__device__ float g_b2s;
__device__ u32   g_bar_count;
__device__ u32   g_bar_gen;

// ---------------------------------------------------------------- init kernel
__global__ void init_kernel() {
    int i = blockIdx.x * blockDim.x + threadIdx.x;
    if (i < ND) g_cursor[i] = 0;
    if (i == ND) { g_bar_count = 0; g_bar_gen = 0; g_ovfCnt = 0; }
}

// ---------------------------------------------------------------- f32x2 helpers
__device__ __forceinline__ u64 pack2(float lo, float hi) {
    u64 r;
    asm("mov.b64 %0, {%1, %2};" : "=l"(r) : "f"(lo), "f"(hi));
    return r;
}
__device__ __forceinline__ void unpack2(u64 v, float& lo, float& hi) {
    asm("mov.b64 {%0, %1}, %2;" : "=f"(lo), "=f"(hi) : "l"(v));
}
__device__ __forceinline__ void fma2(u64& acc, u64 a, u64 b) {
    asm("fma.rn.f32x2 %0, %1, %2, %0;" : "+l"(acc) : "l"(a), "l"(b));
}

// ---------------------------------------------------------------- shared layout
// [0,16384)      w1p u64[2048]                 | phase7: wcp 32KB + red
// [16384,16640)  b1s float[64]
// [16640,16896)  w2ss float[64]
// [16896,17920)  ssel int[16*16]
// [17920,42496)  wkeys u64[16*KEYCAP]
#define SH_BYTES (43*1024)

__global__ void __launch_bounds__(NTHR, 2)
mega_kernel(const int* __restrict__ DKG,
            const float* __restrict__ drug_emb,
            const float* __restrict__ rel_emb,
            const float* __restrict__ tail_emb,
            const float* __restrict__ W1,
            const float* __restrict__ b1,
            const float* __restrict__ W2,
            const float* __restrict__ b2,
            const float* __restrict__ Wc,
            const float* __restrict__ bc,
            const float* __restrict__ gamma,
            const float* __restrict__ beta,
            float* __restrict__ out,
            int E, u32 k1x, u32 k1y, u32 kLx, u32 kLy) {
    __shared__ __align__(16) char sh_raw[SH_BYTES];
    __shared__ u32 s_gen;

    const int tid  = threadIdx.x;
    const int bid  = blockIdx.x;
    const int gtid = bid * NTHR + tid;
    const int nth  = NBLK * NTHR;
    const int lane = tid & 31;
    const int wid  = tid >> 5;

    if (tid == 0) s_gen = 0;

    auto gsync = [&]() {
        __syncthreads();
        if (tid == 0) {
            u32 target = s_gen + 1;
            __threadfence();
            u32 t = atomicAdd(&g_bar_count, 1u);
            if (t == (u32)NBLK - 1) {
                atomicExch(&g_bar_count, 0u);
                __threadfence();
                atomicExch(&g_bar_gen, target);
            } else {
                volatile u32* vg = &g_bar_gen;
                while (*vg < target) { }
            }
            __threadfence();
            s_gen = target;
        }
        __syncthreads();
    };

    // ============ phase A: threefry + direct bucket scatter ============
    if (bid == NBLK - 1) {
        if (tid < DIM) {
            float s = 0.f;
            for (int j = 0; j < DIM; j++) s += W2[tid*DIM + j];
            g_w2s[tid] = s;
        }
        if (tid == DIM) {
            float s = 0.f;
            for (int j = 0; j < DIM; j++) s += b2[j];
            g_b2s = s;
        }
    }
    for (int e = gtid; e < E; e += nth) {
        int h = DKG[3*e];
        u32 bits = rbits_stream(k1x, k1y, e);
        u64 key = (((u64)(bits >> 9)) << 20) | (u32)e;
        int slot = atomicAdd(&g_cursor[h], 1);
        if (slot < CAP) g_bucket[(size_t)h*CAP + slot] = key;
        else {
            int o = atomicAdd(&g_ovfCnt, 1);
            if (o < OVFCAP) g_ovf[o] = ((u64)h << 43) | key;
        }
    }
    gsync();

    // ============ phase B fused: select top16 + score + aggregate ============
    {
        u64*   w1p   = (u64*)sh_raw;
        float* b1s   = (float*)(sh_raw + 16384);
        float* w2ss  = (float*)(sh_raw + 16640);
        int*   ssel  = (int*)(sh_raw + 16896) + wid * 16;
        u64*   wkeys = (u64*)(sh_raw + 17920) + wid * KEYCAP;

        for (int i = tid; i < 64*32; i += NTHR) {
            int r = i >> 5, c = i & 31;
            w1p[i] = pack2(W1[r*DIM + c], W1[r*DIM + c + 32]);
        }
        if (tid < DIM)        b1s[tid] = b1[tid];
        else if (tid < 2*DIM) w2ss[tid - DIM] = g_w2s[tid - DIM];
        __syncthreads();
        const float b2s = g_b2s;

        for (int d = bid * NWPB + wid; d < ND; d += NWARP) {
            const int degd = g_cursor[d];
            const int cnt  = (degd < SS) ? degd : SS;
            const u64* bkt = g_bucket + (size_t)d*CAP;

            if (cnt > 0) {
                // ---- selection: top-16 smallest keys, rank-ordered ----
                if (degd <= KEYCAP) {
                    for (int t = lane; t < degd; t += 32) wkeys[t] = bkt[t];
                    __syncwarp();
                    for (int t = lane; t < degd; t += 32) {
                        u64 k = wkeys[t];
                        int rank = 0;
                        for (int j = 0; j < degd; j++) rank += (wkeys[j] < k);
                        if (rank < SS) ssel[rank] = (int)(k & 0xFFFFFu);
                    }
                } else {
                    // never expected (deg > 192): exact slow path incl. overflow
                    int nb = (degd < CAP) ? degd : CAP;
                    int novf = g_ovfCnt; if (novf > OVFCAP) novf = OVFCAP;
                    for (int t = lane; t < nb; t += 32) {
                        u64 k = bkt[t];
                        int rank = 0;
                        for (int j = 0; j < nb; j++) rank += (bkt[j] < k);
                        for (int o = 0; o < novf; o++) {
                            u64 v = g_ovf[o];
                            if ((int)(v >> 43) == d) rank += ((v & 0x7FFFFFFFFFFULL) < k);
                        }
                        if (rank < SS) ssel[rank] = (int)(k & 0xFFFFFu);
                    }
                    for (int t = lane; t < novf; t += 32) {
                        u64 v = g_ovf[t];
                        if ((int)(v >> 43) == d) {
                            u64 k = v & 0x7FFFFFFFFFFULL;
                            int rank = 0;
                            for (int j = 0; j < nb; j++) rank += (bkt[j] < k);
                            for (int o = 0; o < novf; o++) {
                                u64 w = g_ovf[o];
                                if ((int)(w >> 43) == d) rank += ((w & 0x7FFFFFFFFFFULL) < k);
                            }
                            if (rank < SS) ssel[rank] = (int)(k & 0xFFFFFu);
                        }
                    }
                }
                __syncwarp();

                int tail = 0, rel = 0;
                if (lane < cnt) {
                    int e = ssel[lane];
                    tail = DKG[3*e + 1];
                    rel  = DKG[3*e + 2];
                }
                __syncwarp();

                const float de0 = drug_emb[d*DIM + lane];
                const float de1 = drug_emb[d*DIM + 32 + lane];
                const u64 binit = pack2(b1s[lane], b1s[lane + 32]);
                const float w20 = w2ss[lane], w21 = w2ss[lane + 32];

                float myscore = 0.f;
                for (int k = 0; k < cnt; k += 4) {
                    const int i0 = k;
                    const int i1 = (k+1 < cnt) ? k+1 : cnt-1;
                    const int i2 = (k+2 < cnt) ? k+2 : cnt-1;
                    const int i3 = (k+3 < cnt) ? k+3 : cnt-1;
                    int rA = __shfl_sync(0xffffffffu, rel, i0);
                    int rB = __shfl_sync(0xffffffffu, rel, i1);
                    int rC = __shfl_sync(0xffffffffu, rel, i2);
                    int rD = __shfl_sync(0xffffffffu, rel, i3);
                    float hA0 = de0 * rel_emb[rA*DIM + lane];
                    float hA1 = de1 * rel_emb[rA*DIM + 32 + lane];
                    float hB0 = de0 * rel_emb[rB*DIM + lane];
                    float hB1 = de1 * rel_emb[rB*DIM + 32 + lane];
                    float hC0 = de0 * rel_emb[rC*DIM + lane];
                    float hC1 = de1 * rel_emb[rC*DIM + 32 + lane];
                    float hD0 = de0 * rel_emb[rD*DIM + lane];
                    float hD1 = de1 * rel_emb[rD*DIM + 32 + lane];
                    u64 aA = binit, aB = binit, aC = binit, aD = binit;
                    #pragma unroll
                    for (int i = 0; i < 32; i++) {
                        u64 w = w1p[i*32 + lane];
                        float v;
                        v = __shfl_sync(0xffffffffu, hA0, i); fma2(aA, pack2(v, v), w);
                        v = __shfl_sync(0xffffffffu, hB0, i); fma2(aB, pack2(v, v), w);
                        v = __shfl_sync(0xffffffffu, hC0, i); fma2(aC, pack2(v, v), w);
                        v = __shfl_sync(0xffffffffu, hD0, i); fma2(aD, pack2(v, v), w);
                    }
                    #pragma unroll
                    for (int i = 0; i < 32; i++) {
                        u64 w = w1p[(i + 32)*32 + lane];
                        float v;
                        v = __shfl_sync(0xffffffffu, hA1, i); fma2(aA, pack2(v, v), w);
                        v = __shfl_sync(0xffffffffu, hB1, i); fma2(aB, pack2(v, v), w);
                        v = __shfl_sync(0xffffffffu, hC1, i); fma2(aC, pack2(v, v), w);
                        v = __shfl_sync(0xffffffffu, hD1, i); fma2(aD, pack2(v, v), w);
                    }
                    float a0, a1;
                    unpack2(aA, a0, a1);
                    float pA = (1.f/(1.f+__expf(-a0)))*w20 + (1.f/(1.f+__expf(-a1)))*w21;
                    unpack2(aB, a0, a1);
                    float pB = (1.f/(1.f+__expf(-a0)))*w20 + (1.f/(1.f+__expf(-a1)))*w21;
                    unpack2(aC, a0, a1);
                    float pC = (1.f/(1.f+__expf(-a0)))*w20 + (1.f/(1.f+__expf(-a1)))*w21;
                    unpack2(aD, a0, a1);
                    float pD = (1.f/(1.f+__expf(-a0)))*w20 + (1.f/(1.f+__expf(-a1)))*w21;
                    #pragma unroll
                    for (int o = 16; o; o >>= 1) {
                        pA += __shfl_xor_sync(0xffffffffu, pA, o);
                        pB += __shfl_xor_sync(0xffffffffu, pB, o);
                        pC += __shfl_xor_sync(0xffffffffu, pC, o);
                        pD += __shfl_xor_sync(0xffffffffu, pD, o);
                    }
                    if (lane == i0) myscore = pA + b2s;
                    if (i1 > i0 && lane == i1) myscore = pB + b2s;
                    if (i2 > i1 && lane == i2) myscore = pC + b2s;
                    if (i3 > i2 && lane == i3) myscore = pD + b2s;
                }

                // ---- aggregation (rank order, then extras) ----
                float acc0 = 0.f, acc1 = 0.f;
                for (int k = 0; k < cnt; k++) {
                    float sc = __shfl_sync(0xffffffffu, myscore, k);
                    int   t  = __shfl_sync(0xffffffffu, tail, k);
                    acc0 = fmaf(sc, tail_emb[t*DIM + lane], acc0);
                    acc1 = fmaf(sc, tail_emb[t*DIM + 32 + lane], acc1);
                }
                if (degd < SS) {
                    for (int s = 0; s < SS - degd; s++) {
                        u32 bits = rbits_stream(kLx, kLy, d*SS + s);
                        int idx = (int)((bits % 2147483647u) % (u32)degd);
                        float sc = __shfl_sync(0xffffffffu, myscore, idx);
                        int   t  = __shfl_sync(0xffffffffu, tail, idx);
                        acc0 = fmaf(sc, tail_emb[t*DIM + lane], acc0);
                        acc1 = fmaf(sc, tail_emb[t*DIM + 32 + lane], acc1);
                    }
                }
                g_neigh[d*DIM + lane]      = acc0;
                g_neigh[d*DIM + 32 + lane] = acc1;
            } else {
                g_neigh[d*DIM + lane]      = 0.f;
                g_neigh[d*DIM + 32 + lane] = 0.f;
            }
        }
    }
    gsync();

    // ============ phase C: y = [drug_emb, neigh] @ Wc + bc, partial BN stats ============
    {
        u64*   wcp = (u64*)sh_raw;                   // 128*32 u64 = 32KB
        float* red = (float*)(sh_raw + 32768);       // 512 floats
        for (int i = tid; i < 2*DIM*32; i += NTHR) {
            int r = i >> 5, c = i & 31;
            wcp[i] = pack2(Wc[r*DIM + c], Wc[r*DIM + c + 32]);
        }
        __syncthreads();
        const int sub = tid >> 5;                    // 0..15
        const int o = lane;
        const u64 bcv = pack2(bc[o], bc[o + 32]);
        float S0 = 0.f, S1 = 0.f, Q0 = 0.f, Q1 = 0.f;
        const int NR32 = (ND + 31) / 32;             // 313
        for (int r32 = bid; r32 < NR32; r32 += NBLK) {
            int row0 = r32*32 + sub;
            int row1 = row0 + 16;
            bool has1 = (row1 < ND);
            const float* de0p = drug_emb + row0*DIM;
            const float* ne0p = g_neigh + row0*DIM;
            const float* de1p = drug_emb + (has1 ? row1 : row0)*DIM;
            const float* ne1p = g_neigh + (has1 ? row1 : row0)*DIM;
            u64 accR0 = bcv, accR1 = bcv;
            #pragma unroll
            for (int i = 0; i < DIM; i++) {
                u64 w = wcp[i*32 + o];
                float v0 = de0p[i], v1 = de1p[i];
                fma2(accR0, pack2(v0, v0), w);
                fma2(accR1, pack2(v1, v1), w);
            }
            #pragma unroll
            for (int i = 0; i < DIM; i++) {
                u64 w = wcp[(DIM + i)*32 + o];
                float v0 = ne0p[i], v1 = ne1p[i];
                fma2(accR0, pack2(v0, v0), w);
                fma2(accR1, pack2(v1, v1), w);
            }
            float y00, y01, y10, y11;
            unpack2(accR0, y00, y01);
            unpack2(accR1, y10, y11);
            g_y[row0*DIM + o]      = y00;
            g_y[row0*DIM + 32 + o] = y01;
            S0 += y00; S1 += y01; Q0 += y00*y00; Q1 += y01*y01;
            if (has1) {
                g_y[row1*DIM + o]      = y10;
                g_y[row1*DIM + 32 + o] = y11;
                S0 += y10; S1 += y11; Q0 += y10*y10; Q1 += y11*y11;
            }
        }
        red[tid] = S0;
        __syncthreads();
        if (tid < 32) { float s = 0.f;
            #pragma unroll
            for (int p = 0; p < 16; p++) s += red[p*32 + lane];
            g_psum[bid*DIM + lane] = s; }
        __syncthreads();
        red[tid] = S1;
        __syncthreads();
        if (tid < 32) { float s = 0.f;
            #pragma unroll
            for (int p = 0; p < 16; p++) s += red[p*32 + lane];
            g_psum[bid*DIM + 32 + lane] = s; }
        __syncthreads();
        red[tid] = Q0;
        __syncthreads();
        if (tid < 32) { float s = 0.f;
            #pragma unroll
            for (int p = 0; p < 16; p++) s += red[p*32 + lane];
            g_psq[bid*DIM + lane] = s; }
        __syncthreads();
        red[tid] = Q1;
        __syncthreads();
        if (tid < 32) { float s = 0.f;
            #pragma unroll
            for (int p = 0; p < 16; p++) s += red[p*32 + lane];
            g_psq[bid*DIM + 32 + lane] = s; }
    }
    gsync();

    // ============ phase D: distributed BN stats (every block, redundant) ============
    {
        float* rs = (float*)sh_raw;                 // 512
        float* rq = (float*)(sh_raw + 2048);        // 512
        float* A  = (float*)(sh_raw + 4096);        // 64: gamma*rstd
        float* B  = (float*)(sh_raw + 4352);        // 64: beta - gamma*mean*rstd
        const int col = tid & 63, part = tid >> 6;  // 8 parts
        float s = 0.f, q = 0.f;
        for (int b = part; b < NBLK; b += 8) {
            s += g_psum[b*DIM + col];
            q += g_psq[b*DIM + col];
        }
        rs[tid] = s; rq[tid] = q;
        __syncthreads();
        if (tid < 64) {
            float S = 0.f, Q = 0.f;
            #pragma unroll
            for (int p = 0; p < 8; p++) { S += rs[p*64 + col]; Q += rq[p*64 + col]; }
            float mean = S / (float)ND;
            float var  = Q / (float)ND - mean * mean;
            float rstd = rsqrtf(var + 1e-5f);
            float gm = gamma[col];
            A[col] = gm * rstd;
            B[col] = beta[col] - gm * mean * rstd;
        }
        __syncthreads();

        // ---- normalize + write out (float4) ----
        const float4* y4 = (const float4*)g_y;
        float4* o4 = (float4*)out;
        for (int t = gtid; t < ND*DIM/4; t += nth) {
            int c = (t*4) & 63;
            float4 v = y4[t];
            float4 r;
            r.x = fmaf(v.x, A[c+0], B[c+0]);
            r.y = fmaf(v.y, A[c+1], B[c+1]);
            r.z = fmaf(v.z, A[c+2], B[c+2]);
            r.w = fmaf(v.w, A[c+3], B[c+3]);
            o4[t] = r;
        }
    }
}

// ---------------------------------------------------------------- host
static void compute_keys(u32& k1x, u32& k1y, u32& kLx, u32& kLy) {
    u32 a, b, c, d, e, f;
    threefry(0u, 42u, 0u, 0u, a, b);   // k1 = split(key(42))[0]
    k1x = a; k1y = b;
    threefry(0u, 42u, 0u, 1u, c, d);   // k2 = split(key(42))[1]
    threefry(c, d, 0u, 1u, e, f);      // split(k2)[1]
    kLx = e; kLy = f;
}

extern "C" void kernel_launch(void* const* d_in, const int* in_sizes, int n_in,
                              void* d_out, int out_size) {
    const float* HF       = (const float*)d_in[0];
    const float* X        = (const float*)d_in[1];
    const float* drug_emb = (const float*)d_in[2];
    const float* rel_emb  = (const float*)d_in[3];
    const float* tail_emb = (const float*)d_in[4];
    const float* W1       = (const float*)d_in[5];
    const float* b1       = (const float*)d_in[6];
    const float* W2       = (const float*)d_in[7];
    const float* b2       = (const float*)d_in[8];
    const float* Wc       = (const float*)d_in[9];
    const float* bc       = (const float*)d_in[10];
    const float* gamma    = (const float*)d_in[11];
    const float* beta     = (const float*)d_in[12];
    const int*   DKG      = (const int*)d_in[13];
    int E    = in_sizes[13] / 3;
    int hf_n = in_sizes[0];
    int x_n  = in_sizes[1];
    float* out = (float*)d_out;

    u32 k1x, k1y, kLx, kLy;
    compute_keys(k1x, k1y, kLx, kLy);

    cudaMemcpyAsync(out, HF, (size_t)hf_n * sizeof(float), cudaMemcpyDeviceToDevice, 0);
    cudaMemcpyAsync(out + hf_n + ND*DIM, X, (size_t)x_n * sizeof(float),
                    cudaMemcpyDeviceToDevice, 0);

    init_kernel<<<(ND + 256)/256, 256>>>();
    mega_kernel<<<NBLK, NTHR>>>(DKG, drug_emb, rel_emb, tail_emb, W1, b1, W2, b2,
                                Wc, bc, gamma, beta, out + hf_n,
                                E, k1x, k1y, kLx, kLy);
}

// round 6
// speedup vs baseline: 1.2631x; 1.0527x over previous
#include <cuda_runtime.h>
#include <stdint.h>

#define ND    10000
#define DIM   64
#define SS    16
#define EMAX  1000000
#define NBLK  296
#define NTHR  512
#define NWPB  16                 // warps per block
#define NWARP (NBLK*NWPB)
#define CAP   192                // per-drug bucket capacity (deg ~ Poisson(100))
#define REGCAP 160               // fast-path selection capacity (5 keys/lane)
#define OVFCAP 8192

typedef unsigned int u32;
typedef unsigned long long u64;

// ---------------------------------------------------------------- threefry2x32
__host__ __device__ __forceinline__ void threefry(u32 k0, u32 k1, u32 x0, u32 x1,
                                                  u32& o0, u32& o1) {
#ifdef __CUDA_ARCH__
#define TFR(a,b,r) { a += b; b = __funnelshift_l(b, b, r); b ^= a; }
#else
#define TFR(a,b,r) { a += b; b = (b<<r)|(b>>(32-r)); b ^= a; }
#endif
    u32 ks2 = k0 ^ k1 ^ 0x1BD11BDAu;
    x0 += k0; x1 += k1;
    TFR(x0,x1,13); TFR(x0,x1,15); TFR(x0,x1,26); TFR(x0,x1,6);
    x0 += k1; x1 += ks2 + 1u;
    TFR(x0,x1,17); TFR(x0,x1,29); TFR(x0,x1,16); TFR(x0,x1,24);
    x0 += ks2; x1 += k0 + 2u;
    TFR(x0,x1,13); TFR(x0,x1,15); TFR(x0,x1,26); TFR(x0,x1,6);
    x0 += k0; x1 += k1 + 3u;
    TFR(x0,x1,17); TFR(x0,x1,29); TFR(x0,x1,16); TFR(x0,x1,24);
    x0 += k1; x1 += ks2 + 4u;
    TFR(x0,x1,13); TFR(x0,x1,15); TFR(x0,x1,26); TFR(x0,x1,6);
    x0 += ks2; x1 += k0 + 5u;
    o0 = x0; o1 = x1;
#undef TFR
}
__device__ __forceinline__ u32 rbits_stream(u32 kx, u32 ky, int i) {
    u32 a, b; threefry(kx, ky, 0u, (u32)i, a, b);
    return a ^ b;
}

// ---------------------------------------------------------------- scratch
__device__ int   g_cursor[ND];
__device__ u64   g_bucket[(size_t)ND*CAP];   // rank(23)|edge(20)
__device__ int   g_ovfCnt;
__device__ u64   g_ovf[OVFCAP];              // d(14) << 43 | rank23|edge20
__device__ float g_neigh[ND*DIM];
__device__ float g_y[ND*DIM];
__device__ float g_psum[NBLK*DIM];
__device__ float g_psq[NBLK*DIM];
__device__ float g_w2s[DIM];
__device__ float g_b2s;
__device__ u32   g_bar_count;
__device__ u32   g_bar_gen;

// ---------------------------------------------------------------- init kernel
__global__ void init_kernel() {
    int i = blockIdx.x * blockDim.x + threadIdx.x;
    if (i < ND) g_cursor[i] = 0;
    if (i == ND) { g_bar_count = 0; g_bar_gen = 0; g_ovfCnt = 0; }
}

// ---------------------------------------------------------------- f32x2 helpers
__device__ __forceinline__ u64 pack2(float lo, float hi) {
    u64 r;
    asm("mov.b64 %0, {%1, %2};" : "=l"(r) : "f"(lo), "f"(hi));
    return r;
}
__device__ __forceinline__ void unpack2(u64 v, float& lo, float& hi) {
    asm("mov.b64 {%0, %1}, %2;" : "=f"(lo), "=f"(hi) : "l"(v));
}
__device__ __forceinline__ void fma2(u64& acc, u64 a, u64 b) {
    asm("fma.rn.f32x2 %0, %1, %2, %0;" : "+l"(acc) : "l"(a), "l"(b));
}
__device__ __forceinline__ u64 umin64(u64 a, u64 b) { return a < b ? a : b; }

// ---------------------------------------------------------------- shared layout
// phase B: [0,16384) w1pk u64[2048] ipair-major | [16384) b1s | [16640) w2ss | [16896,17920) ssel
// phase C: [0,32768) wcp | [32768,34816) red
#define SH_BYTES (35*1024)

__global__ void __launch_bounds__(NTHR, 2)
mega_kernel(const int* __restrict__ DKG,
            const float* __restrict__ drug_emb,
            const float* __restrict__ rel_emb,
            const float* __restrict__ tail_emb,
            const float* __restrict__ W1,
            const float* __restrict__ b1,
            const float* __restrict__ W2,
            const float* __restrict__ b2,
            const float* __restrict__ Wc,
            const float* __restrict__ bc,
            const float* __restrict__ gamma,
            const float* __restrict__ beta,
            float* __restrict__ out,
            int E, u32 k1x, u32 k1y, u32 kLx, u32 kLy) {
    __shared__ __align__(16) char sh_raw[SH_BYTES];
    __shared__ u32 s_gen;

    const int tid  = threadIdx.x;
    const int bid  = blockIdx.x;
    const int gtid = bid * NTHR + tid;
    const int nth  = NBLK * NTHR;
    const int lane = tid & 31;
    const int wid  = tid >> 5;

    if (tid == 0) s_gen = 0;

    auto gsync = [&]() {
        __syncthreads();
        if (tid == 0) {
            u32 target = s_gen + 1;
            __threadfence();
            u32 t = atomicAdd(&g_bar_count, 1u);
            if (t == (u32)NBLK - 1) {
                atomicExch(&g_bar_count, 0u);
                __threadfence();
                atomicExch(&g_bar_gen, target);
            } else {
                volatile u32* vg = &g_bar_gen;
                while (*vg < target) { }
            }
            __threadfence();
            s_gen = target;
        }
        __syncthreads();
    };

    // ============ phase A: threefry + direct bucket scatter ============
    if (bid == NBLK - 1) {
        if (tid < DIM) {
            float s = 0.f;
            for (int j = 0; j < DIM; j++) s += W2[tid*DIM + j];
            g_w2s[tid] = s;
        }
        if (tid == DIM) {
            float s = 0.f;
            for (int j = 0; j < DIM; j++) s += b2[j];
            g_b2s = s;
        }
    }
    for (int e = gtid; e < E; e += nth) {
        int h = DKG[3*e];
        u32 bits = rbits_stream(k1x, k1y, e);
        u64 key = (((u64)(bits >> 9)) << 20) | (u32)e;
        int slot = atomicAdd(&g_cursor[h], 1);
        if (slot < CAP) g_bucket[(size_t)h*CAP + slot] = key;
        else {
            int o = atomicAdd(&g_ovfCnt, 1);
            if (o < OVFCAP) g_ovf[o] = ((u64)h << 43) | key;
        }
    }
    gsync();

    // ============ phase B fused: select top16 + score + aggregate ============
    {
        u64*   w1pk  = (u64*)sh_raw;                  // [ipair*64 + j], 2048 u64
        float* b1s   = (float*)(sh_raw + 16384);
        float* w2ss  = (float*)(sh_raw + 16640);
        int*   ssel  = (int*)(sh_raw + 16896) + wid * 16;

        for (int i = tid; i < 32*64; i += NTHR) {
            int ip = i >> 6, j = i & 63;
            w1pk[i] = pack2(W1[(2*ip)*DIM + j], W1[(2*ip + 1)*DIM + j]);
        }
        if (tid < DIM)        b1s[tid] = b1[tid];
        else if (tid < 2*DIM) w2ss[tid - DIM] = g_w2s[tid - DIM];
        __syncthreads();
        const float b2s = g_b2s;
        const u64 FULLK = ~0ULL;

        for (int d = bid * NWPB + wid; d < ND; d += NWARP) {
            const int degd = g_cursor[d];
            const int cnt  = (degd < SS) ? degd : SS;
            const u64* bkt = g_bucket + (size_t)d*CAP;

            if (cnt > 0) {
                int myedge = 0;
                // ---- selection: 16 rounds of warp min-extraction ----
                if (degd <= REGCAP) {
                    u64 c0 = (lane       < degd) ? bkt[lane]       : FULLK;
                    u64 c1 = (lane + 32  < degd) ? bkt[lane + 32]  : FULLK;
                    u64 c2 = (lane + 64  < degd) ? bkt[lane + 64]  : FULLK;
                    u64 c3 = (lane + 96  < degd) ? bkt[lane + 96]  : FULLK;
                    u64 c4 = (lane + 128 < degd) ? bkt[lane + 128] : FULLK;
                    u64 lmin = umin64(umin64(umin64(c0, c1), umin64(c2, c3)), c4);
                    for (int r = 0; r < cnt; r++) {
                        u64 m = lmin;
                        #pragma unroll
                        for (int o = 16; o; o >>= 1) {
                            u64 t = __shfl_xor_sync(0xffffffffu, m, o);
                            m = umin64(m, t);
                        }
                        if (lane == r) myedge = (int)(m & 0xFFFFFu);
                        if (lmin == m) {
                            if      (c0 == m) c0 = FULLK;
                            else if (c1 == m) c1 = FULLK;
                            else if (c2 == m) c2 = FULLK;
                            else if (c3 == m) c3 = FULLK;
                            else              c4 = FULLK;
                            lmin = umin64(umin64(umin64(c0, c1), umin64(c2, c3)), c4);
                        }
                    }
                } else {
                    // rare path (deg > 160): exact all-pairs ranking incl. overflow
                    int nb = (degd < CAP) ? degd : CAP;
                    int novf = g_ovfCnt; if (novf > OVFCAP) novf = OVFCAP;
                    for (int t = lane; t < nb; t += 32) {
                        u64 k = bkt[t];
                        int rank = 0;
                        for (int j = 0; j < nb; j++) rank += (bkt[j] < k);
                        for (int o = 0; o < novf; o++) {
                            u64 v = g_ovf[o];
                            if ((int)(v >> 43) == d) rank += ((v & 0x7FFFFFFFFFFULL) < k);
                        }
                        if (rank < SS) ssel[rank] = (int)(k & 0xFFFFFu);
                    }
                    for (int t = lane; t < novf; t += 32) {
                        u64 v = g_ovf[t];
                        if ((int)(v >> 43) == d) {
                            u64 k = v & 0x7FFFFFFFFFFULL;
                            int rank = 0;
                            for (int j = 0; j < nb; j++) rank += (bkt[j] < k);
                            for (int o = 0; o < novf; o++) {
                                u64 w = g_ovf[o];
                                if ((int)(w >> 43) == d) rank += ((w & 0x7FFFFFFFFFFULL) < k);
                            }
                            if (rank < SS) ssel[rank] = (int)(k & 0xFFFFFu);
                        }
                    }
                    __syncwarp();
                    if (lane < cnt) myedge = ssel[lane];
                }

                int tail = 0, rel = 0;
                if (lane < cnt) {
                    tail = DKG[3*myedge + 1];
                    rel  = DKG[3*myedge + 2];
                }
                __syncwarp();

                // per-lane packed drug pair (h indexes 2*lane, 2*lane+1)
                const float2 de2 = ((const float2*)(drug_emb + d*DIM))[lane];
                const u64 bin0 = pack2(b1s[lane], 0.f);
                const u64 bin1 = pack2(b1s[lane + 32], 0.f);
                const float w20 = w2ss[lane], w21 = w2ss[lane + 32];

                float myscore = 0.f;
                for (int k = 0; k < cnt; k += 4) {
                    const int i0 = k;
                    const int i1 = (k+1 < cnt) ? k+1 : cnt-1;
                    const int i2 = (k+2 < cnt) ? k+2 : cnt-1;
                    const int i3 = (k+3 < cnt) ? k+3 : cnt-1;
                    int rA = __shfl_sync(0xffffffffu, rel, i0);
                    int rB = __shfl_sync(0xffffffffu, rel, i1);
                    int rC = __shfl_sync(0xffffffffu, rel, i2);
                    int rD = __shfl_sync(0xffffffffu, rel, i3);
                    float2 reA = ((const float2*)(rel_emb + rA*DIM))[lane];
                    float2 reB = ((const float2*)(rel_emb + rB*DIM))[lane];
                    float2 reC = ((const float2*)(rel_emb + rC*DIM))[lane];
                    float2 reD = ((const float2*)(rel_emb + rD*DIM))[lane];
                    u64 hA = pack2(de2.x*reA.x, de2.y*reA.y);
                    u64 hB = pack2(de2.x*reB.x, de2.y*reB.y);
                    u64 hC = pack2(de2.x*reC.x, de2.y*reC.y);
                    u64 hD = pack2(de2.x*reD.x, de2.y*reD.y);
                    u64 aA0 = bin0, aA1 = bin1, aB0 = bin0, aB1 = bin1;
                    u64 aC0 = bin0, aC1 = bin1, aD0 = bin0, aD1 = bin1;
                    #pragma unroll
                    for (int ip = 0; ip < 32; ip++) {
                        u64 w0  = w1pk[ip*64 + lane];
                        u64 w1v = w1pk[ip*64 + 32 + lane];
                        u64 hb;
                        hb = __shfl_sync(0xffffffffu, hA, ip);
                        fma2(aA0, hb, w0); fma2(aA1, hb, w1v);
                        hb = __shfl_sync(0xffffffffu, hB, ip);
                        fma2(aB0, hb, w0); fma2(aB1, hb, w1v);
                        hb = __shfl_sync(0xffffffffu, hC, ip);
                        fma2(aC0, hb, w0); fma2(aC1, hb, w1v);
                        hb = __shfl_sync(0xffffffffu, hD, ip);
                        fma2(aD0, hb, w0); fma2(aD1, hb, w1v);
                    }
                    float e0, o0, e1, o1;
                    unpack2(aA0, e0, o0); unpack2(aA1, e1, o1);
                    float pA = (1.f/(1.f+__expf(-(e0+o0))))*w20
                             + (1.f/(1.f+__expf(-(e1+o1))))*w21;
                    unpack2(aB0, e0, o0); unpack2(aB1, e1, o1);
                    float pB = (1.f/(1.f+__expf(-(e0+o0))))*w20
                             + (1.f/(1.f+__expf(-(e1+o1))))*w21;
                    unpack2(aC0, e0, o0); unpack2(aC1, e1, o1);
                    float pC = (1.f/(1.f+__expf(-(e0+o0))))*w20
                             + (1.f/(1.f+__expf(-(e1+o1))))*w21;
                    unpack2(aD0, e0, o0); unpack2(aD1, e1, o1);
                    float pD = (1.f/(1.f+__expf(-(e0+o0))))*w20
                             + (1.f/(1.f+__expf(-(e1+o1))))*w21;
                    #pragma unroll
                    for (int o = 16; o; o >>= 1) {
                        pA += __shfl_xor_sync(0xffffffffu, pA, o);
                        pB += __shfl_xor_sync(0xffffffffu, pB, o);
                        pC += __shfl_xor_sync(0xffffffffu, pC, o);
                        pD += __shfl_xor_sync(0xffffffffu, pD, o);
                    }
                    if (lane == i0) myscore = pA + b2s;
                    if (i1 > i0 && lane == i1) myscore = pB + b2s;
                    if (i2 > i1 && lane == i2) myscore = pC + b2s;
                    if (i3 > i2 && lane == i3) myscore = pD + b2s;
                }

                // ---- aggregation (rank order, then extras) ----
                float acc0 = 0.f, acc1 = 0.f;
                for (int k = 0; k < cnt; k++) {
                    float sc = __shfl_sync(0xffffffffu, myscore, k);
                    int   t  = __shfl_sync(0xffffffffu, tail, k);
                    acc0 = fmaf(sc, tail_emb[t*DIM + lane], acc0);
                    acc1 = fmaf(sc, tail_emb[t*DIM + 32 + lane], acc1);
                }
                if (degd < SS) {
                    for (int s = 0; s < SS - degd; s++) {
                        u32 bits = rbits_stream(kLx, kLy, d*SS + s);
                        int idx = (int)((bits % 2147483647u) % (u32)degd);
                        float sc = __shfl_sync(0xffffffffu, myscore, idx);
                        int   t  = __shfl_sync(0xffffffffu, tail, idx);
                        acc0 = fmaf(sc, tail_emb[t*DIM + lane], acc0);
                        acc1 = fmaf(sc, tail_emb[t*DIM + 32 + lane], acc1);
                    }
                }
                g_neigh[d*DIM + lane]      = acc0;
                g_neigh[d*DIM + 32 + lane] = acc1;
            } else {
                g_neigh[d*DIM + lane]      = 0.f;
                g_neigh[d*DIM + 32 + lane] = 0.f;
            }
        }
    }
    gsync();

    // ============ phase C: y = [drug_emb, neigh] @ Wc + bc, partial BN stats ============
    {
        u64*   wcp = (u64*)sh_raw;                   // 128*32 u64 = 32KB
        float* red = (float*)(sh_raw + 32768);       // 512 floats
        for (int i = tid; i < 2*DIM*32; i += NTHR) {
            int r = i >> 5, c = i & 31;
            wcp[i] = pack2(Wc[r*DIM + c], Wc[r*DIM + c + 32]);
        }
        __syncthreads();
        const int sub = tid >> 5;                    // 0..15
        const int o = lane;
        const u64 bcv = pack2(bc[o], bc[o + 32]);
        float S0 = 0.f, S1 = 0.f, Q0 = 0.f, Q1 = 0.f;
        const int NR32 = (ND + 31) / 32;             // 313
        for (int r32 = bid; r32 < NR32; r32 += NBLK) {
            int row0 = r32*32 + sub;
            int row1 = row0 + 16;
            bool has1 = (row1 < ND);
            const float* de0p = drug_emb + row0*DIM;
            const float* ne0p = g_neigh + row0*DIM;
            const float* de1p = drug_emb + (has1 ? row1 : row0)*DIM;
            const float* ne1p = g_neigh + (has1 ? row1 : row0)*DIM;
            u64 accR0 = bcv, accR1 = bcv;
            #pragma unroll
            for (int i = 0; i < DIM; i++) {
                u64 w = wcp[i*32 + o];
                float v0 = de0p[i], v1 = de1p[i];
                fma2(accR0, pack2(v0, v0), w);
                fma2(accR1, pack2(v1, v1), w);
            }
            #pragma unroll
            for (int i = 0; i < DIM; i++) {
                u64 w = wcp[(DIM + i)*32 + o];
                float v0 = ne0p[i], v1 = ne1p[i];
                fma2(accR0, pack2(v0, v0), w);
                fma2(accR1, pack2(v1, v1), w);
            }
            float y00, y01, y10, y11;
            unpack2(accR0, y00, y01);
            unpack2(accR1, y10, y11);
            g_y[row0*DIM + o]      = y00;
            g_y[row0*DIM + 32 + o] = y01;
            S0 += y00; S1 += y01; Q0 += y00*y00; Q1 += y01*y01;
            if (has1) {
                g_y[row1*DIM + o]      = y10;
                g_y[row1*DIM + 32 + o] = y11;
                S0 += y10; S1 += y11; Q0 += y10*y10; Q1 += y11*y11;
            }
        }
        red[tid] = S0;
        __syncthreads();
        if (tid < 32) { float s = 0.f;
            #pragma unroll
            for (int p = 0; p < 16; p++) s += red[p*32 + lane];
            g_psum[bid*DIM + lane] = s; }
        __syncthreads();
        red[tid] = S1;
        __syncthreads();
        if (tid < 32) { float s = 0.f;
            #pragma unroll
            for (int p = 0; p < 16; p++) s += red[p*32 + lane];
            g_psum[bid*DIM + 32 + lane] = s; }
        __syncthreads();
        red[tid] = Q0;
        __syncthreads();
        if (tid < 32) { float s = 0.f;
            #pragma unroll
            for (int p = 0; p < 16; p++) s += red[p*32 + lane];
            g_psq[bid*DIM + lane] = s; }
        __syncthreads();
        red[tid] = Q1;
        __syncthreads();
        if (tid < 32) { float s = 0.f;
            #pragma unroll
            for (int p = 0; p < 16; p++) s += red[p*32 + lane];
            g_psq[bid*DIM + 32 + lane] = s; }
    }
    gsync();

    // ============ phase D: distributed BN stats + normalize + write ============
    {
        float* rs = (float*)sh_raw;                 // 512
        float* rq = (float*)(sh_raw + 2048);        // 512
        float* A  = (float*)(sh_raw + 4096);        // 64: gamma*rstd
        float* B  = (float*)(sh_raw + 4352);        // 64: beta - gamma*mean*rstd
        const int col = tid & 63, part = tid >> 6;  // 8 parts
        float s = 0.f, q = 0.f;
        for (int b = part; b < NBLK; b += 8) {
            s += g_psum[b*DIM + col];
            q += g_psq[b*DIM + col];
        }
        rs[tid] = s; rq[tid] = q;
        __syncthreads();
        if (tid < 64) {
            float S = 0.f, Q = 0.f;
            #pragma unroll
            for (int p = 0; p < 8; p++) { S += rs[p*64 + col]; Q += rq[p*64 + col]; }
            float mean = S / (float)ND;
            float var  = Q / (float)ND - mean * mean;
            float rstd = rsqrtf(var + 1e-5f);
            float gm = gamma[col];
            A[col] = gm * rstd;
            B[col] = beta[col] - gm * mean * rstd;
        }
        __syncthreads();

        const float4* y4 = (const float4*)g_y;
        float4* o4 = (float4*)out;
        for (int t = gtid; t < ND*DIM/4; t += nth) {
            int c = (t*4) & 63;
            float4 v = y4[t];
            float4 r;
            r.x = fmaf(v.x, A[c+0], B[c+0]);
            r.y = fmaf(v.y, A[c+1], B[c+1]);
            r.z = fmaf(v.z, A[c+2], B[c+2]);
            r.w = fmaf(v.w, A[c+3], B[c+3]);
            o4[t] = r;
        }
    }
}

// ---------------------------------------------------------------- host
static void compute_keys(u32& k1x, u32& k1y, u32& kLx, u32& kLy) {
    u32 a, b, c, d, e, f;
    threefry(0u, 42u, 0u, 0u, a, b);   // k1 = split(key(42))[0]
    k1x = a; k1y = b;
    threefry(0u, 42u, 0u, 1u, c, d);   // k2 = split(key(42))[1]
    threefry(c, d, 0u, 1u, e, f);      // split(k2)[1]
    kLx = e; kLy = f;
}

extern "C" void kernel_launch(void* const* d_in, const int* in_sizes, int n_in,
                              void* d_out, int out_size) {
    const float* HF       = (const float*)d_in[0];
    const float* X        = (const float*)d_in[1];
    const float* drug_emb = (const float*)d_in[2];
    const float* rel_emb  = (const float*)d_in[3];
    const float* tail_emb = (const float*)d_in[4];
    const float* W1       = (const float*)d_in[5];
    const float* b1       = (const float*)d_in[6];
    const float* W2       = (const float*)d_in[7];
    const float* b2       = (const float*)d_in[8];
    const float* Wc       = (const float*)d_in[9];
    const float* bc       = (const float*)d_in[10];
    const float* gamma    = (const float*)d_in[11];
    const float* beta     = (const float*)d_in[12];
    const int*   DKG      = (const int*)d_in[13];
    int E    = in_sizes[13] / 3;
    int hf_n = in_sizes[0];
    int x_n  = in_sizes[1];
    float* out = (float*)d_out;

    u32 k1x, k1y, kLx, kLy;
    compute_keys(k1x, k1y, kLx, kLy);

    cudaMemcpyAsync(out, HF, (size_t)hf_n * sizeof(float), cudaMemcpyDeviceToDevice, 0);
    cudaMemcpyAsync(out + hf_n + ND*DIM, X, (size_t)x_n * sizeof(float),
                    cudaMemcpyDeviceToDevice, 0);

    init_kernel<<<(ND + 256)/256, 256>>>();
    mega_kernel<<<NBLK, NTHR>>>(DKG, drug_emb, rel_emb, tail_emb, W1, b1, W2, b2,
                                Wc, bc, gamma, beta, out + hf_n,
                                E, k1x, k1y, kLx, kLy);
}

// round 7
// speedup vs baseline: 1.9748x; 1.5635x over previous
#include <cuda_runtime.h>
#include <stdint.h>

#define ND    10000
#define DIM   64
#define SS    16
#define EMAX  1000000
#define NBLK  296
#define NTHR  512
#define NWPB  16                 // warps per block
#define NWARP (NBLK*NWPB)
#define CAP   192                // per-drug bucket capacity (deg ~ Poisson(100))
#define REGCAP 160               // fast-path selection capacity (5 keys/lane)
#define OVFCAP 8192

typedef unsigned int u32;
typedef unsigned long long u64;

// ---------------------------------------------------------------- threefry2x32
__host__ __device__ __forceinline__ void threefry(u32 k0, u32 k1, u32 x0, u32 x1,
                                                  u32& o0, u32& o1) {
#ifdef __CUDA_ARCH__
#define TFR(a,b,r) { a += b; b = __funnelshift_l(b, b, r); b ^= a; }
#else
#define TFR(a,b,r) { a += b; b = (b<<r)|(b>>(32-r)); b ^= a; }
#endif
    u32 ks2 = k0 ^ k1 ^ 0x1BD11BDAu;
    x0 += k0; x1 += k1;
    TFR(x0,x1,13); TFR(x0,x1,15); TFR(x0,x1,26); TFR(x0,x1,6);
    x0 += k1; x1 += ks2 + 1u;
    TFR(x0,x1,17); TFR(x0,x1,29); TFR(x0,x1,16); TFR(x0,x1,24);
    x0 += ks2; x1 += k0 + 2u;
    TFR(x0,x1,13); TFR(x0,x1,15); TFR(x0,x1,26); TFR(x0,x1,6);
    x0 += k0; x1 += k1 + 3u;
    TFR(x0,x1,17); TFR(x0,x1,29); TFR(x0,x1,16); TFR(x0,x1,24);
    x0 += k1; x1 += ks2 + 4u;
    TFR(x0,x1,13); TFR(x0,x1,15); TFR(x0,x1,26); TFR(x0,x1,6);
    x0 += ks2; x1 += k0 + 5u;
    o0 = x0; o1 = x1;
#undef TFR
}
__device__ __forceinline__ u32 rbits_stream(u32 kx, u32 ky, int i) {
    u32 a, b; threefry(kx, ky, 0u, (u32)i, a, b);
    return a ^ b;
}

// ---------------------------------------------------------------- scratch
__device__ int   g_cursor[ND];
__device__ u64   g_bucket[(size_t)ND*CAP];   // rank(23)|edge(20)
__device__ int   g_ovfCnt;
__device__ u64   g_ovf[OVFCAP];              // d(14) << 43 | rank23|edge20
__device__ float g_neigh[ND*DIM];
__device__ float g_y[ND*DIM];
__device__ float g_psum[NBLK*DIM];
__device__ float g_psq[NBLK*DIM];
__device__ float g_w2s[DIM];
__device__ float g_b2s;
__device__ u32   g_bar_count;
__device__ u32   g_bar_gen;
__device__ u32   g_work;

// ---------------------------------------------------------------- init kernel
__global__ void init_kernel() {
    int i = blockIdx.x * blockDim.x + threadIdx.x;
    if (i < ND) g_cursor[i] = 0;
    if (i == ND) { g_bar_count = 0; g_bar_gen = 0; g_ovfCnt = 0; g_work = 0; }
}

// ---------------------------------------------------------------- f32x2 helpers
__device__ __forceinline__ u64 pack2(float lo, float hi) {
    u64 r;
    asm("mov.b64 %0, {%1, %2};" : "=l"(r) : "f"(lo), "f"(hi));
    return r;
}
__device__ __forceinline__ void unpack2(u64 v, float& lo, float& hi) {
    asm("mov.b64 {%0, %1}, %2;" : "=f"(lo), "=f"(hi) : "l"(v));
}
__device__ __forceinline__ void fma2(u64& acc, u64 a, u64 b) {
    asm("fma.rn.f32x2 %0, %1, %2, %0;" : "+l"(acc) : "l"(a), "l"(b));
}
__device__ __forceinline__ u64 umin64(u64 a, u64 b) { return a < b ? a : b; }

// ---------------------------------------------------------------- shared layout
// phase B: [0,16384) w1pk u64[2048] | [16384) b1s | [16640) w2ss | [16896,17920) ssel
// phase C: [0,32768) wcp | [32768,34816) red
#define SH_BYTES (35*1024)

__global__ void __launch_bounds__(NTHR, 2)
mega_kernel(const int* __restrict__ DKG,
            const float* __restrict__ drug_emb,
            const float* __restrict__ rel_emb,
            const float* __restrict__ tail_emb,
            const float* __restrict__ W1,
            const float* __restrict__ b1,
            const float* __restrict__ W2,
            const float* __restrict__ b2,
            const float* __restrict__ Wc,
            const float* __restrict__ bc,
            const float* __restrict__ gamma,
            const float* __restrict__ beta,
            float* __restrict__ out,
            int E, u32 k1x, u32 k1y, u32 kLx, u32 kLy) {
    __shared__ __align__(16) char sh_raw[SH_BYTES];
    __shared__ u32 s_gen;

    const int tid  = threadIdx.x;
    const int bid  = blockIdx.x;
    const int gtid = bid * NTHR + tid;
    const int nth  = NBLK * NTHR;
    const int lane = tid & 31;
    const int wid  = tid >> 5;

    if (tid == 0) s_gen = 0;

    auto gsync = [&]() {
        __syncthreads();
        if (tid == 0) {
            u32 target = s_gen + 1;
            __threadfence();
            u32 t = atomicAdd(&g_bar_count, 1u);
            if (t == (u32)NBLK - 1) {
                atomicExch(&g_bar_count, 0u);
                __threadfence();
                atomicExch(&g_bar_gen, target);
            } else {
                volatile u32* vg = &g_bar_gen;
                while (*vg < target) { }
            }
            __threadfence();
            s_gen = target;
        }
        __syncthreads();
    };

    // ============ phase A: threefry + direct bucket scatter ============
    if (bid == NBLK - 1) {
        if (tid < DIM) {
            float s = 0.f;
            for (int j = 0; j < DIM; j++) s += W2[tid*DIM + j];
            g_w2s[tid] = s;
        }
        if (tid == DIM) {
            float s = 0.f;
            for (int j = 0; j < DIM; j++) s += b2[j];
            g_b2s = s;
        }
    }
    #pragma unroll 2
    for (int e = gtid; e < E; e += nth) {
        int h = DKG[3*e];
        u32 bits = rbits_stream(k1x, k1y, e);
        u64 key = (((u64)(bits >> 9)) << 20) | (u32)e;
        int slot = atomicAdd(&g_cursor[h], 1);
        if (slot < CAP) g_bucket[(size_t)h*CAP + slot] = key;
        else {
            int o = atomicAdd(&g_ovfCnt, 1);
            if (o < OVFCAP) g_ovf[o] = ((u64)h << 43) | key;
        }
    }
    gsync();

    // ============ phase B fused: select top16 + score + aggregate (work-stealing) ============
    {
        u64*   w1pk  = (u64*)sh_raw;                  // [ipair*64 + j], 2048 u64
        float* b1s   = (float*)(sh_raw + 16384);
        float* w2ss  = (float*)(sh_raw + 16640);
        int*   ssel  = (int*)(sh_raw + 16896) + wid * 16;

        for (int i = tid; i < 32*64; i += NTHR) {
            int ip = i >> 6, j = i & 63;
            w1pk[i] = pack2(W1[(2*ip)*DIM + j], W1[(2*ip + 1)*DIM + j]);
        }
        if (tid < DIM)        b1s[tid] = b1[tid];
        else if (tid < 2*DIM) w2ss[tid - DIM] = g_w2s[tid - DIM];
        __syncthreads();
        const float b2s = g_b2s;
        const u64 FULLK = ~0ULL;

        for (;;) {
            int d;
            if (lane == 0) d = (int)atomicAdd(&g_work, 1u);
            d = __shfl_sync(0xffffffffu, d, 0);
            if (d >= ND) break;

            const int degd = g_cursor[d];
            const int cnt  = (degd < SS) ? degd : SS;
            const u64* bkt = g_bucket + (size_t)d*CAP;

            if (degd >= SS && degd <= REGCAP) {
                // ================= FAST PATH (cnt == 16) =================
                u64 c0 = (lane       < degd) ? bkt[lane]       : FULLK;
                u64 c1 = (lane + 32  < degd) ? bkt[lane + 32]  : FULLK;
                u64 c2 = (lane + 64  < degd) ? bkt[lane + 64]  : FULLK;
                u64 c3 = (lane + 96  < degd) ? bkt[lane + 96]  : FULLK;
                u64 c4 = (lane + 128 < degd) ? bkt[lane + 128] : FULLK;
                u64 lmin = umin64(umin64(umin64(c0, c1), umin64(c2, c3)), c4);
                int myedge = 0;
                #pragma unroll
                for (int r = 0; r < SS; r++) {
                    u64 m = lmin;
                    #pragma unroll
                    for (int o = 16; o; o >>= 1) {
                        u64 t = __shfl_xor_sync(0xffffffffu, m, o);
                        m = umin64(m, t);
                    }
                    if (lane == r) myedge = (int)(m & 0xFFFFFu);
                    if (lmin == m) {
                        if      (c0 == m) c0 = FULLK;
                        else if (c1 == m) c1 = FULLK;
                        else if (c2 == m) c2 = FULLK;
                        else if (c3 == m) c3 = FULLK;
                        else              c4 = FULLK;
                        lmin = umin64(umin64(umin64(c0, c1), umin64(c2, c3)), c4);
                    }
                }

                int tail = 0, rel = 0;
                if (lane < SS) {
                    tail = DKG[3*myedge + 1];
                    rel  = DKG[3*myedge + 2];
                }

                const float2 de2 = ((const float2*)(drug_emb + d*DIM))[lane];
                const u64 bin0 = pack2(b1s[lane], 0.f);
                const u64 bin1 = pack2(b1s[lane + 32], 0.f);
                const float w20 = w2ss[lane], w21 = w2ss[lane + 32];

                float myscore = 0.f;
                #pragma unroll
                for (int k = 0; k < SS; k += 4) {
                    int rA = __shfl_sync(0xffffffffu, rel, k);
                    int rB = __shfl_sync(0xffffffffu, rel, k + 1);
                    int rC = __shfl_sync(0xffffffffu, rel, k + 2);
                    int rD = __shfl_sync(0xffffffffu, rel, k + 3);
                    float2 reA = ((const float2*)(rel_emb + rA*DIM))[lane];
                    float2 reB = ((const float2*)(rel_emb + rB*DIM))[lane];
                    float2 reC = ((const float2*)(rel_emb + rC*DIM))[lane];
                    float2 reD = ((const float2*)(rel_emb + rD*DIM))[lane];
                    u64 hA = pack2(de2.x*reA.x, de2.y*reA.y);
                    u64 hB = pack2(de2.x*reB.x, de2.y*reB.y);
                    u64 hC = pack2(de2.x*reC.x, de2.y*reC.y);
                    u64 hD = pack2(de2.x*reD.x, de2.y*reD.y);
                    u64 aA0 = bin0, aA1 = bin1, aB0 = bin0, aB1 = bin1;
                    u64 aC0 = bin0, aC1 = bin1, aD0 = bin0, aD1 = bin1;
                    #pragma unroll
                    for (int ip = 0; ip < 32; ip++) {
                        u64 w0  = w1pk[ip*64 + lane];
                        u64 w1v = w1pk[ip*64 + 32 + lane];
                        u64 hb;
                        hb = __shfl_sync(0xffffffffu, hA, ip);
                        fma2(aA0, hb, w0); fma2(aA1, hb, w1v);
                        hb = __shfl_sync(0xffffffffu, hB, ip);
                        fma2(aB0, hb, w0); fma2(aB1, hb, w1v);
                        hb = __shfl_sync(0xffffffffu, hC, ip);
                        fma2(aC0, hb, w0); fma2(aC1, hb, w1v);
                        hb = __shfl_sync(0xffffffffu, hD, ip);
                        fma2(aD0, hb, w0); fma2(aD1, hb, w1v);
                    }
                    float e0, o0, e1, o1;
                    unpack2(aA0, e0, o0); unpack2(aA1, e1, o1);
                    float pA = (1.f/(1.f+__expf(-(e0+o0))))*w20
                             + (1.f/(1.f+__expf(-(e1+o1))))*w21;
                    unpack2(aB0, e0, o0); unpack2(aB1, e1, o1);
                    float pB = (1.f/(1.f+__expf(-(e0+o0))))*w20
                             + (1.f/(1.f+__expf(-(e1+o1))))*w21;
                    unpack2(aC0, e0, o0); unpack2(aC1, e1, o1);
                    float pC = (1.f/(1.f+__expf(-(e0+o0))))*w20
                             + (1.f/(1.f+__expf(-(e1+o1))))*w21;
                    unpack2(aD0, e0, o0); unpack2(aD1, e1, o1);
                    float pD = (1.f/(1.f+__expf(-(e0+o0))))*w20
                             + (1.f/(1.f+__expf(-(e1+o1))))*w21;
                    #pragma unroll
                    for (int o = 16; o; o >>= 1) {
                        pA += __shfl_xor_sync(0xffffffffu, pA, o);
                        pB += __shfl_xor_sync(0xffffffffu, pB, o);
                        pC += __shfl_xor_sync(0xffffffffu, pC, o);
                        pD += __shfl_xor_sync(0xffffffffu, pD, o);
                    }
                    if (lane == k)     myscore = pA + b2s;
                    if (lane == k + 1) myscore = pB + b2s;
                    if (lane == k + 2) myscore = pC + b2s;
                    if (lane == k + 3) myscore = pD + b2s;
                }

                // ---- aggregation: fully unrolled, loads batched ----
                float acc0 = 0.f, acc1 = 0.f;
                #pragma unroll
                for (int k = 0; k < SS; k++) {
                    float sc = __shfl_sync(0xffffffffu, myscore, k);
                    int   t  = __shfl_sync(0xffffffffu, tail, k);
                    acc0 = fmaf(sc, tail_emb[t*DIM + lane], acc0);
                    acc1 = fmaf(sc, tail_emb[t*DIM + 32 + lane], acc1);
                }
                g_neigh[d*DIM + lane]      = acc0;
                g_neigh[d*DIM + 32 + lane] = acc1;

            } else if (cnt > 0) {
                // ================= SLOW PATH (deg < 16 or deg > REGCAP) =================
                int myedge = 0;
                if (degd <= REGCAP) {
                    u64 c0 = (lane       < degd) ? bkt[lane]       : FULLK;
                    u64 c1 = (lane + 32  < degd) ? bkt[lane + 32]  : FULLK;
                    u64 c2 = (lane + 64  < degd) ? bkt[lane + 64]  : FULLK;
                    u64 c3 = (lane + 96  < degd) ? bkt[lane + 96]  : FULLK;
                    u64 c4 = (lane + 128 < degd) ? bkt[lane + 128] : FULLK;
                    u64 lmin = umin64(umin64(umin64(c0, c1), umin64(c2, c3)), c4);
                    for (int r = 0; r < cnt; r++) {
                        u64 m = lmin;
                        #pragma unroll
                        for (int o = 16; o; o >>= 1) {
                            u64 t = __shfl_xor_sync(0xffffffffu, m, o);
                            m = umin64(m, t);
                        }
                        if (lane == r) myedge = (int)(m & 0xFFFFFu);
                        if (lmin == m) {
                            if      (c0 == m) c0 = FULLK;
                            else if (c1 == m) c1 = FULLK;
                            else if (c2 == m) c2 = FULLK;
                            else if (c3 == m) c3 = FULLK;
                            else              c4 = FULLK;
                            lmin = umin64(umin64(umin64(c0, c1), umin64(c2, c3)), c4);
                        }
                    }
                } else {
                    int nb = (degd < CAP) ? degd : CAP;
                    int novf = g_ovfCnt; if (novf > OVFCAP) novf = OVFCAP;
                    for (int t = lane; t < nb; t += 32) {
                        u64 k = bkt[t];
                        int rank = 0;
                        for (int j = 0; j < nb; j++) rank += (bkt[j] < k);
                        for (int o = 0; o < novf; o++) {
                            u64 v = g_ovf[o];
                            if ((int)(v >> 43) == d) rank += ((v & 0x7FFFFFFFFFFULL) < k);
                        }
                        if (rank < SS) ssel[rank] = (int)(k & 0xFFFFFu);
                    }
                    for (int t = lane; t < novf; t += 32) {
                        u64 v = g_ovf[t];
                        if ((int)(v >> 43) == d) {
                            u64 k = v & 0x7FFFFFFFFFFULL;
                            int rank = 0;
                            for (int j = 0; j < nb; j++) rank += (bkt[j] < k);
                            for (int o = 0; o < novf; o++) {
                                u64 w = g_ovf[o];
                                if ((int)(w >> 43) == d) rank += ((w & 0x7FFFFFFFFFFULL) < k);
                            }
                            if (rank < SS) ssel[rank] = (int)(k & 0xFFFFFu);
                        }
                    }
                    __syncwarp();
                    if (lane < cnt) myedge = ssel[lane];
                }

                int tail = 0, rel = 0;
                if (lane < cnt) {
                    tail = DKG[3*myedge + 1];
                    rel  = DKG[3*myedge + 2];
                }
                __syncwarp();

                const float2 de2 = ((const float2*)(drug_emb + d*DIM))[lane];
                const u64 bin0 = pack2(b1s[lane], 0.f);
                const u64 bin1 = pack2(b1s[lane + 32], 0.f);
                const float w20 = w2ss[lane], w21 = w2ss[lane + 32];

                float myscore = 0.f;
                for (int k = 0; k < cnt; k++) {
                    int rA = __shfl_sync(0xffffffffu, rel, k);
                    float2 reA = ((const float2*)(rel_emb + rA*DIM))[lane];
                    u64 hA = pack2(de2.x*reA.x, de2.y*reA.y);
                    u64 aA0 = bin0, aA1 = bin1;
                    #pragma unroll
                    for (int ip = 0; ip < 32; ip++) {
                        u64 w0  = w1pk[ip*64 + lane];
                        u64 w1v = w1pk[ip*64 + 32 + lane];
                        u64 hb = __shfl_sync(0xffffffffu, hA, ip);
                        fma2(aA0, hb, w0); fma2(aA1, hb, w1v);
                    }
                    float e0, o0, e1, o1;
                    unpack2(aA0, e0, o0); unpack2(aA1, e1, o1);
                    float pA = (1.f/(1.f+__expf(-(e0+o0))))*w20
                             + (1.f/(1.f+__expf(-(e1+o1))))*w21;
                    #pragma unroll
                    for (int o = 16; o; o >>= 1) pA += __shfl_xor_sync(0xffffffffu, pA, o);
                    if (lane == k) myscore = pA + b2s;
                }

                float acc0 = 0.f, acc1 = 0.f;
                for (int k = 0; k < cnt; k++) {
                    float sc = __shfl_sync(0xffffffffu, myscore, k);
                    int   t  = __shfl_sync(0xffffffffu, tail, k);
                    acc0 = fmaf(sc, tail_emb[t*DIM + lane], acc0);
                    acc1 = fmaf(sc, tail_emb[t*DIM + 32 + lane], acc1);
                }
                if (degd < SS) {
                    for (int s = 0; s < SS - degd; s++) {
                        u32 bits = rbits_stream(kLx, kLy, d*SS + s);
                        int idx = (int)((bits % 2147483647u) % (u32)degd);
                        float sc = __shfl_sync(0xffffffffu, myscore, idx);
                        int   t  = __shfl_sync(0xffffffffu, tail, idx);
                        acc0 = fmaf(sc, tail_emb[t*DIM + lane], acc0);
                        acc1 = fmaf(sc, tail_emb[t*DIM + 32 + lane], acc1);
                    }
                }
                g_neigh[d*DIM + lane]      = acc0;
                g_neigh[d*DIM + 32 + lane] = acc1;
            } else {
                g_neigh[d*DIM + lane]      = 0.f;
                g_neigh[d*DIM + 32 + lane] = 0.f;
            }
        }
    }
    gsync();

    // ============ phase C: y = [drug_emb, neigh] @ Wc + bc (shfl-broadcast inputs) ============
    {
        u64*   wcp = (u64*)sh_raw;                   // 128*32 u64 = 32KB
        float* red = (float*)(sh_raw + 32768);       // 512 floats
        for (int i = tid; i < 2*DIM*32; i += NTHR) {
            int r = i >> 5, c = i & 31;
            wcp[i] = pack2(Wc[r*DIM + c], Wc[r*DIM + c + 32]);
        }
        __syncthreads();
        const int sub = tid >> 5;                    // 0..15
        const int o = lane;
        const u64 bcv = pack2(bc[o], bc[o + 32]);
        float S0 = 0.f, S1 = 0.f, Q0 = 0.f, Q1 = 0.f;
        const int NR32 = (ND + 31) / 32;             // 313
        for (int r32 = bid; r32 < NR32; r32 += NBLK) {
            int row0 = r32*32 + sub;
            int row1 = row0 + 16;
            bool has1 = (row1 < ND);
            int row1c = has1 ? row1 : row0;
            // coalesced per-lane loads of both rows' inputs
            float2 deA = ((const float2*)(drug_emb + row0*DIM))[lane];
            float2 neA = ((const float2*)(g_neigh + row0*DIM))[lane];
            float2 deB = ((const float2*)(drug_emb + row1c*DIM))[lane];
            float2 neB = ((const float2*)(g_neigh + row1c*DIM))[lane];
            u64 accR0 = bcv, accR1 = bcv;
            #pragma unroll
            for (int i = 0; i < DIM; i++) {
                u64 w = wcp[i*32 + o];
                float v0 = __shfl_sync(0xffffffffu, (i & 1) ? deA.y : deA.x, i >> 1);
                float v1 = __shfl_sync(0xffffffffu, (i & 1) ? deB.y : deB.x, i >> 1);
                fma2(accR0, pack2(v0, v0), w);
                fma2(accR1, pack2(v1, v1), w);
            }
            #pragma unroll
            for (int i = 0; i < DIM; i++) {
                u64 w = wcp[(DIM + i)*32 + o];
                float v0 = __shfl_sync(0xffffffffu, (i & 1) ? neA.y : neA.x, i >> 1);
                float v1 = __shfl_sync(0xffffffffu, (i & 1) ? neB.y : neB.x, i >> 1);
                fma2(accR0, pack2(v0, v0), w);
                fma2(accR1, pack2(v1, v1), w);
            }
            float y00, y01, y10, y11;
            unpack2(accR0, y00, y01);
            unpack2(accR1, y10, y11);
            g_y[row0*DIM + o]      = y00;
            g_y[row0*DIM + 32 + o] = y01;
            S0 += y00; S1 += y01; Q0 += y00*y00; Q1 += y01*y01;
            if (has1) {
                g_y[row1*DIM + o]      = y10;
                g_y[row1*DIM + 32 + o] = y11;
                S0 += y10; S1 += y11; Q0 += y10*y10; Q1 += y11*y11;
            }
        }
        red[tid] = S0;
        __syncthreads();
        if (tid < 32) { float s = 0.f;
            #pragma unroll
            for (int p = 0; p < 16; p++) s += red[p*32 + lane];
            g_psum[bid*DIM + lane] = s; }
        __syncthreads();
        red[tid] = S1;
        __syncthreads();
        if (tid < 32) { float s = 0.f;
            #pragma unroll
            for (int p = 0; p < 16; p++) s += red[p*32 + lane];
            g_psum[bid*DIM + 32 + lane] = s; }
        __syncthreads();
        red[tid] = Q0;
        __syncthreads();
        if (tid < 32) { float s = 0.f;
            #pragma unroll
            for (int p = 0; p < 16; p++) s += red[p*32 + lane];
            g_psq[bid*DIM + lane] = s; }
        __syncthreads();
        red[tid] = Q1;
        __syncthreads();
        if (tid < 32) { float s = 0.f;
            #pragma unroll
            for (int p = 0; p < 16; p++) s += red[p*32 + lane];
            g_psq[bid*DIM + 32 + lane] = s; }
    }
    gsync();

    // ============ phase D: distributed BN stats + normalize + write ============
    {
        float* rs = (float*)sh_raw;                 // 512
        float* rq = (float*)(sh_raw + 2048);        // 512
        float* A  = (float*)(sh_raw + 4096);        // 64: gamma*rstd
        float* B  = (float*)(sh_raw + 4352);        // 64: beta - gamma*mean*rstd
        const int col = tid & 63, part = tid >> 6;  // 8 parts
        float s = 0.f, q = 0.f;
        for (int b = part; b < NBLK; b += 8) {
            s += g_psum[b*DIM + col];
            q += g_psq[b*DIM + col];
        }
        rs[tid] = s; rq[tid] = q;
        __syncthreads();
        if (tid < 64) {
            float S = 0.f, Q = 0.f;
            #pragma unroll
            for (int p = 0; p < 8; p++) { S += rs[p*64 + col]; Q += rq[p*64 + col]; }
            float mean = S / (float)ND;
            float var  = Q / (float)ND - mean * mean;
            float rstd = rsqrtf(var + 1e-5f);
            float gm = gamma[col];
            A[col] = gm * rstd;
            B[col] = beta[col] - gm * mean * rstd;
        }
        __syncthreads();

        const float4* y4 = (const float4*)g_y;
        float4* o4 = (float4*)out;
        for (int t = gtid; t < ND*DIM/4; t += nth) {
            int c = (t*4) & 63;
            float4 v = y4[t];
            float4 r;
            r.x = fmaf(v.x, A[c+0], B[c+0]);
            r.y = fmaf(v.y, A[c+1], B[c+1]);
            r.z = fmaf(v.z, A[c+2], B[c+2]);
            r.w = fmaf(v.w, A[c+3], B[c+3]);
            o4[t] = r;
        }
    }
}

// ---------------------------------------------------------------- host
static void compute_keys(u32& k1x, u32& k1y, u32& kLx, u32& kLy) {
    u32 a, b, c, d, e, f;
    threefry(0u, 42u, 0u, 0u, a, b);   // k1 = split(key(42))[0]
    k1x = a; k1y = b;
    threefry(0u, 42u, 0u, 1u, c, d);   // k2 = split(key(42))[1]
    threefry(c, d, 0u, 1u, e, f);      // split(k2)[1]
    kLx = e; kLy = f;
}

extern "C" void kernel_launch(void* const* d_in, const int* in_sizes, int n_in,
                              void* d_out, int out_size) {
    const float* HF       = (const float*)d_in[0];
    const float* X        = (const float*)d_in[1];
    const float* drug_emb = (const float*)d_in[2];
    const float* rel_emb  = (const float*)d_in[3];
    const float* tail_emb = (const float*)d_in[4];
    const float* W1       = (const float*)d_in[5];
    const float* b1       = (const float*)d_in[6];
    const float* W2       = (const float*)d_in[7];
    const float* b2       = (const float*)d_in[8];
    const float* Wc       = (const float*)d_in[9];
    const float* bc       = (const float*)d_in[10];
    const float* gamma    = (const float*)d_in[11];
    const float* beta     = (const float*)d_in[12];
    const int*   DKG      = (const int*)d_in[13];
    int E    = in_sizes[13] / 3;
    int hf_n = in_sizes[0];
    int x_n  = in_sizes[1];
    float* out = (float*)d_out;

    u32 k1x, k1y, kLx, kLy;
    compute_keys(k1x, k1y, kLx, kLy);

    cudaMemcpyAsync(out, HF, (size_t)hf_n * sizeof(float), cudaMemcpyDeviceToDevice, 0);
    cudaMemcpyAsync(out + hf_n + ND*DIM, X, (size_t)x_n * sizeof(float),
                    cudaMemcpyDeviceToDevice, 0);

    init_kernel<<<(ND + 256)/256, 256>>>();
    mega_kernel<<<NBLK, NTHR>>>(DKG, drug_emb, rel_emb, tail_emb, W1, b1, W2, b2,
                                Wc, bc, gamma, beta, out + hf_n,
                                E, k1x, k1y, kLx, kLy);
}

// round 8
// speedup vs baseline: 2.0451x; 1.0356x over previous
#include <cuda_runtime.h>
#include <stdint.h>

#define ND    10000
#define DIM   64
#define SS    16
#define EMAX  1000000
#define NBLK  296
#define NTHR  512
#define NWPB  16                 // warps per block
#define NWARP (NBLK*NWPB)
#define CAP   192                // per-drug bucket capacity (deg ~ Poisson(100))
#define REGCAP 160               // fast-path selection capacity (5 keys/lane)
#define OVFCAP 8192

typedef unsigned int u32;
typedef unsigned long long u64;

// ---------------------------------------------------------------- threefry2x32
__host__ __device__ __forceinline__ void threefry(u32 k0, u32 k1, u32 x0, u32 x1,
                                                  u32& o0, u32& o1) {
#ifdef __CUDA_ARCH__
#define TFR(a,b,r) { a += b; b = __funnelshift_l(b, b, r); b ^= a; }
#else
#define TFR(a,b,r) { a += b; b = (b<<r)|(b>>(32-r)); b ^= a; }
#endif
    u32 ks2 = k0 ^ k1 ^ 0x1BD11BDAu;
    x0 += k0; x1 += k1;
    TFR(x0,x1,13); TFR(x0,x1,15); TFR(x0,x1,26); TFR(x0,x1,6);
    x0 += k1; x1 += ks2 + 1u;
    TFR(x0,x1,17); TFR(x0,x1,29); TFR(x0,x1,16); TFR(x0,x1,24);
    x0 += ks2; x1 += k0 + 2u;
    TFR(x0,x1,13); TFR(x0,x1,15); TFR(x0,x1,26); TFR(x0,x1,6);
    x0 += k0; x1 += k1 + 3u;
    TFR(x0,x1,17); TFR(x0,x1,29); TFR(x0,x1,16); TFR(x0,x1,24);
    x0 += k1; x1 += ks2 + 4u;
    TFR(x0,x1,13); TFR(x0,x1,15); TFR(x0,x1,26); TFR(x0,x1,6);
    x0 += ks2; x1 += k0 + 5u;
    o0 = x0; o1 = x1;
#undef TFR
}
__device__ __forceinline__ u32 rbits_stream(u32 kx, u32 ky, int i) {
    u32 a, b; threefry(kx, ky, 0u, (u32)i, a, b);
    return a ^ b;
}

// ---------------------------------------------------------------- scratch
__device__ int   g_cursor[ND];               // zeroed at module load; re-zeroed in phase D
__device__ u64   g_bucket[(size_t)ND*CAP];   // rank(23)|edge(20)
__device__ int   g_ovfCnt;
__device__ u64   g_ovf[OVFCAP];              // d(14) << 43 | rank23|edge20
__device__ float g_neigh[ND*DIM];
__device__ float g_y[ND*DIM];
__device__ float g_psum[NBLK*DIM];
__device__ float g_psq[NBLK*DIM];
__device__ float g_w2s[DIM];
__device__ float g_b2s;
__device__ u32   g_bar_count;
__device__ u32   g_bar_gen;                  // monotonically increasing across replays
__device__ u32   g_work;

// ---------------------------------------------------------------- f32x2 helpers
__device__ __forceinline__ u64 pack2(float lo, float hi) {
    u64 r;
    asm("mov.b64 %0, {%1, %2};" : "=l"(r) : "f"(lo), "f"(hi));
    return r;
}
__device__ __forceinline__ void unpack2(u64 v, float& lo, float& hi) {
    asm("mov.b64 {%0, %1}, %2;" : "=f"(lo), "=f"(hi) : "l"(v));
}
__device__ __forceinline__ void fma2(u64& acc, u64 a, u64 b) {
    asm("fma.rn.f32x2 %0, %1, %2, %0;" : "+l"(acc) : "l"(a), "l"(b));
}
__device__ __forceinline__ u64 umin64(u64 a, u64 b) { return a < b ? a : b; }

// ---------------------------------------------------------------- shared layout
// phase B: [0,16384) w1pk u64[2048] | [16384) b1s | [16640) w2ss | [16896,17920) ssel
// phase C: [0,32768) wcp | [32768,34816) red
#define SH_BYTES (35*1024)

__global__ void __launch_bounds__(NTHR, 2)
mega_kernel(const int* __restrict__ DKG,
            const float* __restrict__ HF,
            const float* __restrict__ X,
            const float* __restrict__ drug_emb,
            const float* __restrict__ rel_emb,
            const float* __restrict__ tail_emb,
            const float* __restrict__ W1,
            const float* __restrict__ b1,
            const float* __restrict__ W2,
            const float* __restrict__ b2,
            const float* __restrict__ Wc,
            const float* __restrict__ bc,
            const float* __restrict__ gamma,
            const float* __restrict__ beta,
            float* __restrict__ outBase,     // d_out base
            int E, int hf_n, int x_n,
            u32 k1x, u32 k1y, u32 kLx, u32 kLy) {
    __shared__ __align__(16) char sh_raw[SH_BYTES];
    __shared__ u32 s_gen;

    const int tid  = threadIdx.x;
    const int bid  = blockIdx.x;
    const int gtid = bid * NTHR + tid;
    const int nth  = NBLK * NTHR;
    const int lane = tid & 31;
    const int wid  = tid >> 5;

    float* out = outBase + hf_n;             // BN output region

    // snapshot barrier generation (replay-safe: all blocks read the same stable
    // value before any release can occur, since release requires all arrivals)
    if (tid == 0) s_gen = *((volatile u32*)&g_bar_gen);

    auto gsync = [&]() {
        __syncthreads();
        if (tid == 0) {
            u32 target = s_gen + 1;
            __threadfence();
            u32 t = atomicAdd(&g_bar_count, 1u);
            if (t == (u32)NBLK - 1) {
                atomicExch(&g_bar_count, 0u);
                __threadfence();
                atomicExch(&g_bar_gen, target);
            } else {
                volatile u32* vg = &g_bar_gen;
                while (*vg < target) { }
            }
            __threadfence();
            s_gen = target;
        }
        __syncthreads();
    };

    // ============ phase A: passthrough copies + threefry + bucket scatter ============
    {
        // HF -> out[0:hf_n), X -> out[hf_n + ND*DIM : ...)   (float4)
        const float4* hf4 = (const float4*)HF;
        float4* o4 = (float4*)outBase;
        for (int t = gtid; t < hf_n/4; t += nth) o4[t] = hf4[t];
        const float4* x4 = (const float4*)X;
        float4* ox4 = (float4*)(outBase + hf_n + ND*DIM);
        for (int t = gtid; t < x_n/4; t += nth) ox4[t] = x4[t];
    }
    if (bid == NBLK - 1) {
        if (tid < DIM) {
            float s = 0.f;
            for (int j = 0; j < DIM; j++) s += W2[tid*DIM + j];
            g_w2s[tid] = s;
        }
        if (tid == DIM) {
            float s = 0.f;
            for (int j = 0; j < DIM; j++) s += b2[j];
            g_b2s = s;
        }
    }
    #pragma unroll 4
    for (int e = gtid; e < E; e += nth) {
        int h = DKG[3*e];
        u32 bits = rbits_stream(k1x, k1y, e);
        u64 key = (((u64)(bits >> 9)) << 20) | (u32)e;
        int slot = atomicAdd(&g_cursor[h], 1);
        if (slot < CAP) g_bucket[(size_t)h*CAP + slot] = key;
        else {
            int o = atomicAdd(&g_ovfCnt, 1);
            if (o < OVFCAP) g_ovf[o] = ((u64)h << 43) | key;
        }
    }
    gsync();

    // ============ phase B fused: select top16 + score + aggregate (work-stealing) ============
    {
        u64*   w1pk  = (u64*)sh_raw;                  // [ipair*64 + j], 2048 u64
        float* b1s   = (float*)(sh_raw + 16384);
        float* w2ss  = (float*)(sh_raw + 16640);
        int*   ssel  = (int*)(sh_raw + 16896) + wid * 16;

        for (int i = tid; i < 32*64; i += NTHR) {
            int ip = i >> 6, j = i & 63;
            w1pk[i] = pack2(W1[(2*ip)*DIM + j], W1[(2*ip + 1)*DIM + j]);
        }
        if (tid < DIM)        b1s[tid] = b1[tid];
        else if (tid < 2*DIM) w2ss[tid - DIM] = g_w2s[tid - DIM];
        __syncthreads();
        const float b2s = g_b2s;
        const u64 FULLK = ~0ULL;

        for (;;) {
            int d;
            if (lane == 0) d = (int)atomicAdd(&g_work, 1u);
            d = __shfl_sync(0xffffffffu, d, 0);
            if (d >= ND) break;

            const int degd = g_cursor[d];
            const int cnt  = (degd < SS) ? degd : SS;
            const u64* bkt = g_bucket + (size_t)d*CAP;

            if (degd >= SS && degd <= REGCAP) {
                // ================= FAST PATH (cnt == 16) =================
                u64 c0 = (lane       < degd) ? bkt[lane]       : FULLK;
                u64 c1 = (lane + 32  < degd) ? bkt[lane + 32]  : FULLK;
                u64 c2 = (lane + 64  < degd) ? bkt[lane + 64]  : FULLK;
                u64 c3 = (lane + 96  < degd) ? bkt[lane + 96]  : FULLK;
                u64 c4 = (lane + 128 < degd) ? bkt[lane + 128] : FULLK;
                u64 lmin = umin64(umin64(umin64(c0, c1), umin64(c2, c3)), c4);
                int tail = 0, rel = 0;
                #pragma unroll
                for (int r = 0; r < SS; r++) {
                    // redux-min on top 32 bits; unique => exact full-key winner
                    u32 hi = (u32)(lmin >> 11);
                    u32 mhi = __reduce_min_sync(0xffffffffu, hi);
                    u32 bal = __ballot_sync(0xffffffffu, hi == mhi);
                    u64 m;
                    if (__popc(bal) == 1) {
                        m = __shfl_sync(0xffffffffu, lmin, __ffs(bal) - 1);
                    } else {
                        m = lmin;
                        #pragma unroll
                        for (int o = 16; o; o >>= 1)
                            m = umin64(m, __shfl_xor_sync(0xffffffffu, m, o));
                    }
                    int er = (int)(m & 0xFFFFFu);
                    if (lane == r) {                 // early gather, hidden by later rounds
                        tail = DKG[3*er + 1];
                        rel  = DKG[3*er + 2];
                    }
                    if (lmin == m) {
                        if      (c0 == m) c0 = FULLK;
                        else if (c1 == m) c1 = FULLK;
                        else if (c2 == m) c2 = FULLK;
                        else if (c3 == m) c3 = FULLK;
                        else              c4 = FULLK;
                        lmin = umin64(umin64(umin64(c0, c1), umin64(c2, c3)), c4);
                    }
                }

                const float2 de2 = ((const float2*)(drug_emb + d*DIM))[lane];
                const u64 bin0 = pack2(b1s[lane], 0.f);
                const u64 bin1 = pack2(b1s[lane + 32], 0.f);
                const float w20 = w2ss[lane], w21 = w2ss[lane + 32];

                float myscore = 0.f;
                #pragma unroll
                for (int k = 0; k < SS; k += 4) {
                    int rA = __shfl_sync(0xffffffffu, rel, k);
                    int rB = __shfl_sync(0xffffffffu, rel, k + 1);
                    int rC = __shfl_sync(0xffffffffu, rel, k + 2);
                    int rD = __shfl_sync(0xffffffffu, rel, k + 3);
                    float2 reA = ((const float2*)(rel_emb + rA*DIM))[lane];
                    float2 reB = ((const float2*)(rel_emb + rB*DIM))[lane];
                    float2 reC = ((const float2*)(rel_emb + rC*DIM))[lane];
                    float2 reD = ((const float2*)(rel_emb + rD*DIM))[lane];
                    u64 hA = pack2(de2.x*reA.x, de2.y*reA.y);
                    u64 hB = pack2(de2.x*reB.x, de2.y*reB.y);
                    u64 hC = pack2(de2.x*reC.x, de2.y*reC.y);
                    u64 hD = pack2(de2.x*reD.x, de2.y*reD.y);
                    u64 aA0 = bin0, aA1 = bin1, aB0 = bin0, aB1 = bin1;
                    u64 aC0 = bin0, aC1 = bin1, aD0 = bin0, aD1 = bin1;
                    #pragma unroll
                    for (int ip = 0; ip < 32; ip++) {
                        u64 w0  = w1pk[ip*64 + lane];
                        u64 w1v = w1pk[ip*64 + 32 + lane];
                        u64 hb;
                        hb = __shfl_sync(0xffffffffu, hA, ip);
                        fma2(aA0, hb, w0); fma2(aA1, hb, w1v);
                        hb = __shfl_sync(0xffffffffu, hB, ip);
                        fma2(aB0, hb, w0); fma2(aB1, hb, w1v);
                        hb = __shfl_sync(0xffffffffu, hC, ip);
                        fma2(aC0, hb, w0); fma2(aC1, hb, w1v);
                        hb = __shfl_sync(0xffffffffu, hD, ip);
                        fma2(aD0, hb, w0); fma2(aD1, hb, w1v);
                    }
                    float e0, o0, e1, o1;
                    unpack2(aA0, e0, o0); unpack2(aA1, e1, o1);
                    float pA = (1.f/(1.f+__expf(-(e0+o0))))*w20
                             + (1.f/(1.f+__expf(-(e1+o1))))*w21;
                    unpack2(aB0, e0, o0); unpack2(aB1, e1, o1);
                    float pB = (1.f/(1.f+__expf(-(e0+o0))))*w20
                             + (1.f/(1.f+__expf(-(e1+o1))))*w21;
                    unpack2(aC0, e0, o0); unpack2(aC1, e1, o1);
                    float pC = (1.f/(1.f+__expf(-(e0+o0))))*w20
                             + (1.f/(1.f+__expf(-(e1+o1))))*w21;
                    unpack2(aD0, e0, o0); unpack2(aD1, e1, o1);
                    float pD = (1.f/(1.f+__expf(-(e0+o0))))*w20
                             + (1.f/(1.f+__expf(-(e1+o1))))*w21;
                    #pragma unroll
                    for (int o = 16; o; o >>= 1) {
                        pA += __shfl_xor_sync(0xffffffffu, pA, o);
                        pB += __shfl_xor_sync(0xffffffffu, pB, o);
                        pC += __shfl_xor_sync(0xffffffffu, pC, o);
                        pD += __shfl_xor_sync(0xffffffffu, pD, o);
                    }
                    if (lane == k)     myscore = pA + b2s;
                    if (lane == k + 1) myscore = pB + b2s;
                    if (lane == k + 2) myscore = pC + b2s;
                    if (lane == k + 3) myscore = pD + b2s;
                }

                float acc0 = 0.f, acc1 = 0.f;
                #pragma unroll
                for (int k = 0; k < SS; k++) {
                    float sc = __shfl_sync(0xffffffffu, myscore, k);
                    int   t  = __shfl_sync(0xffffffffu, tail, k);
                    acc0 = fmaf(sc, tail_emb[t*DIM + lane], acc0);
                    acc1 = fmaf(sc, tail_emb[t*DIM + 32 + lane], acc1);
                }
                g_neigh[d*DIM + lane]      = acc0;
                g_neigh[d*DIM + 32 + lane] = acc1;

            } else if (cnt > 0) {
                // ================= SLOW PATH (deg < 16 or deg > REGCAP) =================
                int myedge = 0;
                if (degd <= REGCAP) {
                    u64 c0 = (lane       < degd) ? bkt[lane]       : FULLK;
                    u64 c1 = (lane + 32  < degd) ? bkt[lane + 32]  : FULLK;
                    u64 c2 = (lane + 64  < degd) ? bkt[lane + 64]  : FULLK;
                    u64 c3 = (lane + 96  < degd) ? bkt[lane + 96]  : FULLK;
                    u64 c4 = (lane + 128 < degd) ? bkt[lane + 128] : FULLK;
                    u64 lmin = umin64(umin64(umin64(c0, c1), umin64(c2, c3)), c4);
                    for (int r = 0; r < cnt; r++) {
                        u64 m = lmin;
                        #pragma unroll
                        for (int o = 16; o; o >>= 1) {
                            u64 t = __shfl_xor_sync(0xffffffffu, m, o);
                            m = umin64(m, t);
                        }
                        if (lane == r) myedge = (int)(m & 0xFFFFFu);
                        if (lmin == m) {
                            if      (c0 == m) c0 = FULLK;
                            else if (c1 == m) c1 = FULLK;
                            else if (c2 == m) c2 = FULLK;
                            else if (c3 == m) c3 = FULLK;
                            else              c4 = FULLK;
                            lmin = umin64(umin64(umin64(c0, c1), umin64(c2, c3)), c4);
                        }
                    }
                } else {
                    int nb = (degd < CAP) ? degd : CAP;
                    int novf = g_ovfCnt; if (novf > OVFCAP) novf = OVFCAP;
                    for (int t = lane; t < nb; t += 32) {
                        u64 k = bkt[t];
                        int rank = 0;
                        for (int j = 0; j < nb; j++) rank += (bkt[j] < k);
                        for (int o = 0; o < novf; o++) {
                            u64 v = g_ovf[o];
                            if ((int)(v >> 43) == d) rank += ((v & 0x7FFFFFFFFFFULL) < k);
                        }
                        if (rank < SS) ssel[rank] = (int)(k & 0xFFFFFu);
                    }
                    for (int t = lane; t < novf; t += 32) {
                        u64 v = g_ovf[t];
                        if ((int)(v >> 43) == d) {
                            u64 k = v & 0x7FFFFFFFFFFULL;
                            int rank = 0;
                            for (int j = 0; j < nb; j++) rank += (bkt[j] < k);
                            for (int o = 0; o < novf; o++) {
                                u64 w = g_ovf[o];
                                if ((int)(w >> 43) == d) rank += ((w & 0x7FFFFFFFFFFULL) < k);
                            }
                            if (rank < SS) ssel[rank] = (int)(k & 0xFFFFFu);
                        }
                    }
                    __syncwarp();
                    if (lane < cnt) myedge = ssel[lane];
                }

                int tail = 0, rel = 0;
                if (lane < cnt) {
                    tail = DKG[3*myedge + 1];
                    rel  = DKG[3*myedge + 2];
                }
                __syncwarp();

                const float2 de2 = ((const float2*)(drug_emb + d*DIM))[lane];
                const u64 bin0 = pack2(b1s[lane], 0.f);
                const u64 bin1 = pack2(b1s[lane + 32], 0.f);
                const float w20 = w2ss[lane], w21 = w2ss[lane + 32];

                float myscore = 0.f;
                for (int k = 0; k < cnt; k++) {
                    int rA = __shfl_sync(0xffffffffu, rel, k);
                    float2 reA = ((const float2*)(rel_emb + rA*DIM))[lane];
                    u64 hA = pack2(de2.x*reA.x, de2.y*reA.y);
                    u64 aA0 = bin0, aA1 = bin1;
                    #pragma unroll
                    for (int ip = 0; ip < 32; ip++) {
                        u64 w0  = w1pk[ip*64 + lane];
                        u64 w1v = w1pk[ip*64 + 32 + lane];
                        u64 hb = __shfl_sync(0xffffffffu, hA, ip);
                        fma2(aA0, hb, w0); fma2(aA1, hb, w1v);
                    }
                    float e0, o0, e1, o1;
                    unpack2(aA0, e0, o0); unpack2(aA1, e1, o1);
                    float pA = (1.f/(1.f+__expf(-(e0+o0))))*w20
                             + (1.f/(1.f+__expf(-(e1+o1))))*w21;
                    #pragma unroll
                    for (int o = 16; o; o >>= 1) pA += __shfl_xor_sync(0xffffffffu, pA, o);
                    if (lane == k) myscore = pA + b2s;
                }

                float acc0 = 0.f, acc1 = 0.f;
                for (int k = 0; k < cnt; k++) {
                    float sc = __shfl_sync(0xffffffffu, myscore, k);
                    int   t  = __shfl_sync(0xffffffffu, tail, k);
                    acc0 = fmaf(sc, tail_emb[t*DIM + lane], acc0);
                    acc1 = fmaf(sc, tail_emb[t*DIM + 32 + lane], acc1);
                }
                if (degd < SS) {
                    for (int s = 0; s < SS - degd; s++) {
                        u32 bits = rbits_stream(kLx, kLy, d*SS + s);
                        int idx = (int)((bits % 2147483647u) % (u32)degd);
                        float sc = __shfl_sync(0xffffffffu, myscore, idx);
                        int   t  = __shfl_sync(0xffffffffu, tail, idx);
                        acc0 = fmaf(sc, tail_emb[t*DIM + lane], acc0);
                        acc1 = fmaf(sc, tail_emb[t*DIM + 32 + lane], acc1);
                    }
                }
                g_neigh[d*DIM + lane]      = acc0;
                g_neigh[d*DIM + 32 + lane] = acc1;
            } else {
                g_neigh[d*DIM + lane]      = 0.f;
                g_neigh[d*DIM + 32 + lane] = 0.f;
            }
        }
    }
    gsync();

    // ============ phase C: y = [drug_emb, neigh] @ Wc + bc (shfl-broadcast inputs) ============
    {
        if (gtid == 0) { g_work = 0; g_ovfCnt = 0; }   // replay-state reset (post-B barrier)
        u64*   wcp = (u64*)sh_raw;                   // 128*32 u64 = 32KB
        float* red = (float*)(sh_raw + 32768);       // 512 floats
        for (int i = tid; i < 2*DIM*32; i += NTHR) {
            int r = i >> 5, c = i & 31;
            wcp[i] = pack2(Wc[r*DIM + c], Wc[r*DIM + c + 32]);
        }
        __syncthreads();
        const int sub = tid >> 5;                    // 0..15
        const int o = lane;
        const u64 bcv = pack2(bc[o], bc[o + 32]);
        float S0 = 0.f, S1 = 0.f, Q0 = 0.f, Q1 = 0.f;
        const int NR32 = (ND + 31) / 32;             // 313
        for (int r32 = bid; r32 < NR32; r32 += NBLK) {
            int row0 = r32*32 + sub;
            int row1 = row0 + 16;
            bool has1 = (row1 < ND);
            int row1c = has1 ? row1 : row0;
            float2 deA = ((const float2*)(drug_emb + row0*DIM))[lane];
            float2 neA = ((const float2*)(g_neigh + row0*DIM))[lane];
            float2 deB = ((const float2*)(drug_emb + row1c*DIM))[lane];
            float2 neB = ((const float2*)(g_neigh + row1c*DIM))[lane];
            u64 accR0 = bcv, accR1 = bcv;
            #pragma unroll
            for (int i = 0; i < DIM; i++) {
                u64 w = wcp[i*32 + o];
                float v0 = __shfl_sync(0xffffffffu, (i & 1) ? deA.y : deA.x, i >> 1);
                float v1 = __shfl_sync(0xffffffffu, (i & 1) ? deB.y : deB.x, i >> 1);
                fma2(accR0, pack2(v0, v0), w);
                fma2(accR1, pack2(v1, v1), w);
            }
            #pragma unroll
            for (int i = 0; i < DIM; i++) {
                u64 w = wcp[(DIM + i)*32 + o];
                float v0 = __shfl_sync(0xffffffffu, (i & 1) ? neA.y : neA.x, i >> 1);
                float v1 = __shfl_sync(0xffffffffu, (i & 1) ? neB.y : neB.x, i >> 1);
                fma2(accR0, pack2(v0, v0), w);
                fma2(accR1, pack2(v1, v1), w);
            }
            float y00, y01, y10, y11;
            unpack2(accR0, y00, y01);
            unpack2(accR1, y10, y11);
            g_y[row0*DIM + o]      = y00;
            g_y[row0*DIM + 32 + o] = y01;
            S0 += y00; S1 += y01; Q0 += y00*y00; Q1 += y01*y01;
            if (has1) {
                g_y[row1*DIM + o]      = y10;
                g_y[row1*DIM + 32 + o] = y11;
                S0 += y10; S1 += y11; Q0 += y10*y10; Q1 += y11*y11;
            }
        }
        red[tid] = S0;
        __syncthreads();
        if (tid < 32) { float s = 0.f;
            #pragma unroll
            for (int p = 0; p < 16; p++) s += red[p*32 + lane];
            g_psum[bid*DIM + lane] = s; }
        __syncthreads();
        red[tid] = S1;
        __syncthreads();
        if (tid < 32) { float s = 0.f;
            #pragma unroll
            for (int p = 0; p < 16; p++) s += red[p*32 + lane];
            g_psum[bid*DIM + 32 + lane] = s; }
        __syncthreads();
        red[tid] = Q0;
        __syncthreads();
        if (tid < 32) { float s = 0.f;
            #pragma unroll
            for (int p = 0; p < 16; p++) s += red[p*32 + lane];
            g_psq[bid*DIM + lane] = s; }
        __syncthreads();
        red[tid] = Q1;
        __syncthreads();
        if (tid < 32) { float s = 0.f;
            #pragma unroll
            for (int p = 0; p < 16; p++) s += red[p*32 + lane];
            g_psq[bid*DIM + 32 + lane] = s; }
    }
    gsync();

    // ============ phase D: distributed BN stats + normalize + write + state reset ============
    {
        float* rs = (float*)sh_raw;                 // 512
        float* rq = (float*)(sh_raw + 2048);        // 512
        float* A  = (float*)(sh_raw + 4096);        // 64: gamma*rstd
        float* B  = (float*)(sh_raw + 4352);        // 64: beta - gamma*mean*rstd
        const int col = tid & 63, part = tid >> 6;  // 8 parts
        float s = 0.f, q = 0.f;
        for (int b = part; b < NBLK; b += 8) {
            s += g_psum[b*DIM + col];
            q += g_psq[b*DIM + col];
        }
        rs[tid] = s; rq[tid] = q;
        __syncthreads();
        if (tid < 64) {
            float S = 0.f, Q = 0.f;
            #pragma unroll
            for (int p = 0; p < 8; p++) { S += rs[p*64 + col]; Q += rq[p*64 + col]; }
            float mean = S / (float)ND;
            float var  = Q / (float)ND - mean * mean;
            float rstd = rsqrtf(var + 1e-5f);
            float gm = gamma[col];
            A[col] = gm * rstd;
            B[col] = beta[col] - gm * mean * rstd;
        }
        __syncthreads();

        const float4* y4 = (const float4*)g_y;
        float4* o4 = (float4*)out;
        for (int t = gtid; t < ND*DIM/4; t += nth) {
            int c = (t*4) & 63;
            float4 v = y4[t];
            float4 r;
            r.x = fmaf(v.x, A[c+0], B[c+0]);
            r.y = fmaf(v.y, A[c+1], B[c+1]);
            r.z = fmaf(v.z, A[c+2], B[c+2]);
            r.w = fmaf(v.w, A[c+3], B[c+3]);
            o4[t] = r;
        }

        // replay-state reset: g_cursor must be zero at next launch's phase A
        for (int i = gtid; i < ND; i += nth) g_cursor[i] = 0;
    }
}

// ---------------------------------------------------------------- host
static void compute_keys(u32& k1x, u32& k1y, u32& kLx, u32& kLy) {
    u32 a, b, c, d, e, f;
    threefry(0u, 42u, 0u, 0u, a, b);   // k1 = split(key(42))[0]
    k1x = a; k1y = b;
    threefry(0u, 42u, 0u, 1u, c, d);   // k2 = split(key(42))[1]
    threefry(c, d, 0u, 1u, e, f);      // split(k2)[1]
    kLx = e; kLy = f;
}

extern "C" void kernel_launch(void* const* d_in, const int* in_sizes, int n_in,
                              void* d_out, int out_size) {
    const float* HF       = (const float*)d_in[0];
    const float* X        = (const float*)d_in[1];
    const float* drug_emb = (const float*)d_in[2];
    const float* rel_emb  = (const float*)d_in[3];
    const float* tail_emb = (const float*)d_in[4];
    const float* W1       = (const float*)d_in[5];
    const float* b1       = (const float*)d_in[6];
    const float* W2       = (const float*)d_in[7];
    const float* b2       = (const float*)d_in[8];
    const float* Wc       = (const float*)d_in[9];
    const float* bc       = (const float*)d_in[10];
    const float* gamma    = (const float*)d_in[11];
    const float* beta     = (const float*)d_in[12];
    const int*   DKG      = (const int*)d_in[13];
    int E    = in_sizes[13] / 3;
    int hf_n = in_sizes[0];
    int x_n  = in_sizes[1];
    float* out = (float*)d_out;

    u32 k1x, k1y, kLx, kLy;
    compute_keys(k1x, k1y, kLx, kLy);

    mega_kernel<<<NBLK, NTHR>>>(DKG, HF, X, drug_emb, rel_emb, tail_emb,
                                W1, b1, W2, b2, Wc, bc, gamma, beta,
                                out, E, hf_n, x_n, k1x, k1y, kLx, kLy);
}

// round 9
// speedup vs baseline: 2.0461x; 1.0005x over previous
#include <cuda_runtime.h>
#include <stdint.h>

#define ND    10000
#define DIM   64
#define SS    16
#define EMAX  1000000
#define NBLK  296
#define NTHR  512
#define NWPB  16
#define NWARP (NBLK*NWPB)
#define CAP   192                // per-drug bucket capacity (deg ~ Poisson(100))
#define REGCAP 160               // fast-path selection capacity (5 keys/lane)
#define OVFCAP 8192
#define ABLK  1184               // scatter kernel blocks
#define ATHR  256

typedef unsigned int u32;
typedef unsigned long long u64;

// ---------------------------------------------------------------- threefry2x32
__host__ __device__ __forceinline__ void threefry(u32 k0, u32 k1, u32 x0, u32 x1,
                                                  u32& o0, u32& o1) {
#ifdef __CUDA_ARCH__
#define TFR(a,b,r) { a += b; b = __funnelshift_l(b, b, r); b ^= a; }
#else
#define TFR(a,b,r) { a += b; b = (b<<r)|(b>>(32-r)); b ^= a; }
#endif
    u32 ks2 = k0 ^ k1 ^ 0x1BD11BDAu;
    x0 += k0; x1 += k1;
    TFR(x0,x1,13); TFR(x0,x1,15); TFR(x0,x1,26); TFR(x0,x1,6);
    x0 += k1; x1 += ks2 + 1u;
    TFR(x0,x1,17); TFR(x0,x1,29); TFR(x0,x1,16); TFR(x0,x1,24);
    x0 += ks2; x1 += k0 + 2u;
    TFR(x0,x1,13); TFR(x0,x1,15); TFR(x0,x1,26); TFR(x0,x1,6);
    x0 += k0; x1 += k1 + 3u;
    TFR(x0,x1,17); TFR(x0,x1,29); TFR(x0,x1,16); TFR(x0,x1,24);
    x0 += k1; x1 += ks2 + 4u;
    TFR(x0,x1,13); TFR(x0,x1,15); TFR(x0,x1,26); TFR(x0,x1,6);
    x0 += ks2; x1 += k0 + 5u;
    o0 = x0; o1 = x1;
#undef TFR
}
__device__ __forceinline__ u32 rbits_stream(u32 kx, u32 ky, int i) {
    u32 a, b; threefry(kx, ky, 0u, (u32)i, a, b);
    return a ^ b;
}

// ---------------------------------------------------------------- scratch
__device__ int   g_cursor[ND];               // zero at launch; re-zeroed in phase D
__device__ u64   g_bucket[(size_t)ND*CAP];   // rank(23)|edge(20)
__device__ int   g_ovfCnt;
__device__ u64   g_ovf[OVFCAP];
__device__ float g_neigh[ND*DIM];
__device__ float g_y[ND*DIM];
__device__ float g_psum[NBLK*DIM];
__device__ float g_psq[NBLK*DIM];
__device__ float g_w2s[DIM];
__device__ float g_b2s;
__device__ u32   g_bar_count;
__device__ u32   g_bar_gen;                  // monotonic across replays
__device__ u32   g_work;

// ---------------------------------------------------------------- f32x2 helpers
__device__ __forceinline__ u64 pack2(float lo, float hi) {
    u64 r;
    asm("mov.b64 %0, {%1, %2};" : "=l"(r) : "f"(lo), "f"(hi));
    return r;
}
__device__ __forceinline__ void unpack2(u64 v, float& lo, float& hi) {
    asm("mov.b64 {%0, %1}, %2;" : "=f"(lo), "=f"(hi) : "l"(v));
}
__device__ __forceinline__ void fma2(u64& acc, u64 a, u64 b) {
    asm("fma.rn.f32x2 %0, %1, %2, %0;" : "+l"(acc) : "l"(a), "l"(b));
}
__device__ __forceinline__ u64 umin64(u64 a, u64 b) { return a < b ? a : b; }

// ================================================================ scatter kernel
// High-occupancy (low-reg, no smem): passthrough copies + w2s + threefry scatter.
__global__ void scatter_kernel(const int* __restrict__ DKG,
                               const float* __restrict__ HF,
                               const float* __restrict__ X,
                               const float* __restrict__ W2,
                               const float* __restrict__ b2,
                               float* __restrict__ outBase,
                               int E, int hf_n, int x_n,
                               u32 k1x, u32 k1y) {
    const int gtid = blockIdx.x * ATHR + threadIdx.x;
    const int nth  = ABLK * ATHR;

    // passthrough copies (float4)
    {
        const float4* hf4 = (const float4*)HF;
        float4* o4 = (float4*)outBase;
        for (int t = gtid; t < hf_n/4; t += nth) o4[t] = hf4[t];
        const float4* x4 = (const float4*)X;
        float4* ox4 = (float4*)(outBase + hf_n + ND*DIM);
        for (int t = gtid; t < x_n/4; t += nth) ox4[t] = x4[t];
    }
    if (blockIdx.x == ABLK - 1) {
        int t = threadIdx.x;
        if (t < DIM) {
            float s = 0.f;
            for (int j = 0; j < DIM; j++) s += W2[t*DIM + j];
            g_w2s[t] = s;
        }
        if (t == DIM) {
            float s = 0.f;
            for (int j = 0; j < DIM; j++) s += b2[j];
            g_b2s = s;
        }
    }

    // threefry + bucket scatter, 2-way interleaved for ILP
    for (int e = gtid*2; e < E; e += nth*2) {
        int e1 = e + 1;
        int h0 = DKG[3*e];
        int h1 = (e1 < E) ? DKG[3*e1] : 0;
        u32 a0, b0, a1, b1v;
        threefry(k1x, k1y, 0u, (u32)e,  a0, b0);
        threefry(k1x, k1y, 0u, (u32)e1, a1, b1v);
        u32 bits0 = a0 ^ b0, bits1 = a1 ^ b1v;
        u64 key0 = (((u64)(bits0 >> 9)) << 20) | (u32)e;
        int slot0 = atomicAdd(&g_cursor[h0], 1);
        if (slot0 < CAP) g_bucket[(size_t)h0*CAP + slot0] = key0;
        else {
            int o = atomicAdd(&g_ovfCnt, 1);
            if (o < OVFCAP) g_ovf[o] = ((u64)h0 << 43) | key0;
        }
        if (e1 < E) {
            u64 key1 = (((u64)(bits1 >> 9)) << 20) | (u32)e1;
            int slot1 = atomicAdd(&g_cursor[h1], 1);
            if (slot1 < CAP) g_bucket[(size_t)h1*CAP + slot1] = key1;
            else {
                int o = atomicAdd(&g_ovfCnt, 1);
                if (o < OVFCAP) g_ovf[o] = ((u64)h1 << 43) | key1;
            }
        }
    }
}

// ---------------------------------------------------------------- shared layout
#define SH_BYTES (35*1024)

__global__ void __launch_bounds__(NTHR, 2)
mega_kernel(const int* __restrict__ DKG,
            const float* __restrict__ drug_emb,
            const float* __restrict__ rel_emb,
            const float* __restrict__ tail_emb,
            const float* __restrict__ W1,
            const float* __restrict__ b1,
            const float* __restrict__ Wc,
            const float* __restrict__ bc,
            const float* __restrict__ gamma,
            const float* __restrict__ beta,
            float* __restrict__ out,         // BN output region
            u32 kLx, u32 kLy) {
    __shared__ __align__(16) char sh_raw[SH_BYTES];
    __shared__ u32 s_gen;

    const int tid  = threadIdx.x;
    const int bid  = blockIdx.x;
    const int gtid = bid * NTHR + tid;
    const int nth  = NBLK * NTHR;
    const int lane = tid & 31;
    const int wid  = tid >> 5;

    if (tid == 0) s_gen = *((volatile u32*)&g_bar_gen);

    auto gsync = [&]() {
        __syncthreads();
        if (tid == 0) {
            u32 target = s_gen + 1;
            __threadfence();
            u32 t = atomicAdd(&g_bar_count, 1u);
            if (t == (u32)NBLK - 1) {
                atomicExch(&g_bar_count, 0u);
                __threadfence();
                atomicExch(&g_bar_gen, target);
            } else {
                volatile u32* vg = &g_bar_gen;
                while (*vg < target) { }
            }
            __threadfence();
            s_gen = target;
        }
        __syncthreads();
    };

    // ============ phase B fused: select top16 + score + aggregate (work-stealing) ============
    {
        u64*   w1pk  = (u64*)sh_raw;                  // [ipair*64 + j], 2048 u64
        float* b1s   = (float*)(sh_raw + 16384);
        float* w2ss  = (float*)(sh_raw + 16640);
        int*   ssel  = (int*)(sh_raw + 16896) + wid * 16;

        for (int i = tid; i < 32*64; i += NTHR) {
            int ip = i >> 6, j = i & 63;
            w1pk[i] = pack2(W1[(2*ip)*DIM + j], W1[(2*ip + 1)*DIM + j]);
        }
        if (tid < DIM)        b1s[tid] = b1[tid];
        else if (tid < 2*DIM) w2ss[tid - DIM] = g_w2s[tid - DIM];
        __syncthreads();
        const float b2s = g_b2s;
        const u64 FULLK = ~0ULL;

        for (;;) {
            int d;
            if (lane == 0) d = (int)atomicAdd(&g_work, 1u);
            d = __shfl_sync(0xffffffffu, d, 0);
            if (d >= ND) break;

            const int degd = g_cursor[d];
            const int cnt  = (degd < SS) ? degd : SS;
            const u64* bkt = g_bucket + (size_t)d*CAP;

            if (degd >= SS && degd <= REGCAP) {
                // ================= FAST PATH (cnt == 16) =================
                u64 c0 = (lane       < degd) ? bkt[lane]       : FULLK;
                u64 c1 = (lane + 32  < degd) ? bkt[lane + 32]  : FULLK;
                u64 c2 = (lane + 64  < degd) ? bkt[lane + 64]  : FULLK;
                u64 c3 = (lane + 96  < degd) ? bkt[lane + 96]  : FULLK;
                u64 c4 = (lane + 128 < degd) ? bkt[lane + 128] : FULLK;
                u64 lmin = umin64(umin64(umin64(c0, c1), umin64(c2, c3)), c4);
                int tail = 0, rel = 0;
                #pragma unroll
                for (int r = 0; r < SS; r++) {
                    u32 hi = (u32)(lmin >> 11);
                    u32 mhi = __reduce_min_sync(0xffffffffu, hi);
                    u32 bal = __ballot_sync(0xffffffffu, hi == mhi);
                    u64 m;
                    if (__popc(bal) == 1) {
                        m = __shfl_sync(0xffffffffu, lmin, __ffs(bal) - 1);
                    } else {
                        m = lmin;
                        #pragma unroll
                        for (int o = 16; o; o >>= 1)
                            m = umin64(m, __shfl_xor_sync(0xffffffffu, m, o));
                    }
                    int er = (int)(m & 0xFFFFFu);
                    if (lane == r) {
                        tail = DKG[3*er + 1];
                        rel  = DKG[3*er + 2];
                    }
                    if (lmin == m) {
                        if      (c0 == m) c0 = FULLK;
                        else if (c1 == m) c1 = FULLK;
                        else if (c2 == m) c2 = FULLK;
                        else if (c3 == m) c3 = FULLK;
                        else              c4 = FULLK;
                        lmin = umin64(umin64(umin64(c0, c1), umin64(c2, c3)), c4);
                    }
                }

                const float2 de2 = ((const float2*)(drug_emb + d*DIM))[lane];
                const u64 bin0 = pack2(b1s[lane], 0.f);
                const u64 bin1 = pack2(b1s[lane + 32], 0.f);
                const float w20 = w2ss[lane], w21 = w2ss[lane + 32];

                float myscore = 0.f;
                #pragma unroll
                for (int k = 0; k < SS; k += 4) {
                    int rA = __shfl_sync(0xffffffffu, rel, k);
                    int rB = __shfl_sync(0xffffffffu, rel, k + 1);
                    int rC = __shfl_sync(0xffffffffu, rel, k + 2);
                    int rD = __shfl_sync(0xffffffffu, rel, k + 3);
                    float2 reA = ((const float2*)(rel_emb + rA*DIM))[lane];
                    float2 reB = ((const float2*)(rel_emb + rB*DIM))[lane];
                    float2 reC = ((const float2*)(rel_emb + rC*DIM))[lane];
                    float2 reD = ((const float2*)(rel_emb + rD*DIM))[lane];
                    u64 hA = pack2(de2.x*reA.x, de2.y*reA.y);
                    u64 hB = pack2(de2.x*reB.x, de2.y*reB.y);
                    u64 hC = pack2(de2.x*reC.x, de2.y*reC.y);
                    u64 hD = pack2(de2.x*reD.x, de2.y*reD.y);
                    u64 aA0 = bin0, aA1 = bin1, aB0 = bin0, aB1 = bin1;
                    u64 aC0 = bin0, aC1 = bin1, aD0 = bin0, aD1 = bin1;
                    #pragma unroll
                    for (int ip = 0; ip < 32; ip++) {
                        u64 w0  = w1pk[ip*64 + lane];
                        u64 w1v = w1pk[ip*64 + 32 + lane];
                        u64 hb;
                        hb = __shfl_sync(0xffffffffu, hA, ip);
                        fma2(aA0, hb, w0); fma2(aA1, hb, w1v);
                        hb = __shfl_sync(0xffffffffu, hB, ip);
                        fma2(aB0, hb, w0); fma2(aB1, hb, w1v);
                        hb = __shfl_sync(0xffffffffu, hC, ip);
                        fma2(aC0, hb, w0); fma2(aC1, hb, w1v);
                        hb = __shfl_sync(0xffffffffu, hD, ip);
                        fma2(aD0, hb, w0); fma2(aD1, hb, w1v);
                    }
                    float e0, o0, e1, o1;
                    unpack2(aA0, e0, o0); unpack2(aA1, e1, o1);
                    float pA = (1.f/(1.f+__expf(-(e0+o0))))*w20
                             + (1.f/(1.f+__expf(-(e1+o1))))*w21;
                    unpack2(aB0, e0, o0); unpack2(aB1, e1, o1);
                    float pB = (1.f/(1.f+__expf(-(e0+o0))))*w20
                             + (1.f/(1.f+__expf(-(e1+o1))))*w21;
                    unpack2(aC0, e0, o0); unpack2(aC1, e1, o1);
                    float pC = (1.f/(1.f+__expf(-(e0+o0))))*w20
                             + (1.f/(1.f+__expf(-(e1+o1))))*w21;
                    unpack2(aD0, e0, o0); unpack2(aD1, e1, o1);
                    float pD = (1.f/(1.f+__expf(-(e0+o0))))*w20
                             + (1.f/(1.f+__expf(-(e1+o1))))*w21;
                    #pragma unroll
                    for (int o = 16; o; o >>= 1) {
                        pA += __shfl_xor_sync(0xffffffffu, pA, o);
                        pB += __shfl_xor_sync(0xffffffffu, pB, o);
                        pC += __shfl_xor_sync(0xffffffffu, pC, o);
                        pD += __shfl_xor_sync(0xffffffffu, pD, o);
                    }
                    if (lane == k)     myscore = pA + b2s;
                    if (lane == k + 1) myscore = pB + b2s;
                    if (lane == k + 2) myscore = pC + b2s;
                    if (lane == k + 3) myscore = pD + b2s;
                }

                float acc0 = 0.f, acc1 = 0.f;
                #pragma unroll
                for (int k = 0; k < SS; k++) {
                    float sc = __shfl_sync(0xffffffffu, myscore, k);
                    int   t  = __shfl_sync(0xffffffffu, tail, k);
                    acc0 = fmaf(sc, tail_emb[t*DIM + lane], acc0);
                    acc1 = fmaf(sc, tail_emb[t*DIM + 32 + lane], acc1);
                }
                g_neigh[d*DIM + lane]      = acc0;
                g_neigh[d*DIM + 32 + lane] = acc1;

            } else if (cnt > 0) {
                // ================= SLOW PATH =================
                int myedge = 0;
                if (degd <= REGCAP) {
                    u64 c0 = (lane       < degd) ? bkt[lane]       : FULLK;
                    u64 c1 = (lane + 32  < degd) ? bkt[lane + 32]  : FULLK;
                    u64 c2 = (lane + 64  < degd) ? bkt[lane + 64]  : FULLK;
                    u64 c3 = (lane + 96  < degd) ? bkt[lane + 96]  : FULLK;
                    u64 c4 = (lane + 128 < degd) ? bkt[lane + 128] : FULLK;
                    u64 lmin = umin64(umin64(umin64(c0, c1), umin64(c2, c3)), c4);
                    for (int r = 0; r < cnt; r++) {
                        u64 m = lmin;
                        #pragma unroll
                        for (int o = 16; o; o >>= 1) {
                            u64 t = __shfl_xor_sync(0xffffffffu, m, o);
                            m = umin64(m, t);
                        }
                        if (lane == r) myedge = (int)(m & 0xFFFFFu);
                        if (lmin == m) {
                            if      (c0 == m) c0 = FULLK;
                            else if (c1 == m) c1 = FULLK;
                            else if (c2 == m) c2 = FULLK;
                            else if (c3 == m) c3 = FULLK;
                            else              c4 = FULLK;
                            lmin = umin64(umin64(umin64(c0, c1), umin64(c2, c3)), c4);
                        }
                    }
                } else {
                    int nb = (degd < CAP) ? degd : CAP;
                    int novf = g_ovfCnt; if (novf > OVFCAP) novf = OVFCAP;
                    for (int t = lane; t < nb; t += 32) {
                        u64 k = bkt[t];
                        int rank = 0;
                        for (int j = 0; j < nb; j++) rank += (bkt[j] < k);
                        for (int o = 0; o < novf; o++) {
                            u64 v = g_ovf[o];
                            if ((int)(v >> 43) == d) rank += ((v & 0x7FFFFFFFFFFULL) < k);
                        }
                        if (rank < SS) ssel[rank] = (int)(k & 0xFFFFFu);
                    }
                    for (int t = lane; t < novf; t += 32) {
                        u64 v = g_ovf[t];
                        if ((int)(v >> 43) == d) {
                            u64 k = v & 0x7FFFFFFFFFFULL;
                            int rank = 0;
                            for (int j = 0; j < nb; j++) rank += (bkt[j] < k);
                            for (int o = 0; o < novf; o++) {
                                u64 w = g_ovf[o];
                                if ((int)(w >> 43) == d) rank += ((w & 0x7FFFFFFFFFFULL) < k);
                            }
                            if (rank < SS) ssel[rank] = (int)(k & 0xFFFFFu);
                        }
                    }
                    __syncwarp();
                    if (lane < cnt) myedge = ssel[lane];
                }

                int tail = 0, rel = 0;
                if (lane < cnt) {
                    tail = DKG[3*myedge + 1];
                    rel  = DKG[3*myedge + 2];
                }
                __syncwarp();

                const float2 de2 = ((const float2*)(drug_emb + d*DIM))[lane];
                const u64 bin0 = pack2(b1s[lane], 0.f);
                const u64 bin1 = pack2(b1s[lane + 32], 0.f);
                const float w20 = w2ss[lane], w21 = w2ss[lane + 32];

                float myscore = 0.f;
                for (int k = 0; k < cnt; k++) {
                    int rA = __shfl_sync(0xffffffffu, rel, k);
                    float2 reA = ((const float2*)(rel_emb + rA*DIM))[lane];
                    u64 hA = pack2(de2.x*reA.x, de2.y*reA.y);
                    u64 aA0 = bin0, aA1 = bin1;
                    #pragma unroll
                    for (int ip = 0; ip < 32; ip++) {
                        u64 w0  = w1pk[ip*64 + lane];
                        u64 w1v = w1pk[ip*64 + 32 + lane];
                        u64 hb = __shfl_sync(0xffffffffu, hA, ip);
                        fma2(aA0, hb, w0); fma2(aA1, hb, w1v);
                    }
                    float e0, o0, e1, o1;
                    unpack2(aA0, e0, o0); unpack2(aA1, e1, o1);
                    float pA = (1.f/(1.f+__expf(-(e0+o0))))*w20
                             + (1.f/(1.f+__expf(-(e1+o1))))*w21;
                    #pragma unroll
                    for (int o = 16; o; o >>= 1) pA += __shfl_xor_sync(0xffffffffu, pA, o);
                    if (lane == k) myscore = pA + b2s;
                }

                float acc0 = 0.f, acc1 = 0.f;
                for (int k = 0; k < cnt; k++) {
                    float sc = __shfl_sync(0xffffffffu, myscore, k);
                    int   t  = __shfl_sync(0xffffffffu, tail, k);
                    acc0 = fmaf(sc, tail_emb[t*DIM + lane], acc0);
                    acc1 = fmaf(sc, tail_emb[t*DIM + 32 + lane], acc1);
                }
                if (degd < SS) {
                    for (int s = 0; s < SS - degd; s++) {
                        u32 bits = rbits_stream(kLx, kLy, d*SS + s);
                        int idx = (int)((bits % 2147483647u) % (u32)degd);
                        float sc = __shfl_sync(0xffffffffu, myscore, idx);
                        int   t  = __shfl_sync(0xffffffffu, tail, idx);
                        acc0 = fmaf(sc, tail_emb[t*DIM + lane], acc0);
                        acc1 = fmaf(sc, tail_emb[t*DIM + 32 + lane], acc1);
                    }
                }
                g_neigh[d*DIM + lane]      = acc0;
                g_neigh[d*DIM + 32 + lane] = acc1;
            } else {
                g_neigh[d*DIM + lane]      = 0.f;
                g_neigh[d*DIM + 32 + lane] = 0.f;
            }
        }
    }
    gsync();

    // ============ phase C: y = [drug_emb, neigh] @ Wc + bc ============
    {
        if (gtid == 0) { g_work = 0; g_ovfCnt = 0; }   // replay-state reset
        u64*   wcp = (u64*)sh_raw;                   // 32KB
        float* red = (float*)(sh_raw + 32768);
        for (int i = tid; i < 2*DIM*32; i += NTHR) {
            int r = i >> 5, c = i & 31;
            wcp[i] = pack2(Wc[r*DIM + c], Wc[r*DIM + c + 32]);
        }
        __syncthreads();
        const int sub = tid >> 5;
        const int o = lane;
        const u64 bcv = pack2(bc[o], bc[o + 32]);
        float S0 = 0.f, S1 = 0.f, Q0 = 0.f, Q1 = 0.f;
        const int NR32 = (ND + 31) / 32;
        for (int r32 = bid; r32 < NR32; r32 += NBLK) {
            int row0 = r32*32 + sub;
            int row1 = row0 + 16;
            bool has1 = (row1 < ND);
            int row1c = has1 ? row1 : row0;
            float2 deA = ((const float2*)(drug_emb + row0*DIM))[lane];
            float2 neA = ((const float2*)(g_neigh + row0*DIM))[lane];
            float2 deB = ((const float2*)(drug_emb + row1c*DIM))[lane];
            float2 neB = ((const float2*)(g_neigh + row1c*DIM))[lane];
            u64 accR0 = bcv, accR1 = bcv;
            #pragma unroll
            for (int i = 0; i < DIM; i++) {
                u64 w = wcp[i*32 + o];
                float v0 = __shfl_sync(0xffffffffu, (i & 1) ? deA.y : deA.x, i >> 1);
                float v1 = __shfl_sync(0xffffffffu, (i & 1) ? deB.y : deB.x, i >> 1);
                fma2(accR0, pack2(v0, v0), w);
                fma2(accR1, pack2(v1, v1), w);
            }
            #pragma unroll
            for (int i = 0; i < DIM; i++) {
                u64 w = wcp[(DIM + i)*32 + o];
                float v0 = __shfl_sync(0xffffffffu, (i & 1) ? neA.y : neA.x, i >> 1);
                float v1 = __shfl_sync(0xffffffffu, (i & 1) ? neB.y : neB.x, i >> 1);
                fma2(accR0, pack2(v0, v0), w);
                fma2(accR1, pack2(v1, v1), w);
            }
            float y00, y01, y10, y11;
            unpack2(accR0, y00, y01);
            unpack2(accR1, y10, y11);
            g_y[row0*DIM + o]      = y00;
            g_y[row0*DIM + 32 + o] = y01;
            S0 += y00; S1 += y01; Q0 += y00*y00; Q1 += y01*y01;
            if (has1) {
                g_y[row1*DIM + o]      = y10;
                g_y[row1*DIM + 32 + o] = y11;
                S0 += y10; S1 += y11; Q0 += y10*y10; Q1 += y11*y11;
            }
        }
        red[tid] = S0;
        __syncthreads();
        if (tid < 32) { float s = 0.f;
            #pragma unroll
            for (int p = 0; p < 16; p++) s += red[p*32 + lane];
            g_psum[bid*DIM + lane] = s; }
        __syncthreads();
        red[tid] = S1;
        __syncthreads();
        if (tid < 32) { float s = 0.f;
            #pragma unroll
            for (int p = 0; p < 16; p++) s += red[p*32 + lane];
            g_psum[bid*DIM + 32 + lane] = s; }
        __syncthreads();
        red[tid] = Q0;
        __syncthreads();
        if (tid < 32) { float s = 0.f;
            #pragma unroll
            for (int p = 0; p < 16; p++) s += red[p*32 + lane];
            g_psq[bid*DIM + lane] = s; }
        __syncthreads();
        red[tid] = Q1;
        __syncthreads();
        if (tid < 32) { float s = 0.f;
            #pragma unroll
            for (int p = 0; p < 16; p++) s += red[p*32 + lane];
            g_psq[bid*DIM + 32 + lane] = s; }
    }
    gsync();

    // ============ phase D: distributed BN stats + normalize + write + reset ============
    {
        float* rs = (float*)sh_raw;
        float* rq = (float*)(sh_raw + 2048);
        float* A  = (float*)(sh_raw + 4096);
        float* B  = (float*)(sh_raw + 4352);
        const int col = tid & 63, part = tid >> 6;
        float s = 0.f, q = 0.f;
        for (int b = part; b < NBLK; b += 8) {
            s += g_psum[b*DIM + col];
            q += g_psq[b*DIM + col];
        }
        rs[tid] = s; rq[tid] = q;
        __syncthreads();
        if (tid < 64) {
            float S = 0.f, Q = 0.f;
            #pragma unroll
            for (int p = 0; p < 8; p++) { S += rs[p*64 + col]; Q += rq[p*64 + col]; }
            float mean = S / (float)ND;
            float var  = Q / (float)ND - mean * mean;
            float rstd = rsqrtf(var + 1e-5f);
            float gm = gamma[col];
            A[col] = gm * rstd;
            B[col] = beta[col] - gm * mean * rstd;
        }
        __syncthreads();

        const float4* y4 = (const float4*)g_y;
        float4* o4 = (float4*)out;
        for (int t = gtid; t < ND*DIM/4; t += nth) {
            int c = (t*4) & 63;
            float4 v = y4[t];
            float4 r;
            r.x = fmaf(v.x, A[c+0], B[c+0]);
            r.y = fmaf(v.y, A[c+1], B[c+1]);
            r.z = fmaf(v.z, A[c+2], B[c+2]);
            r.w = fmaf(v.w, A[c+3], B[c+3]);
            o4[t] = r;
        }

        // replay-state reset: g_cursor must be zero for next replay's scatter
        for (int i = gtid; i < ND; i += nth) g_cursor[i] = 0;
    }
}

// ---------------------------------------------------------------- host
static void compute_keys(u32& k1x, u32& k1y, u32& kLx, u32& kLy) {
    u32 a, b, c, d, e, f;
    threefry(0u, 42u, 0u, 0u, a, b);   // k1 = split(key(42))[0]
    k1x = a; k1y = b;
    threefry(0u, 42u, 0u, 1u, c, d);   // k2 = split(key(42))[1]
    threefry(c, d, 0u, 1u, e, f);      // split(k2)[1]
    kLx = e; kLy = f;
}

extern "C" void kernel_launch(void* const* d_in, const int* in_sizes, int n_in,
                              void* d_out, int out_size) {
    const float* HF       = (const float*)d_in[0];
    const float* X        = (const float*)d_in[1];
    const float* drug_emb = (const float*)d_in[2];
    const float* rel_emb  = (const float*)d_in[3];
    const float* tail_emb = (const float*)d_in[4];
    const float* W1       = (const float*)d_in[5];
    const float* b1       = (const float*)d_in[6];
    const float* W2       = (const float*)d_in[7];
    const float* b2       = (const float*)d_in[8];
    const float* Wc       = (const float*)d_in[9];
    const float* bc       = (const float*)d_in[10];
    const float* gamma    = (const float*)d_in[11];
    const float* beta     = (const float*)d_in[12];
    const int*   DKG      = (const int*)d_in[13];
    int E    = in_sizes[13] / 3;
    int hf_n = in_sizes[0];
    int x_n  = in_sizes[1];
    float* out = (float*)d_out;

    u32 k1x, k1y, kLx, kLy;
    compute_keys(k1x, k1y, kLx, kLy);

    scatter_kernel<<<ABLK, ATHR>>>(DKG, HF, X, W2, b2, out, E, hf_n, x_n, k1x, k1y);
    mega_kernel<<<NBLK, NTHR>>>(DKG, drug_emb, rel_emb, tail_emb, W1, b1,
                                Wc, bc, gamma, beta, out + hf_n, kLx, kLy);
}

// round 10
// speedup vs baseline: 2.1057x; 1.0291x over previous
#include <cuda_runtime.h>
#include <stdint.h>

#define ND    10000
#define DIM   64
#define SS    16
#define EMAX  1000000
#define NBLK  296
#define NTHR  512
#define NWPB  16
#define NWARP (NBLK*NWPB)
#define CAP   192                // per-drug bucket capacity (deg ~ Poisson(100))
#define REGCAP 160               // fast-path selection capacity (5 keys/lane)
#define OVFCAP 8192
#define ABLK  1184               // scatter kernel blocks
#define ATHR  256

typedef unsigned int u32;
typedef unsigned long long u64;

// ---------------------------------------------------------------- threefry2x32
__host__ __device__ __forceinline__ void threefry(u32 k0, u32 k1, u32 x0, u32 x1,
                                                  u32& o0, u32& o1) {
#ifdef __CUDA_ARCH__
#define TFR(a,b,r) { a += b; b = __funnelshift_l(b, b, r); b ^= a; }
#else
#define TFR(a,b,r) { a += b; b = (b<<r)|(b>>(32-r)); b ^= a; }
#endif
    u32 ks2 = k0 ^ k1 ^ 0x1BD11BDAu;
    x0 += k0; x1 += k1;
    TFR(x0,x1,13); TFR(x0,x1,15); TFR(x0,x1,26); TFR(x0,x1,6);
    x0 += k1; x1 += ks2 + 1u;
    TFR(x0,x1,17); TFR(x0,x1,29); TFR(x0,x1,16); TFR(x0,x1,24);
    x0 += ks2; x1 += k0 + 2u;
    TFR(x0,x1,13); TFR(x0,x1,15); TFR(x0,x1,26); TFR(x0,x1,6);
    x0 += k0; x1 += k1 + 3u;
    TFR(x0,x1,17); TFR(x0,x1,29); TFR(x0,x1,16); TFR(x0,x1,24);
    x0 += k1; x1 += ks2 + 4u;
    TFR(x0,x1,13); TFR(x0,x1,15); TFR(x0,x1,26); TFR(x0,x1,6);
    x0 += ks2; x1 += k0 + 5u;
    o0 = x0; o1 = x1;
#undef TFR
}
__device__ __forceinline__ u32 rbits_stream(u32 kx, u32 ky, int i) {
    u32 a, b; threefry(kx, ky, 0u, (u32)i, a, b);
    return a ^ b;
}

// ---------------------------------------------------------------- scratch
__device__ int   g_cursor[ND];               // zero at launch; re-zeroed in phase D
__device__ u64   g_bucket[(size_t)ND*CAP];   // rank(23)|edge(20)
__device__ int   g_ovfCnt;
__device__ u64   g_ovf[OVFCAP];
__device__ float g_neigh[ND*DIM];
__device__ float g_y[ND*DIM];
__device__ float g_psum[NBLK*DIM];
__device__ float g_psq[NBLK*DIM];
__device__ float g_w2s[DIM];
__device__ float g_b2s;
__device__ u32   g_bar_count;
__device__ u32   g_bar_gen;                  // monotonic across replays
__device__ u32   g_work;

// ---------------------------------------------------------------- f32x2 helpers
__device__ __forceinline__ u64 pack2(float lo, float hi) {
    u64 r;
    asm("mov.b64 %0, {%1, %2};" : "=l"(r) : "f"(lo), "f"(hi));
    return r;
}
__device__ __forceinline__ void unpack2(u64 v, float& lo, float& hi) {
    asm("mov.b64 {%0, %1}, %2;" : "=f"(lo), "=f"(hi) : "l"(v));
}
__device__ __forceinline__ void fma2(u64& acc, u64 a, u64 b) {
    asm("fma.rn.f32x2 %0, %1, %2, %0;" : "+l"(acc) : "l"(a), "l"(b));
}
__device__ __forceinline__ u64 umin64(u64 a, u64 b) { return a < b ? a : b; }

// ================================================================ scatter kernel
__global__ void scatter_kernel(const int* __restrict__ DKG,
                               const float* __restrict__ HF,
                               const float* __restrict__ X,
                               const float* __restrict__ W2,
                               const float* __restrict__ b2,
                               float* __restrict__ outBase,
                               int E, int hf_n, int x_n,
                               u32 k1x, u32 k1y) {
    const int gtid = blockIdx.x * ATHR + threadIdx.x;
    const int nth  = ABLK * ATHR;

    {
        const float4* hf4 = (const float4*)HF;
        float4* o4 = (float4*)outBase;
        for (int t = gtid; t < hf_n/4; t += nth) o4[t] = hf4[t];
        const float4* x4 = (const float4*)X;
        float4* ox4 = (float4*)(outBase + hf_n + ND*DIM);
        for (int t = gtid; t < x_n/4; t += nth) ox4[t] = x4[t];
    }
    if (blockIdx.x == ABLK - 1) {
        int t = threadIdx.x;
        if (t < DIM) {
            float s = 0.f;
            for (int j = 0; j < DIM; j++) s += W2[t*DIM + j];
            g_w2s[t] = s;
        }
        if (t == DIM) {
            float s = 0.f;
            for (int j = 0; j < DIM; j++) s += b2[j];
            g_b2s = s;
        }
    }

    // atomics issued BEFORE threefry so their latency overlaps the hash
    for (int e = gtid*2; e < E; e += nth*2) {
        int e1 = e + 1;
        bool has1 = (e1 < E);
        int h0 = DKG[3*e];
        int h1 = has1 ? DKG[3*e1] : 0;
        int slot0 = atomicAdd(&g_cursor[h0], 1);
        int slot1 = has1 ? atomicAdd(&g_cursor[h1], 1) : 0;
        u32 a0, b0, a1, b1v;
        threefry(k1x, k1y, 0u, (u32)e,  a0, b0);
        threefry(k1x, k1y, 0u, (u32)e1, a1, b1v);
        u32 bits0 = a0 ^ b0, bits1 = a1 ^ b1v;
        u64 key0 = (((u64)(bits0 >> 9)) << 20) | (u32)e;
        if (slot0 < CAP) g_bucket[(size_t)h0*CAP + slot0] = key0;
        else {
            int o = atomicAdd(&g_ovfCnt, 1);
            if (o < OVFCAP) g_ovf[o] = ((u64)h0 << 43) | key0;
        }
        if (has1) {
            u64 key1 = (((u64)(bits1 >> 9)) << 20) | (u32)e1;
            if (slot1 < CAP) g_bucket[(size_t)h1*CAP + slot1] = key1;
            else {
                int o = atomicAdd(&g_ovfCnt, 1);
                if (o < OVFCAP) g_ovf[o] = ((u64)h1 << 43) | key1;
            }
        }
    }
}

// ---------------------------------------------------------------- shared layout
// phase B: [0,16384) w1pk2 ulonglong2[1024] | [16384) b1s | [16640) w2ss | [16896,17920) ssel
// phase C: [0,32768) wcp2 ulonglong2[2048] | [32768,34816) red
#define SH_BYTES (35*1024)

__global__ void __launch_bounds__(NTHR, 2)
mega_kernel(const int* __restrict__ DKG,
            const float* __restrict__ drug_emb,
            const float* __restrict__ rel_emb,
            const float* __restrict__ tail_emb,
            const float* __restrict__ W1,
            const float* __restrict__ b1,
            const float* __restrict__ Wc,
            const float* __restrict__ bc,
            const float* __restrict__ gamma,
            const float* __restrict__ beta,
            float* __restrict__ out,
            u32 kLx, u32 kLy) {
    __shared__ __align__(16) char sh_raw[SH_BYTES];
    __shared__ u32 s_gen;

    const int tid  = threadIdx.x;
    const int bid  = blockIdx.x;
    const int gtid = bid * NTHR + tid;
    const int nth  = NBLK * NTHR;
    const int lane = tid & 31;
    const int wid  = tid >> 5;

    if (tid == 0) s_gen = *((volatile u32*)&g_bar_gen);

    auto gsync = [&]() {
        __syncthreads();
        if (tid == 0) {
            u32 target = s_gen + 1;
            __threadfence();
            u32 t = atomicAdd(&g_bar_count, 1u);
            if (t == (u32)NBLK - 1) {
                atomicExch(&g_bar_count, 0u);
                __threadfence();
                atomicExch(&g_bar_gen, target);
            } else {
                volatile u32* vg = &g_bar_gen;
                while (*vg < target) { }
            }
            __threadfence();
            s_gen = target;
        }
        __syncthreads();
    };

    // ============ phase B fused: select top16 + score + aggregate ============
    {
        ulonglong2* w1pk2 = (ulonglong2*)sh_raw;      // [ip*32+lane] = (w_even|odd @ j, @ j+32)
        float* b1s   = (float*)(sh_raw + 16384);
        float* w2ss  = (float*)(sh_raw + 16640);
        int*   ssel  = (int*)(sh_raw + 16896) + wid * 16;

        for (int i = tid; i < 32*32; i += NTHR) {
            int ip = i >> 5, ln = i & 31;
            ulonglong2 v;
            v.x = pack2(W1[(2*ip)*DIM + ln],      W1[(2*ip + 1)*DIM + ln]);
            v.y = pack2(W1[(2*ip)*DIM + 32 + ln], W1[(2*ip + 1)*DIM + 32 + ln]);
            w1pk2[i] = v;
        }
        if (tid < DIM)        b1s[tid] = b1[tid];
        else if (tid < 2*DIM) w2ss[tid - DIM] = g_w2s[tid - DIM];
        __syncthreads();
        const float b2s = g_b2s;
        const u64 FULLK = ~0ULL;

        for (;;) {
            int d;
            if (lane == 0) d = (int)atomicAdd(&g_work, 1u);
            d = __shfl_sync(0xffffffffu, d, 0);
            if (d >= ND) break;

            const int degd = g_cursor[d];
            const int cnt  = (degd < SS) ? degd : SS;
            const u64* bkt = g_bucket + (size_t)d*CAP;

            if (degd >= SS && degd <= REGCAP) {
                // ================= FAST PATH (cnt == 16) =================
                u64 c0 = (lane       < degd) ? bkt[lane]       : FULLK;
                u64 c1 = (lane + 32  < degd) ? bkt[lane + 32]  : FULLK;
                u64 c2 = (lane + 64  < degd) ? bkt[lane + 64]  : FULLK;
                u64 c3 = (lane + 96  < degd) ? bkt[lane + 96]  : FULLK;
                u64 c4 = (lane + 128 < degd) ? bkt[lane + 128] : FULLK;
                u64 lmin = umin64(umin64(umin64(c0, c1), umin64(c2, c3)), c4);
                int tail = 0, rel = 0;
                #pragma unroll
                for (int r = 0; r < SS; r++) {
                    u32 hi = (u32)(lmin >> 11);
                    u32 mhi = __reduce_min_sync(0xffffffffu, hi);
                    u32 bal = __ballot_sync(0xffffffffu, hi == mhi);
                    u64 m;
                    if (__popc(bal) == 1) {
                        m = __shfl_sync(0xffffffffu, lmin, __ffs(bal) - 1);
                    } else {
                        m = lmin;
                        #pragma unroll
                        for (int o = 16; o; o >>= 1)
                            m = umin64(m, __shfl_xor_sync(0xffffffffu, m, o));
                    }
                    int er = (int)(m & 0xFFFFFu);
                    if (lane == r) {
                        tail = DKG[3*er + 1];
                        rel  = DKG[3*er + 2];
                    }
                    if (lmin == m) {
                        if      (c0 == m) c0 = FULLK;
                        else if (c1 == m) c1 = FULLK;
                        else if (c2 == m) c2 = FULLK;
                        else if (c3 == m) c3 = FULLK;
                        else              c4 = FULLK;
                        lmin = umin64(umin64(umin64(c0, c1), umin64(c2, c3)), c4);
                    }
                }

                const float2 de2 = ((const float2*)(drug_emb + d*DIM))[lane];
                const u64 bin0 = pack2(b1s[lane], 0.f);
                const u64 bin1 = pack2(b1s[lane + 32], 0.f);
                const float w20 = w2ss[lane], w21 = w2ss[lane + 32];

                float myscore = 0.f;
                #pragma unroll
                for (int kb = 0; kb < 2; kb++) {
                    const int kbase = kb * 8;
                    u64 h[8];
                    #pragma unroll
                    for (int u = 0; u < 8; u++) {
                        int rr = __shfl_sync(0xffffffffu, rel, kbase + u);
                        float2 re = ((const float2*)(rel_emb + rr*DIM))[lane];
                        h[u] = pack2(de2.x*re.x, de2.y*re.y);
                    }
                    u64 a0[8], a1[8];
                    #pragma unroll
                    for (int u = 0; u < 8; u++) { a0[u] = bin0; a1[u] = bin1; }
                    #pragma unroll
                    for (int ip = 0; ip < 32; ip++) {
                        ulonglong2 wv = w1pk2[ip*32 + lane];   // LDS.128
                        #pragma unroll
                        for (int u = 0; u < 8; u++) {
                            u64 hb = __shfl_sync(0xffffffffu, h[u], ip);
                            fma2(a0[u], hb, wv.x);
                            fma2(a1[u], hb, wv.y);
                        }
                    }
                    #pragma unroll
                    for (int u = 0; u < 8; u++) {
                        float e0, o0, e1, o1;
                        unpack2(a0[u], e0, o0);
                        unpack2(a1[u], e1, o1);
                        float p = (1.f/(1.f+__expf(-(e0+o0))))*w20
                                + (1.f/(1.f+__expf(-(e1+o1))))*w21;
                        #pragma unroll
                        for (int o = 16; o; o >>= 1)
                            p += __shfl_xor_sync(0xffffffffu, p, o);
                        if (lane == kbase + u) myscore = p + b2s;
                    }
                }

                float acc0 = 0.f, acc1 = 0.f;
                #pragma unroll
                for (int k = 0; k < SS; k++) {
                    float sc = __shfl_sync(0xffffffffu, myscore, k);
                    int   t  = __shfl_sync(0xffffffffu, tail, k);
                    acc0 = fmaf(sc, tail_emb[t*DIM + lane], acc0);
                    acc1 = fmaf(sc, tail_emb[t*DIM + 32 + lane], acc1);
                }
                g_neigh[d*DIM + lane]      = acc0;
                g_neigh[d*DIM + 32 + lane] = acc1;

            } else if (cnt > 0) {
                // ================= SLOW PATH =================
                int myedge = 0;
                if (degd <= REGCAP) {
                    u64 c0 = (lane       < degd) ? bkt[lane]       : FULLK;
                    u64 c1 = (lane + 32  < degd) ? bkt[lane + 32]  : FULLK;
                    u64 c2 = (lane + 64  < degd) ? bkt[lane + 64]  : FULLK;
                    u64 c3 = (lane + 96  < degd) ? bkt[lane + 96]  : FULLK;
                    u64 c4 = (lane + 128 < degd) ? bkt[lane + 128] : FULLK;
                    u64 lmin = umin64(umin64(umin64(c0, c1), umin64(c2, c3)), c4);
                    for (int r = 0; r < cnt; r++) {
                        u64 m = lmin;
                        #pragma unroll
                        for (int o = 16; o; o >>= 1) {
                            u64 t = __shfl_xor_sync(0xffffffffu, m, o);
                            m = umin64(m, t);
                        }
                        if (lane == r) myedge = (int)(m & 0xFFFFFu);
                        if (lmin == m) {
                            if      (c0 == m) c0 = FULLK;
                            else if (c1 == m) c1 = FULLK;
                            else if (c2 == m) c2 = FULLK;
                            else if (c3 == m) c3 = FULLK;
                            else              c4 = FULLK;
                            lmin = umin64(umin64(umin64(c0, c1), umin64(c2, c3)), c4);
                        }
                    }
                } else {
                    int nb = (degd < CAP) ? degd : CAP;
                    int novf = g_ovfCnt; if (novf > OVFCAP) novf = OVFCAP;
                    for (int t = lane; t < nb; t += 32) {
                        u64 k = bkt[t];
                        int rank = 0;
                        for (int j = 0; j < nb; j++) rank += (bkt[j] < k);
                        for (int o = 0; o < novf; o++) {
                            u64 v = g_ovf[o];
                            if ((int)(v >> 43) == d) rank += ((v & 0x7FFFFFFFFFFULL) < k);
                        }
                        if (rank < SS) ssel[rank] = (int)(k & 0xFFFFFu);
                    }
                    for (int t = lane; t < novf; t += 32) {
                        u64 v = g_ovf[t];
                        if ((int)(v >> 43) == d) {
                            u64 k = v & 0x7FFFFFFFFFFULL;
                            int rank = 0;
                            for (int j = 0; j < nb; j++) rank += (bkt[j] < k);
                            for (int o = 0; o < novf; o++) {
                                u64 w = g_ovf[o];
                                if ((int)(w >> 43) == d) rank += ((w & 0x7FFFFFFFFFFULL) < k);
                            }
                            if (rank < SS) ssel[rank] = (int)(k & 0xFFFFFu);
                        }
                    }
                    __syncwarp();
                    if (lane < cnt) myedge = ssel[lane];
                }

                int tail = 0, rel = 0;
                if (lane < cnt) {
                    tail = DKG[3*myedge + 1];
                    rel  = DKG[3*myedge + 2];
                }
                __syncwarp();

                const float2 de2 = ((const float2*)(drug_emb + d*DIM))[lane];
                const u64 bin0 = pack2(b1s[lane], 0.f);
                const u64 bin1 = pack2(b1s[lane + 32], 0.f);
                const float w20 = w2ss[lane], w21 = w2ss[lane + 32];

                float myscore = 0.f;
                for (int k = 0; k < cnt; k++) {
                    int rA = __shfl_sync(0xffffffffu, rel, k);
                    float2 reA = ((const float2*)(rel_emb + rA*DIM))[lane];
                    u64 hA = pack2(de2.x*reA.x, de2.y*reA.y);
                    u64 aA0 = bin0, aA1 = bin1;
                    #pragma unroll
                    for (int ip = 0; ip < 32; ip++) {
                        ulonglong2 wv = w1pk2[ip*32 + lane];
                        u64 hb = __shfl_sync(0xffffffffu, hA, ip);
                        fma2(aA0, hb, wv.x); fma2(aA1, hb, wv.y);
                    }
                    float e0, o0, e1, o1;
                    unpack2(aA0, e0, o0); unpack2(aA1, e1, o1);
                    float pA = (1.f/(1.f+__expf(-(e0+o0))))*w20
                             + (1.f/(1.f+__expf(-(e1+o1))))*w21;
                    #pragma unroll
                    for (int o = 16; o; o >>= 1) pA += __shfl_xor_sync(0xffffffffu, pA, o);
                    if (lane == k) myscore = pA + b2s;
                }

                float acc0 = 0.f, acc1 = 0.f;
                for (int k = 0; k < cnt; k++) {
                    float sc = __shfl_sync(0xffffffffu, myscore, k);
                    int   t  = __shfl_sync(0xffffffffu, tail, k);
                    acc0 = fmaf(sc, tail_emb[t*DIM + lane], acc0);
                    acc1 = fmaf(sc, tail_emb[t*DIM + 32 + lane], acc1);
                }
                if (degd < SS) {
                    for (int s = 0; s < SS - degd; s++) {
                        u32 bits = rbits_stream(kLx, kLy, d*SS + s);
                        int idx = (int)((bits % 2147483647u) % (u32)degd);
                        float sc = __shfl_sync(0xffffffffu, myscore, idx);
                        int   t  = __shfl_sync(0xffffffffu, tail, idx);
                        acc0 = fmaf(sc, tail_emb[t*DIM + lane], acc0);
                        acc1 = fmaf(sc, tail_emb[t*DIM + 32 + lane], acc1);
                    }
                }
                g_neigh[d*DIM + lane]      = acc0;
                g_neigh[d*DIM + 32 + lane] = acc1;
            } else {
                g_neigh[d*DIM + lane]      = 0.f;
                g_neigh[d*DIM + 32 + lane] = 0.f;
            }
        }
    }
    gsync();

    // ============ phase C: y = [drug_emb, neigh] @ Wc + bc ============
    {
        if (gtid == 0) { g_work = 0; g_ovfCnt = 0; }   // replay-state reset
        ulonglong2* wcp2 = (ulonglong2*)sh_raw;      // [i2*32+o], rows (2i2,2i2+1), 32KB
        float* red = (float*)(sh_raw + 32768);
        for (int i = tid; i < 64*32; i += NTHR) {
            int i2 = i >> 5, o = i & 31;
            ulonglong2 v;
            v.x = pack2(Wc[(2*i2)*DIM + o],     Wc[(2*i2)*DIM + o + 32]);
            v.y = pack2(Wc[(2*i2 + 1)*DIM + o], Wc[(2*i2 + 1)*DIM + o + 32]);
            wcp2[i] = v;
        }
        __syncthreads();
        const int sub = tid >> 5;
        const int o = lane;
        const u64 bcv = pack2(bc[o], bc[o + 32]);
        float S0 = 0.f, S1 = 0.f, Q0 = 0.f, Q1 = 0.f;
        const int NR32 = (ND + 31) / 32;
        for (int r32 = bid; r32 < NR32; r32 += NBLK) {
            int row0 = r32*32 + sub;
            int row1 = row0 + 16;
            bool has1 = (row1 < ND);
            int row1c = has1 ? row1 : row0;
            u64 deA = ((const u64*)(drug_emb + row0*DIM))[lane];
            u64 neA = ((const u64*)(g_neigh + row0*DIM))[lane];
            u64 deB = ((const u64*)(drug_emb + row1c*DIM))[lane];
            u64 neB = ((const u64*)(g_neigh + row1c*DIM))[lane];
            u64 accR0 = bcv, accR1 = bcv;
            #pragma unroll
            for (int i2 = 0; i2 < 32; i2++) {
                ulonglong2 wv = wcp2[i2*32 + o];
                u64 dA = __shfl_sync(0xffffffffu, deA, i2);
                u64 dB = __shfl_sync(0xffffffffu, deB, i2);
                float vA0, vA1, vB0, vB1;
                unpack2(dA, vA0, vA1);
                unpack2(dB, vB0, vB1);
                fma2(accR0, pack2(vA0, vA0), wv.x);
                fma2(accR0, pack2(vA1, vA1), wv.y);
                fma2(accR1, pack2(vB0, vB0), wv.x);
                fma2(accR1, pack2(vB1, vB1), wv.y);
            }
            #pragma unroll
            for (int i2 = 0; i2 < 32; i2++) {
                ulonglong2 wv = wcp2[(32 + i2)*32 + o];
                u64 dA = __shfl_sync(0xffffffffu, neA, i2);
                u64 dB = __shfl_sync(0xffffffffu, neB, i2);
                float vA0, vA1, vB0, vB1;
                unpack2(dA, vA0, vA1);
                unpack2(dB, vB0, vB1);
                fma2(accR0, pack2(vA0, vA0), wv.x);
                fma2(accR0, pack2(vA1, vA1), wv.y);
                fma2(accR1, pack2(vB0, vB0), wv.x);
                fma2(accR1, pack2(vB1, vB1), wv.y);
            }
            float y00, y01, y10, y11;
            unpack2(accR0, y00, y01);
            unpack2(accR1, y10, y11);
            g_y[row0*DIM + o]      = y00;
            g_y[row0*DIM + 32 + o] = y01;
            S0 += y00; S1 += y01; Q0 += y00*y00; Q1 += y01*y01;
            if (has1) {
                g_y[row1*DIM + o]      = y10;
                g_y[row1*DIM + 32 + o] = y11;
                S0 += y10; S1 += y11; Q0 += y10*y10; Q1 += y11*y11;
            }
        }
        red[tid] = S0;
        __syncthreads();
        if (tid < 32) { float s = 0.f;
            #pragma unroll
            for (int p = 0; p < 16; p++) s += red[p*32 + lane];
            g_psum[bid*DIM + lane] = s; }
        __syncthreads();
        red[tid] = S1;
        __syncthreads();
        if (tid < 32) { float s = 0.f;
            #pragma unroll
            for (int p = 0; p < 16; p++) s += red[p*32 + lane];
            g_psum[bid*DIM + 32 + lane] = s; }
        __syncthreads();
        red[tid] = Q0;
        __syncthreads();
        if (tid < 32) { float s = 0.f;
            #pragma unroll
            for (int p = 0; p < 16; p++) s += red[p*32 + lane];
            g_psq[bid*DIM + lane] = s; }
        __syncthreads();
        red[tid] = Q1;
        __syncthreads();
        if (tid < 32) { float s = 0.f;
            #pragma unroll
            for (int p = 0; p < 16; p++) s += red[p*32 + lane];
            g_psq[bid*DIM + 32 + lane] = s; }
    }
    gsync();

    // ============ phase D: distributed BN stats + normalize + write + reset ============
    {
        float* rs = (float*)sh_raw;
        float* rq = (float*)(sh_raw + 2048);
        float* A  = (float*)(sh_raw + 4096);
        float* B  = (float*)(sh_raw + 4352);
        const int col = tid & 63, part = tid >> 6;
        float s = 0.f, q = 0.f;
        for (int b = part; b < NBLK; b += 8) {
            s += g_psum[b*DIM + col];
            q += g_psq[b*DIM + col];
        }
        rs[tid] = s; rq[tid] = q;
        __syncthreads();
        if (tid < 64) {
            float S = 0.f, Q = 0.f;
            #pragma unroll
            for (int p = 0; p < 8; p++) { S += rs[p*64 + col]; Q += rq[p*64 + col]; }
            float mean = S / (float)ND;
            float var  = Q / (float)ND - mean * mean;
            float rstd = rsqrtf(var + 1e-5f);
            float gm = gamma[col];
            A[col] = gm * rstd;
            B[col] = beta[col] - gm * mean * rstd;
        }
        __syncthreads();

        const float4* y4 = (const float4*)g_y;
        float4* o4 = (float4*)out;
        for (int t = gtid; t < ND*DIM/4; t += nth) {
            int c = (t*4) & 63;
            float4 v = y4[t];
            float4 r;
            r.x = fmaf(v.x, A[c+0], B[c+0]);
            r.y = fmaf(v.y, A[c+1], B[c+1]);
            r.z = fmaf(v.z, A[c+2], B[c+2]);
            r.w = fmaf(v.w, A[c+3], B[c+3]);
            o4[t] = r;
        }

        // replay-state reset: g_cursor must be zero for next replay's scatter
        for (int i = gtid; i < ND; i += nth) g_cursor[i] = 0;
    }
}

// ---------------------------------------------------------------- host
static void compute_keys(u32& k1x, u32& k1y, u32& kLx, u32& kLy) {
    u32 a, b, c, d, e, f;
    threefry(0u, 42u, 0u, 0u, a, b);   // k1 = split(key(42))[0]
    k1x = a; k1y = b;
    threefry(0u, 42u, 0u, 1u, c, d);   // k2 = split(key(42))[1]
    threefry(c, d, 0u, 1u, e, f);      // split(k2)[1]
    kLx = e; kLy = f;
}

extern "C" void kernel_launch(void* const* d_in, const int* in_sizes, int n_in,
                              void* d_out, int out_size) {
    const float* HF       = (const float*)d_in[0];
    const float* X        = (const float*)d_in[1];
    const float* drug_emb = (const float*)d_in[2];
    const float* rel_emb  = (const float*)d_in[3];
    const float* tail_emb = (const float*)d_in[4];
    const float* W1       = (const float*)d_in[5];
    const float* b1       = (const float*)d_in[6];
    const float* W2       = (const float*)d_in[7];
    const float* b2       = (const float*)d_in[8];
    const float* Wc       = (const float*)d_in[9];
    const float* bc       = (const float*)d_in[10];
    const float* gamma    = (const float*)d_in[11];
    const float* beta     = (const float*)d_in[12];
    const int*   DKG      = (const int*)d_in[13];
    int E    = in_sizes[13] / 3;
    int hf_n = in_sizes[0];
    int x_n  = in_sizes[1];
    float* out = (float*)d_out;

    u32 k1x, k1y, kLx, kLy;
    compute_keys(k1x, k1y, kLx, kLy);

    scatter_kernel<<<ABLK, ATHR>>>(DKG, HF, X, W2, b2, out, E, hf_n, x_n, k1x, k1y);
    mega_kernel<<<NBLK, NTHR>>>(DKG, drug_emb, rel_emb, tail_emb, W1, b1,
                                Wc, bc, gamma, beta, out + hf_n, kLx, kLy);
}

// round 11
// speedup vs baseline: 2.4275x; 1.1528x over previous
#include <cuda_runtime.h>
#include <stdint.h>

#define ND    10000
#define DIM   64
#define SS    16
#define EMAX  1000000
#define NBLK  592
#define NTHR  256
#define NWPB  8
#define NWARP (NBLK*NWPB)
#define CAP   192                // per-drug bucket capacity (deg ~ Poisson(100))
#define REGCAP 160               // fast-path selection capacity (5 keys/lane)
#define OVFCAP 8192
#define ABLK  1184               // scatter kernel blocks
#define ATHR  256

typedef unsigned int u32;
typedef unsigned long long u64;

// ---------------------------------------------------------------- threefry2x32
__host__ __device__ __forceinline__ void threefry(u32 k0, u32 k1, u32 x0, u32 x1,
                                                  u32& o0, u32& o1) {
#ifdef __CUDA_ARCH__
#define TFR(a,b,r) { a += b; b = __funnelshift_l(b, b, r); b ^= a; }
#else
#define TFR(a,b,r) { a += b; b = (b<<r)|(b>>(32-r)); b ^= a; }
#endif
    u32 ks2 = k0 ^ k1 ^ 0x1BD11BDAu;
    x0 += k0; x1 += k1;
    TFR(x0,x1,13); TFR(x0,x1,15); TFR(x0,x1,26); TFR(x0,x1,6);
    x0 += k1; x1 += ks2 + 1u;
    TFR(x0,x1,17); TFR(x0,x1,29); TFR(x0,x1,16); TFR(x0,x1,24);
    x0 += ks2; x1 += k0 + 2u;
    TFR(x0,x1,13); TFR(x0,x1,15); TFR(x0,x1,26); TFR(x0,x1,6);
    x0 += k0; x1 += k1 + 3u;
    TFR(x0,x1,17); TFR(x0,x1,29); TFR(x0,x1,16); TFR(x0,x1,24);
    x0 += k1; x1 += ks2 + 4u;
    TFR(x0,x1,13); TFR(x0,x1,15); TFR(x0,x1,26); TFR(x0,x1,6);
    x0 += ks2; x1 += k0 + 5u;
    o0 = x0; o1 = x1;
#undef TFR
}
__device__ __forceinline__ u32 rbits_stream(u32 kx, u32 ky, int i) {
    u32 a, b; threefry(kx, ky, 0u, (u32)i, a, b);
    return a ^ b;
}

// ---------------------------------------------------------------- scratch
__device__ int   g_cursor[ND];               // zero at launch; re-zeroed at end
__device__ u64   g_bucket[(size_t)ND*CAP];   // rank(23)|edge(20)
__device__ int   g_ovfCnt;
__device__ u64   g_ovf[OVFCAP];
__device__ float g_neigh[ND*DIM];
__device__ float g_y[ND*DIM];
__device__ float g_psum[NBLK*DIM];
__device__ float g_psq[NBLK*DIM];
__device__ float g_A[DIM];
__device__ float g_B[DIM];
__device__ float g_w2s[DIM];
__device__ float g_b2s;
__device__ u32   g_bar_count;
__device__ u32   g_bar_gen;                  // monotonic across replays
__device__ u32   g_work;

// ---------------------------------------------------------------- f32x2 helpers
__device__ __forceinline__ u64 pack2(float lo, float hi) {
    u64 r;
    asm("mov.b64 %0, {%1, %2};" : "=l"(r) : "f"(lo), "f"(hi));
    return r;
}
__device__ __forceinline__ void unpack2(u64 v, float& lo, float& hi) {
    asm("mov.b64 {%0, %1}, %2;" : "=f"(lo), "=f"(hi) : "l"(v));
}
__device__ __forceinline__ void fma2(u64& acc, u64 a, u64 b) {
    asm("fma.rn.f32x2 %0, %1, %2, %0;" : "+l"(acc) : "l"(a), "l"(b));
}
__device__ __forceinline__ u64 umin64(u64 a, u64 b) { return a < b ? a : b; }

// ================================================================ scatter kernel
__global__ void scatter_kernel(const int* __restrict__ DKG,
                               const float* __restrict__ HF,
                               const float* __restrict__ X,
                               const float* __restrict__ W2,
                               const float* __restrict__ b2,
                               float* __restrict__ outBase,
                               int E, int hf_n, int x_n,
                               u32 k1x, u32 k1y) {
    const int gtid = blockIdx.x * ATHR + threadIdx.x;
    const int nth  = ABLK * ATHR;

    {
        const float4* hf4 = (const float4*)HF;
        float4* o4 = (float4*)outBase;
        for (int t = gtid; t < hf_n/4; t += nth) o4[t] = hf4[t];
        const float4* x4 = (const float4*)X;
        float4* ox4 = (float4*)(outBase + hf_n + ND*DIM);
        for (int t = gtid; t < x_n/4; t += nth) ox4[t] = x4[t];
    }
    if (blockIdx.x == ABLK - 1) {
        int t = threadIdx.x;
        if (t < DIM) {
            float s = 0.f;
            for (int j = 0; j < DIM; j++) s += W2[t*DIM + j];
            g_w2s[t] = s;
        }
        if (t == DIM) {
            float s = 0.f;
            for (int j = 0; j < DIM; j++) s += b2[j];
            g_b2s = s;
        }
    }

    for (int e = gtid*2; e < E; e += nth*2) {
        int e1 = e + 1;
        bool has1 = (e1 < E);
        int h0 = DKG[3*e];
        int h1 = has1 ? DKG[3*e1] : 0;
        int slot0 = atomicAdd(&g_cursor[h0], 1);
        int slot1 = has1 ? atomicAdd(&g_cursor[h1], 1) : 0;
        u32 a0, b0, a1, b1v;
        threefry(k1x, k1y, 0u, (u32)e,  a0, b0);
        threefry(k1x, k1y, 0u, (u32)e1, a1, b1v);
        u32 bits0 = a0 ^ b0, bits1 = a1 ^ b1v;
        u64 key0 = (((u64)(bits0 >> 9)) << 20) | (u32)e;
        if (slot0 < CAP) g_bucket[(size_t)h0*CAP + slot0] = key0;
        else {
            int o = atomicAdd(&g_ovfCnt, 1);
            if (o < OVFCAP) g_ovf[o] = ((u64)h0 << 43) | key0;
        }
        if (has1) {
            u64 key1 = (((u64)(bits1 >> 9)) << 20) | (u32)e1;
            if (slot1 < CAP) g_bucket[(size_t)h1*CAP + slot1] = key1;
            else {
                int o = atomicAdd(&g_ovfCnt, 1);
                if (o < OVFCAP) g_ovf[o] = ((u64)h1 << 43) | key1;
            }
        }
    }
}

// ---------------------------------------------------------------- shared layout
// phase B: [0,16384) w1pk2 | [16384) b1s | [16640) w2ss | [16896,33280) hbuf 8w*2KB (ssel aliases)
// phase C: [0,32768) wcp2 | [32768,33792) red | [33792,41984) xbuf 8w*1KB
#define SH_BYTES (42*1024)

__global__ void __launch_bounds__(NTHR, 4)
mega_kernel(const int* __restrict__ DKG,
            const float* __restrict__ drug_emb,
            const float* __restrict__ rel_emb,
            const float* __restrict__ tail_emb,
            const float* __restrict__ W1,
            const float* __restrict__ b1,
            const float* __restrict__ Wc,
            const float* __restrict__ bc,
            const float* __restrict__ gamma,
            const float* __restrict__ beta,
            float* __restrict__ out,
            u32 kLx, u32 kLy) {
    __shared__ __align__(16) char sh_raw[SH_BYTES];
    __shared__ u32 s_gen;

    const int tid  = threadIdx.x;
    const int bid  = blockIdx.x;
    const int gtid = bid * NTHR + tid;
    const int nth  = NBLK * NTHR;
    const int lane = tid & 31;
    const int wid  = tid >> 5;

    if (tid == 0) s_gen = *((volatile u32*)&g_bar_gen);

    auto gsync = [&]() {
        __syncthreads();
        if (tid == 0) {
            u32 target = s_gen + 1;
            __threadfence();
            u32 t = atomicAdd(&g_bar_count, 1u);
            if (t == (u32)NBLK - 1) {
                atomicExch(&g_bar_count, 0u);
                __threadfence();
                atomicExch(&g_bar_gen, target);
            } else {
                volatile u32* vg = &g_bar_gen;
                while (*vg < target) { }
            }
            __threadfence();
            s_gen = target;
        }
        __syncthreads();
    };

    // ============ phase B fused: select top16 + score + aggregate ============
    {
        ulonglong2* w1pk2 = (ulonglong2*)sh_raw;      // [ip*32+lane]
        float* b1s   = (float*)(sh_raw + 16384);
        float* w2ss  = (float*)(sh_raw + 16640);
        u64*   hbuf  = (u64*)(sh_raw + 16896) + wid * 256;   // 2KB/warp
        int*   ssel  = (int*)(sh_raw + 16896 + wid * 2048);  // aliases hbuf (disjoint use)

        for (int i = tid; i < 32*32; i += NTHR) {
            int ip = i >> 5, ln = i & 31;
            ulonglong2 v;
            v.x = pack2(W1[(2*ip)*DIM + ln],      W1[(2*ip + 1)*DIM + ln]);
            v.y = pack2(W1[(2*ip)*DIM + 32 + ln], W1[(2*ip + 1)*DIM + 32 + ln]);
            w1pk2[i] = v;
        }
        if (tid < DIM)        b1s[tid] = b1[tid];
        else if (tid < 2*DIM) w2ss[tid - DIM] = g_w2s[tid - DIM];
        __syncthreads();
        const float b2s = g_b2s;
        const u64 FULLK = ~0ULL;

        for (;;) {
            int d;
            if (lane == 0) d = (int)atomicAdd(&g_work, 1u);
            d = __shfl_sync(0xffffffffu, d, 0);
            if (d >= ND) break;

            const int degd = g_cursor[d];
            const int cnt  = (degd < SS) ? degd : SS;
            const u64* bkt = g_bucket + (size_t)d*CAP;

            if (degd >= SS && degd <= REGCAP) {
                // ================= FAST PATH (cnt == 16) =================
                u64 c0 = (lane       < degd) ? bkt[lane]       : FULLK;
                u64 c1 = (lane + 32  < degd) ? bkt[lane + 32]  : FULLK;
                u64 c2 = (lane + 64  < degd) ? bkt[lane + 64]  : FULLK;
                u64 c3 = (lane + 96  < degd) ? bkt[lane + 96]  : FULLK;
                u64 c4 = (lane + 128 < degd) ? bkt[lane + 128] : FULLK;
                u64 lmin = umin64(umin64(umin64(c0, c1), umin64(c2, c3)), c4);
                int tail = 0, rel = 0;
                #pragma unroll
                for (int r = 0; r < SS; r++) {
                    u32 hi = (u32)(lmin >> 11);
                    u32 mhi = __reduce_min_sync(0xffffffffu, hi);
                    u32 bal = __ballot_sync(0xffffffffu, hi == mhi);
                    u64 m;
                    if (__popc(bal) == 1) {
                        m = __shfl_sync(0xffffffffu, lmin, __ffs(bal) - 1);
                    } else {
                        m = lmin;
                        #pragma unroll
                        for (int o = 16; o; o >>= 1)
                            m = umin64(m, __shfl_xor_sync(0xffffffffu, m, o));
                    }
                    int er = (int)(m & 0xFFFFFu);
                    if (lane == r) {
                        tail = DKG[3*er + 1];
                        rel  = DKG[3*er + 2];
                    }
                    if (lmin == m) {
                        if      (c0 == m) c0 = FULLK;
                        else if (c1 == m) c1 = FULLK;
                        else if (c2 == m) c2 = FULLK;
                        else if (c3 == m) c3 = FULLK;
                        else              c4 = FULLK;
                        lmin = umin64(umin64(umin64(c0, c1), umin64(c2, c3)), c4);
                    }
                }

                const float2 de2 = ((const float2*)(drug_emb + d*DIM))[lane];
                const u64 bin0 = pack2(b1s[lane], 0.f);
                const u64 bin1 = pack2(b1s[lane + 32], 0.f);
                const float w20 = w2ss[lane], w21 = w2ss[lane + 32];

                float myscore = 0.f;
                #pragma unroll
                for (int kb = 0; kb < 2; kb++) {
                    const int kbase = kb * 8;
                    {
                        u64 h[8];
                        #pragma unroll
                        for (int u = 0; u < 8; u++) {
                            int rr = __shfl_sync(0xffffffffu, rel, kbase + u);
                            float2 re = ((const float2*)(rel_emb + rr*DIM))[lane];
                            h[u] = pack2(de2.x*re.x, de2.y*re.y);
                        }
                        #pragma unroll
                        for (int u = 0; u < 8; u++) hbuf[u*32 + lane] = h[u];
                    }
                    __syncwarp();
                    u64 a0[8], a1[8];
                    #pragma unroll
                    for (int u = 0; u < 8; u++) { a0[u] = bin0; a1[u] = bin1; }
                    #pragma unroll
                    for (int ip = 0; ip < 32; ip++) {
                        ulonglong2 wv = w1pk2[ip*32 + lane];   // LDS.128
                        #pragma unroll
                        for (int u = 0; u < 8; u++) {
                            u64 hb = hbuf[u*32 + ip];          // LDS.64 broadcast
                            fma2(a0[u], hb, wv.x);
                            fma2(a1[u], hb, wv.y);
                        }
                    }
                    __syncwarp();
                    #pragma unroll
                    for (int u = 0; u < 8; u++) {
                        float e0, o0, e1, o1;
                        unpack2(a0[u], e0, o0);
                        unpack2(a1[u], e1, o1);
                        float p = (1.f/(1.f+__expf(-(e0+o0))))*w20
                                + (1.f/(1.f+__expf(-(e1+o1))))*w21;
                        #pragma unroll
                        for (int o = 16; o; o >>= 1)
                            p += __shfl_xor_sync(0xffffffffu, p, o);
                        if (lane == kbase + u) myscore = p + b2s;
                    }
                }

                float acc0 = 0.f, acc1 = 0.f;
                #pragma unroll
                for (int k = 0; k < SS; k++) {
                    float sc = __shfl_sync(0xffffffffu, myscore, k);
                    int   t  = __shfl_sync(0xffffffffu, tail, k);
                    acc0 = fmaf(sc, tail_emb[t*DIM + lane], acc0);
                    acc1 = fmaf(sc, tail_emb[t*DIM + 32 + lane], acc1);
                }
                g_neigh[d*DIM + lane]      = acc0;
                g_neigh[d*DIM + 32 + lane] = acc1;

            } else if (cnt > 0) {
                // ================= SLOW PATH =================
                int myedge = 0;
                if (degd <= REGCAP) {
                    u64 c0 = (lane       < degd) ? bkt[lane]       : FULLK;
                    u64 c1 = (lane + 32  < degd) ? bkt[lane + 32]  : FULLK;
                    u64 c2 = (lane + 64  < degd) ? bkt[lane + 64]  : FULLK;
                    u64 c3 = (lane + 96  < degd) ? bkt[lane + 96]  : FULLK;
                    u64 c4 = (lane + 128 < degd) ? bkt[lane + 128] : FULLK;
                    u64 lmin = umin64(umin64(umin64(c0, c1), umin64(c2, c3)), c4);
                    for (int r = 0; r < cnt; r++) {
                        u64 m = lmin;
                        #pragma unroll
                        for (int o = 16; o; o >>= 1) {
                            u64 t = __shfl_xor_sync(0xffffffffu, m, o);
                            m = umin64(m, t);
                        }
                        if (lane == r) myedge = (int)(m & 0xFFFFFu);
                        if (lmin == m) {
                            if      (c0 == m) c0 = FULLK;
                            else if (c1 == m) c1 = FULLK;
                            else if (c2 == m) c2 = FULLK;
                            else if (c3 == m) c3 = FULLK;
                            else              c4 = FULLK;
                            lmin = umin64(umin64(umin64(c0, c1), umin64(c2, c3)), c4);
                        }
                    }
                } else {
                    int nb = (degd < CAP) ? degd : CAP;
                    int novf = g_ovfCnt; if (novf > OVFCAP) novf = OVFCAP;
                    for (int t = lane; t < nb; t += 32) {
                        u64 k = bkt[t];
                        int rank = 0;
                        for (int j = 0; j < nb; j++) rank += (bkt[j] < k);
                        for (int o = 0; o < novf; o++) {
                            u64 v = g_ovf[o];
                            if ((int)(v >> 43) == d) rank += ((v & 0x7FFFFFFFFFFULL) < k);
                        }
                        if (rank < SS) ssel[rank] = (int)(k & 0xFFFFFu);
                    }
                    for (int t = lane; t < novf; t += 32) {
                        u64 v = g_ovf[t];
                        if ((int)(v >> 43) == d) {
                            u64 k = v & 0x7FFFFFFFFFFULL;
                            int rank = 0;
                            for (int j = 0; j < nb; j++) rank += (bkt[j] < k);
                            for (int o = 0; o < novf; o++) {
                                u64 w = g_ovf[o];
                                if ((int)(w >> 43) == d) rank += ((w & 0x7FFFFFFFFFFULL) < k);
                            }
                            if (rank < SS) ssel[rank] = (int)(k & 0xFFFFFu);
                        }
                    }
                    __syncwarp();
                    if (lane < cnt) myedge = ssel[lane];
                }

                int tail = 0, rel = 0;
                if (lane < cnt) {
                    tail = DKG[3*myedge + 1];
                    rel  = DKG[3*myedge + 2];
                }
                __syncwarp();

                const float2 de2 = ((const float2*)(drug_emb + d*DIM))[lane];
                const u64 bin0 = pack2(b1s[lane], 0.f);
                const u64 bin1 = pack2(b1s[lane + 32], 0.f);
                const float w20 = w2ss[lane], w21 = w2ss[lane + 32];

                float myscore = 0.f;
                for (int k = 0; k < cnt; k++) {
                    int rA = __shfl_sync(0xffffffffu, rel, k);
                    float2 reA = ((const float2*)(rel_emb + rA*DIM))[lane];
                    u64 hA = pack2(de2.x*reA.x, de2.y*reA.y);
                    u64 aA0 = bin0, aA1 = bin1;
                    #pragma unroll
                    for (int ip = 0; ip < 32; ip++) {
                        ulonglong2 wv = w1pk2[ip*32 + lane];
                        u64 hb = __shfl_sync(0xffffffffu, hA, ip);
                        fma2(aA0, hb, wv.x); fma2(aA1, hb, wv.y);
                    }
                    float e0, o0, e1, o1;
                    unpack2(aA0, e0, o0); unpack2(aA1, e1, o1);
                    float pA = (1.f/(1.f+__expf(-(e0+o0))))*w20
                             + (1.f/(1.f+__expf(-(e1+o1))))*w21;
                    #pragma unroll
                    for (int o = 16; o; o >>= 1) pA += __shfl_xor_sync(0xffffffffu, pA, o);
                    if (lane == k) myscore = pA + b2s;
                }

                float acc0 = 0.f, acc1 = 0.f;
                for (int k = 0; k < cnt; k++) {
                    float sc = __shfl_sync(0xffffffffu, myscore, k);
                    int   t  = __shfl_sync(0xffffffffu, tail, k);
                    acc0 = fmaf(sc, tail_emb[t*DIM + lane], acc0);
                    acc1 = fmaf(sc, tail_emb[t*DIM + 32 + lane], acc1);
                }
                if (degd < SS) {
                    for (int s = 0; s < SS - degd; s++) {
                        u32 bits = rbits_stream(kLx, kLy, d*SS + s);
                        int idx = (int)((bits % 2147483647u) % (u32)degd);
                        float sc = __shfl_sync(0xffffffffu, myscore, idx);
                        int   t  = __shfl_sync(0xffffffffu, tail, idx);
                        acc0 = fmaf(sc, tail_emb[t*DIM + lane], acc0);
                        acc1 = fmaf(sc, tail_emb[t*DIM + 32 + lane], acc1);
                    }
                }
                g_neigh[d*DIM + lane]      = acc0;
                g_neigh[d*DIM + 32 + lane] = acc1;
            } else {
                g_neigh[d*DIM + lane]      = 0.f;
                g_neigh[d*DIM + 32 + lane] = 0.f;
            }
        }
    }
    gsync();

    // ============ phase C: y = [drug_emb, neigh] @ Wc + bc ============
    {
        if (gtid == 0) { g_work = 0; g_ovfCnt = 0; }   // replay-state reset
        ulonglong2* wcp2 = (ulonglong2*)sh_raw;        // 32KB
        float* red = (float*)(sh_raw + 32768);         // 1KB
        u64*   xb  = (u64*)(sh_raw + 33792) + wid * 128;  // 1KB/warp
        for (int i = tid; i < 64*32; i += NTHR) {
            int i2 = i >> 5, o = i & 31;
            ulonglong2 v;
            v.x = pack2(Wc[(2*i2)*DIM + o],     Wc[(2*i2)*DIM + o + 32]);
            v.y = pack2(Wc[(2*i2 + 1)*DIM + o], Wc[(2*i2 + 1)*DIM + o + 32]);
            wcp2[i] = v;
        }
        __syncthreads();
        const int o = lane;
        const u64 bcv = pack2(bc[o], bc[o + 32]);
        float S0 = 0.f, S1 = 0.f, Q0 = 0.f, Q1 = 0.f;
        for (int r16 = bid; r16 < 625; r16 += NBLK) {   // 625*16 == ND exactly
            int row0 = r16*16 + wid;
            int row1 = row0 + 8;
            xb[lane]      = ((const u64*)(drug_emb + row0*DIM))[lane];
            xb[32 + lane] = ((const u64*)(g_neigh  + row0*DIM))[lane];
            xb[64 + lane] = ((const u64*)(drug_emb + row1*DIM))[lane];
            xb[96 + lane] = ((const u64*)(g_neigh  + row1*DIM))[lane];
            __syncwarp();
            u64 accR0 = bcv, accR1 = bcv;
            #pragma unroll
            for (int i2 = 0; i2 < 32; i2++) {
                ulonglong2 wv = wcp2[i2*32 + o];
                u64 dA = xb[i2];
                u64 dB = xb[64 + i2];
                float vA0, vA1, vB0, vB1;
                unpack2(dA, vA0, vA1);
                unpack2(dB, vB0, vB1);
                fma2(accR0, pack2(vA0, vA0), wv.x);
                fma2(accR0, pack2(vA1, vA1), wv.y);
                fma2(accR1, pack2(vB0, vB0), wv.x);
                fma2(accR1, pack2(vB1, vB1), wv.y);
            }
            #pragma unroll
            for (int i2 = 0; i2 < 32; i2++) {
                ulonglong2 wv = wcp2[(32 + i2)*32 + o];
                u64 dA = xb[32 + i2];
                u64 dB = xb[96 + i2];
                float vA0, vA1, vB0, vB1;
                unpack2(dA, vA0, vA1);
                unpack2(dB, vB0, vB1);
                fma2(accR0, pack2(vA0, vA0), wv.x);
                fma2(accR0, pack2(vA1, vA1), wv.y);
                fma2(accR1, pack2(vB0, vB0), wv.x);
                fma2(accR1, pack2(vB1, vB1), wv.y);
            }
            __syncwarp();
            float y00, y01, y10, y11;
            unpack2(accR0, y00, y01);
            unpack2(accR1, y10, y11);
            g_y[row0*DIM + o]      = y00;
            g_y[row0*DIM + 32 + o] = y01;
            g_y[row1*DIM + o]      = y10;
            g_y[row1*DIM + 32 + o] = y11;
            S0 += y00 + y10;
            S1 += y01 + y11;
            Q0 += y00*y00 + y10*y10;
            Q1 += y01*y01 + y11*y11;
        }
        red[tid] = S0;
        __syncthreads();
        if (tid < 32) { float s = 0.f;
            #pragma unroll
            for (int p = 0; p < 8; p++) s += red[p*32 + lane];
            g_psum[bid*DIM + lane] = s; }
        __syncthreads();
        red[tid] = S1;
        __syncthreads();
        if (tid < 32) { float s = 0.f;
            #pragma unroll
            for (int p = 0; p < 8; p++) s += red[p*32 + lane];
            g_psum[bid*DIM + 32 + lane] = s; }
        __syncthreads();
        red[tid] = Q0;
        __syncthreads();
        if (tid < 32) { float s = 0.f;
            #pragma unroll
            for (int p = 0; p < 8; p++) s += red[p*32 + lane];
            g_psq[bid*DIM + lane] = s; }
        __syncthreads();
        red[tid] = Q1;
        __syncthreads();
        if (tid < 32) { float s = 0.f;
            #pragma unroll
            for (int p = 0; p < 8; p++) s += red[p*32 + lane];
            g_psq[bid*DIM + 32 + lane] = s; }
    }
    gsync();

    // ============ phase D1: per-column BN stats (64 blocks) ============
    if (bid < DIM) {
        float* rs = (float*)sh_raw;
        float* rq = (float*)(sh_raw + 1024);
        const int col = bid;
        float s = 0.f, q = 0.f;
        for (int b = tid; b < NBLK; b += NTHR) {
            s += g_psum[b*DIM + col];
            q += g_psq[b*DIM + col];
        }
        rs[tid] = s; rq[tid] = q;
        __syncthreads();
        for (int ofs = NTHR/2; ofs > 0; ofs >>= 1) {
            if (tid < ofs) { rs[tid] += rs[tid + ofs]; rq[tid] += rq[tid + ofs]; }
            __syncthreads();
        }
        if (tid == 0) {
            float mean = rs[0] / (float)ND;
            float var  = rq[0] / (float)ND - mean * mean;
            float rstd = rsqrtf(var + 1e-5f);
            float gm = gamma[col];
            g_A[col] = gm * rstd;
            g_B[col] = beta[col] - gm * mean * rstd;
        }
    }
    gsync();

    // ============ phase D2: normalize + write + state reset ============
    {
        float* A = (float*)sh_raw;
        float* B = (float*)(sh_raw + 256);
        if (tid < DIM)        A[tid] = g_A[tid];
        else if (tid < 2*DIM) B[tid - DIM] = g_B[tid - DIM];
        __syncthreads();

        const float4* y4 = (const float4*)g_y;
        float4* o4 = (float4*)out;
        for (int t = gtid; t < ND*DIM/4; t += nth) {
            int c = (t*4) & 63;
            float4 v = y4[t];
            float4 r;
            r.x = fmaf(v.x, A[c+0], B[c+0]);
            r.y = fmaf(v.y, A[c+1], B[c+1]);
            r.z = fmaf(v.z, A[c+2], B[c+2]);
            r.w = fmaf(v.w, A[c+3], B[c+3]);
            o4[t] = r;
        }

        // replay-state reset: g_cursor must be zero for next replay's scatter
        for (int i = gtid; i < ND; i += nth) g_cursor[i] = 0;
    }
}

// ---------------------------------------------------------------- host
static void compute_keys(u32& k1x, u32& k1y, u32& kLx, u32& kLy) {
    u32 a, b, c, d, e, f;
    threefry(0u, 42u, 0u, 0u, a, b);   // k1 = split(key(42))[0]
    k1x = a; k1y = b;
    threefry(0u, 42u, 0u, 1u, c, d);   // k2 = split(key(42))[1]
    threefry(c, d, 0u, 1u, e, f);      // split(k2)[1]
    kLx = e; kLy = f;
}

extern "C" void kernel_launch(void* const* d_in, const int* in_sizes, int n_in,
                              void* d_out, int out_size) {
    const float* HF       = (const float*)d_in[0];
    const float* X        = (const float*)d_in[1];
    const float* drug_emb = (const float*)d_in[2];
    const float* rel_emb  = (const float*)d_in[3];
    const float* tail_emb = (const float*)d_in[4];
    const float* W1       = (const float*)d_in[5];
    const float* b1       = (const float*)d_in[6];
    const float* W2       = (const float*)d_in[7];
    const float* b2       = (const float*)d_in[8];
    const float* Wc       = (const float*)d_in[9];
    const float* bc       = (const float*)d_in[10];
    const float* gamma    = (const float*)d_in[11];
    const float* beta     = (const float*)d_in[12];
    const int*   DKG      = (const int*)d_in[13];
    int E    = in_sizes[13] / 3;
    int hf_n = in_sizes[0];
    int x_n  = in_sizes[1];
    float* out = (float*)d_out;

    u32 k1x, k1y, kLx, kLy;
    compute_keys(k1x, k1y, kLx, kLy);

    scatter_kernel<<<ABLK, ATHR>>>(DKG, HF, X, W2, b2, out, E, hf_n, x_n, k1x, k1y);
    mega_kernel<<<NBLK, NTHR>>>(DKG, drug_emb, rel_emb, tail_emb, W1, b1,
                                Wc, bc, gamma, beta, out + hf_n, kLx, kLy);
}

// round 12
// speedup vs baseline: 2.5331x; 1.0435x over previous
#include <cuda_runtime.h>
#include <stdint.h>

#define ND    10000
#define DIM   64
#define SS    16
#define EMAX  1000000
#define NBLK  592
#define NTHR  256
#define NWPB  8
#define NWARP (NBLK*NWPB)
#define CAP   192                // per-drug bucket capacity (deg ~ Poisson(100))
#define REGCAP 160               // fast-path selection capacity (5 keys/lane)
#define OVFCAP 8192
#define ABLK  1184               // scatter kernel blocks
#define ATHR  256

typedef unsigned int u32;
typedef unsigned long long u64;

// ---------------------------------------------------------------- threefry2x32
__host__ __device__ __forceinline__ void threefry(u32 k0, u32 k1, u32 x0, u32 x1,
                                                  u32& o0, u32& o1) {
#ifdef __CUDA_ARCH__
#define TFR(a,b,r) { a += b; b = __funnelshift_l(b, b, r); b ^= a; }
#else
#define TFR(a,b,r) { a += b; b = (b<<r)|(b>>(32-r)); b ^= a; }
#endif
    u32 ks2 = k0 ^ k1 ^ 0x1BD11BDAu;
    x0 += k0; x1 += k1;
    TFR(x0,x1,13); TFR(x0,x1,15); TFR(x0,x1,26); TFR(x0,x1,6);
    x0 += k1; x1 += ks2 + 1u;
    TFR(x0,x1,17); TFR(x0,x1,29); TFR(x0,x1,16); TFR(x0,x1,24);
    x0 += ks2; x1 += k0 + 2u;
    TFR(x0,x1,13); TFR(x0,x1,15); TFR(x0,x1,26); TFR(x0,x1,6);
    x0 += k0; x1 += k1 + 3u;
    TFR(x0,x1,17); TFR(x0,x1,29); TFR(x0,x1,16); TFR(x0,x1,24);
    x0 += k1; x1 += ks2 + 4u;
    TFR(x0,x1,13); TFR(x0,x1,15); TFR(x0,x1,26); TFR(x0,x1,6);
    x0 += ks2; x1 += k0 + 5u;
    o0 = x0; o1 = x1;
#undef TFR
}
__device__ __forceinline__ u32 rbits_stream(u32 kx, u32 ky, int i) {
    u32 a, b; threefry(kx, ky, 0u, (u32)i, a, b);
    return a ^ b;
}

// ---------------------------------------------------------------- scratch
__device__ int   g_cursor[ND];               // zero at launch; re-zeroed at end
__device__ u64   g_bucket[(size_t)ND*CAP];   // rank(23)|edge(20)
__device__ int   g_ovfCnt;
__device__ u64   g_ovf[OVFCAP];
__device__ float g_neigh[ND*DIM];
__device__ float g_y[ND*DIM];
__device__ float g_psum[NBLK*DIM];
__device__ float g_psq[NBLK*DIM];
__device__ float g_A[DIM];
__device__ float g_B[DIM];
__device__ float g_w2s[DIM];
__device__ float g_b2s;
__device__ u32   g_bar_count;
__device__ u32   g_bar_gen;                  // monotonic across replays
__device__ u32   g_work;

// ---------------------------------------------------------------- f32x2 helpers
__device__ __forceinline__ u64 pack2(float lo, float hi) {
    u64 r;
    asm("mov.b64 %0, {%1, %2};" : "=l"(r) : "f"(lo), "f"(hi));
    return r;
}
__device__ __forceinline__ void unpack2(u64 v, float& lo, float& hi) {
    asm("mov.b64 {%0, %1}, %2;" : "=f"(lo), "=f"(hi) : "l"(v));
}
__device__ __forceinline__ void fma2(u64& acc, u64 a, u64 b) {
    asm("fma.rn.f32x2 %0, %1, %2, %0;" : "+l"(acc) : "l"(a), "l"(b));
}
__device__ __forceinline__ u64 umin64(u64 a, u64 b) { return a < b ? a : b; }

// ================================================================ scatter kernel
__global__ void scatter_kernel(const int* __restrict__ DKG,
                               const float* __restrict__ HF,
                               const float* __restrict__ X,
                               const float* __restrict__ W2,
                               const float* __restrict__ b2,
                               float* __restrict__ outBase,
                               int E, int hf_n, int x_n,
                               u32 k1x, u32 k1y) {
    const int gtid = blockIdx.x * ATHR + threadIdx.x;
    const int nth  = ABLK * ATHR;

    {
        const float4* hf4 = (const float4*)HF;
        float4* o4 = (float4*)outBase;
        for (int t = gtid; t < hf_n/4; t += nth) o4[t] = hf4[t];
        const float4* x4 = (const float4*)X;
        float4* ox4 = (float4*)(outBase + hf_n + ND*DIM);
        for (int t = gtid; t < x_n/4; t += nth) ox4[t] = x4[t];
    }
    if (blockIdx.x == ABLK - 1) {
        int t = threadIdx.x;
        if (t < DIM) {
            float s = 0.f;
            for (int j = 0; j < DIM; j++) s += W2[t*DIM + j];
            g_w2s[t] = s;
        }
        if (t == DIM) {
            float s = 0.f;
            for (int j = 0; j < DIM; j++) s += b2[j];
            g_b2s = s;
        }
    }

    for (int e = gtid*2; e < E; e += nth*2) {
        int e1 = e + 1;
        bool has1 = (e1 < E);
        int h0 = DKG[3*e];
        int h1 = has1 ? DKG[3*e1] : 0;
        int slot0 = atomicAdd(&g_cursor[h0], 1);
        int slot1 = has1 ? atomicAdd(&g_cursor[h1], 1) : 0;
        u32 a0, b0, a1, b1v;
        threefry(k1x, k1y, 0u, (u32)e,  a0, b0);
        threefry(k1x, k1y, 0u, (u32)e1, a1, b1v);
        u32 bits0 = a0 ^ b0, bits1 = a1 ^ b1v;
        u64 key0 = (((u64)(bits0 >> 9)) << 20) | (u32)e;
        if (slot0 < CAP) g_bucket[(size_t)h0*CAP + slot0] = key0;
        else {
            int o = atomicAdd(&g_ovfCnt, 1);
            if (o < OVFCAP) g_ovf[o] = ((u64)h0 << 43) | key0;
        }
        if (has1) {
            u64 key1 = (((u64)(bits1 >> 9)) << 20) | (u32)e1;
            if (slot1 < CAP) g_bucket[(size_t)h1*CAP + slot1] = key1;
            else {
                int o = atomicAdd(&g_ovfCnt, 1);
                if (o < OVFCAP) g_ovf[o] = ((u64)h1 << 43) | key1;
            }
        }
    }
}

// ---------------------------------------------------------------- shared layout
// phase B: [0,16384) w1pk2 | [16384) b1s | [16640) w2ss | [16896,33280) hb2 8w*2KB (ssel aliases)
// phase C: [0,32768) wcp2 | [32768,33792) red | [33792,41984) xbuf 8w*1KB
#define SH_BYTES (42*1024)

__global__ void __launch_bounds__(NTHR, 4)
mega_kernel(const int* __restrict__ DKG,
            const float* __restrict__ drug_emb,
            const float* __restrict__ rel_emb,
            const float* __restrict__ tail_emb,
            const float* __restrict__ W1,
            const float* __restrict__ b1,
            const float* __restrict__ Wc,
            const float* __restrict__ bc,
            const float* __restrict__ gamma,
            const float* __restrict__ beta,
            float* __restrict__ out,
            u32 kLx, u32 kLy) {
    __shared__ __align__(16) char sh_raw[SH_BYTES];
    __shared__ u32 s_gen;

    const int tid  = threadIdx.x;
    const int bid  = blockIdx.x;
    const int gtid = bid * NTHR + tid;
    const int nth  = NBLK * NTHR;
    const int lane = tid & 31;
    const int wid  = tid >> 5;

    if (tid == 0) s_gen = *((volatile u32*)&g_bar_gen);

    auto gsync = [&]() {
        __syncthreads();
        if (tid == 0) {
            u32 target = s_gen + 1;
            __threadfence();
            u32 t = atomicAdd(&g_bar_count, 1u);
            if (t == (u32)NBLK - 1) {
                atomicExch(&g_bar_count, 0u);
                __threadfence();
                atomicExch(&g_bar_gen, target);
            } else {
                volatile u32* vg = &g_bar_gen;
                while (*vg < target) { }
            }
            __threadfence();
            s_gen = target;
        }
        __syncthreads();
    };

    // ============ phase B fused: select top16 + score + aggregate ============
    {
        ulonglong2* w1pk2 = (ulonglong2*)sh_raw;      // [ip*32+lane]
        float* b1s   = (float*)(sh_raw + 16384);
        float* w2ss  = (float*)(sh_raw + 16640);
        ulonglong2* hb2 = (ulonglong2*)(sh_raw + 16896) + wid * 128;  // 2KB/warp
        int*   ssel  = (int*)(sh_raw + 16896 + wid * 2048);  // aliases hb2 (disjoint use)

        for (int i = tid; i < 32*32; i += NTHR) {
            int ip = i >> 5, ln = i & 31;
            ulonglong2 v;
            v.x = pack2(W1[(2*ip)*DIM + ln],      W1[(2*ip + 1)*DIM + ln]);
            v.y = pack2(W1[(2*ip)*DIM + 32 + ln], W1[(2*ip + 1)*DIM + 32 + ln]);
            w1pk2[i] = v;
        }
        if (tid < DIM)        b1s[tid] = b1[tid];
        else if (tid < 2*DIM) w2ss[tid - DIM] = g_w2s[tid - DIM];
        __syncthreads();
        const float b2s = g_b2s;
        const u64 FULLK = ~0ULL;

        for (;;) {
            int d;
            if (lane == 0) d = (int)atomicAdd(&g_work, 1u);
            d = __shfl_sync(0xffffffffu, d, 0);
            if (d >= ND) break;

            const int degd = g_cursor[d];
            const int cnt  = (degd < SS) ? degd : SS;
            const u64* bkt = g_bucket + (size_t)d*CAP;

            if (degd >= SS && degd <= REGCAP) {
                // ================= FAST PATH (cnt == 16) =================
                u64 c0 = (lane       < degd) ? bkt[lane]       : FULLK;
                u64 c1 = (lane + 32  < degd) ? bkt[lane + 32]  : FULLK;
                u64 c2 = (lane + 64  < degd) ? bkt[lane + 64]  : FULLK;
                u64 c3 = (lane + 96  < degd) ? bkt[lane + 96]  : FULLK;
                u64 c4 = (lane + 128 < degd) ? bkt[lane + 128] : FULLK;
                u64 lmin = umin64(umin64(umin64(c0, c1), umin64(c2, c3)), c4);
                int tail = 0, rel = 0;
                #pragma unroll
                for (int r = 0; r < SS; r++) {
                    u32 hi = (u32)(lmin >> 11);
                    u32 mhi = __reduce_min_sync(0xffffffffu, hi);
                    u32 bal = __ballot_sync(0xffffffffu, hi == mhi);
                    u64 m;
                    if (__popc(bal) == 1) {
                        m = __shfl_sync(0xffffffffu, lmin, __ffs(bal) - 1);
                    } else {
                        m = lmin;
                        #pragma unroll
                        for (int o = 16; o; o >>= 1)
                            m = umin64(m, __shfl_xor_sync(0xffffffffu, m, o));
                    }
                    int er = (int)(m & 0xFFFFFu);
                    if (lane == r) {
                        tail = DKG[3*er + 1];
                        rel  = DKG[3*er + 2];
                    }
                    if (lmin == m) {
                        if      (c0 == m) c0 = FULLK;
                        else if (c1 == m) c1 = FULLK;
                        else if (c2 == m) c2 = FULLK;
                        else if (c3 == m) c3 = FULLK;
                        else              c4 = FULLK;
                        lmin = umin64(umin64(umin64(c0, c1), umin64(c2, c3)), c4);
                    }
                }

                const float2 de2 = ((const float2*)(drug_emb + d*DIM))[lane];
                const u64 bin0 = pack2(b1s[lane], 0.f);
                const u64 bin1 = pack2(b1s[lane + 32], 0.f);
                const float w20 = w2ss[lane], w21 = w2ss[lane + 32];

                float myscore = 0.f;
                #pragma unroll
                for (int kb = 0; kb < 2; kb++) {
                    const int kbase = kb * 8;
                    {
                        u64 h[8];
                        #pragma unroll
                        for (int u = 0; u < 8; u++) {
                            int rr = __shfl_sync(0xffffffffu, rel, kbase + u);
                            float2 re = ((const float2*)(rel_emb + rr*DIM))[lane];
                            h[u] = pack2(de2.x*re.x, de2.y*re.y);
                        }
                        #pragma unroll
                        for (int p = 0; p < 4; p++) {
                            ulonglong2 hp; hp.x = h[2*p]; hp.y = h[2*p + 1];
                            hb2[p*32 + lane] = hp;          // STS.128
                        }
                    }
                    __syncwarp();
                    u64 a0[8], a1[8];
                    #pragma unroll
                    for (int u = 0; u < 8; u++) { a0[u] = bin0; a1[u] = bin1; }
                    #pragma unroll
                    for (int ip = 0; ip < 32; ip++) {
                        ulonglong2 wv = w1pk2[ip*32 + lane];   // LDS.128
                        #pragma unroll
                        for (int p = 0; p < 4; p++) {
                            ulonglong2 hp = hb2[p*32 + ip];    // LDS.128 broadcast
                            fma2(a0[2*p],     hp.x, wv.x);
                            fma2(a1[2*p],     hp.x, wv.y);
                            fma2(a0[2*p + 1], hp.y, wv.x);
                            fma2(a1[2*p + 1], hp.y, wv.y);
                        }
                    }
                    __syncwarp();
                    #pragma unroll
                    for (int u = 0; u < 8; u++) {
                        float e0, o0, e1, o1;
                        unpack2(a0[u], e0, o0);
                        unpack2(a1[u], e1, o1);
                        float p = (1.f/(1.f+__expf(-(e0+o0))))*w20
                                + (1.f/(1.f+__expf(-(e1+o1))))*w21;
                        #pragma unroll
                        for (int o = 16; o; o >>= 1)
                            p += __shfl_xor_sync(0xffffffffu, p, o);
                        if (lane == kbase + u) myscore = p + b2s;
                    }
                }

                // ---- packed aggregation: lanes own columns (2lane, 2lane+1) ----
                u64 accP = pack2(0.f, 0.f);
                #pragma unroll
                for (int k = 0; k < SS; k++) {
                    float sc = __shfl_sync(0xffffffffu, myscore, k);
                    int   t  = __shfl_sync(0xffffffffu, tail, k);
                    u64 te = ((const u64*)(tail_emb + t*DIM))[lane];
                    fma2(accP, pack2(sc, sc), te);
                }
                ((u64*)(g_neigh + d*DIM))[lane] = accP;

            } else if (cnt > 0) {
                // ================= SLOW PATH =================
                int myedge = 0;
                if (degd <= REGCAP) {
                    u64 c0 = (lane       < degd) ? bkt[lane]       : FULLK;
                    u64 c1 = (lane + 32  < degd) ? bkt[lane + 32]  : FULLK;
                    u64 c2 = (lane + 64  < degd) ? bkt[lane + 64]  : FULLK;
                    u64 c3 = (lane + 96  < degd) ? bkt[lane + 96]  : FULLK;
                    u64 c4 = (lane + 128 < degd) ? bkt[lane + 128] : FULLK;
                    u64 lmin = umin64(umin64(umin64(c0, c1), umin64(c2, c3)), c4);
                    for (int r = 0; r < cnt; r++) {
                        u64 m = lmin;
                        #pragma unroll
                        for (int o = 16; o; o >>= 1) {
                            u64 t = __shfl_xor_sync(0xffffffffu, m, o);
                            m = umin64(m, t);
                        }
                        if (lane == r) myedge = (int)(m & 0xFFFFFu);
                        if (lmin == m) {
                            if      (c0 == m) c0 = FULLK;
                            else if (c1 == m) c1 = FULLK;
                            else if (c2 == m) c2 = FULLK;
                            else if (c3 == m) c3 = FULLK;
                            else              c4 = FULLK;
                            lmin = umin64(umin64(umin64(c0, c1), umin64(c2, c3)), c4);
                        }
                    }
                } else {
                    int nb = (degd < CAP) ? degd : CAP;
                    int novf = g_ovfCnt; if (novf > OVFCAP) novf = OVFCAP;
                    for (int t = lane; t < nb; t += 32) {
                        u64 k = bkt[t];
                        int rank = 0;
                        for (int j = 0; j < nb; j++) rank += (bkt[j] < k);
                        for (int o = 0; o < novf; o++) {
                            u64 v = g_ovf[o];
                            if ((int)(v >> 43) == d) rank += ((v & 0x7FFFFFFFFFFULL) < k);
                        }
                        if (rank < SS) ssel[rank] = (int)(k & 0xFFFFFu);
                    }
                    for (int t = lane; t < novf; t += 32) {
                        u64 v = g_ovf[t];
                        if ((int)(v >> 43) == d) {
                            u64 k = v & 0x7FFFFFFFFFFULL;
                            int rank = 0;
                            for (int j = 0; j < nb; j++) rank += (bkt[j] < k);
                            for (int o = 0; o < novf; o++) {
                                u64 w = g_ovf[o];
                                if ((int)(w >> 43) == d) rank += ((w & 0x7FFFFFFFFFFULL) < k);
                            }
                            if (rank < SS) ssel[rank] = (int)(k & 0xFFFFFu);
                        }
                    }
                    __syncwarp();
                    if (lane < cnt) myedge = ssel[lane];
                }

                int tail = 0, rel = 0;
                if (lane < cnt) {
                    tail = DKG[3*myedge + 1];
                    rel  = DKG[3*myedge + 2];
                }
                __syncwarp();

                const float2 de2 = ((const float2*)(drug_emb + d*DIM))[lane];
                const u64 bin0 = pack2(b1s[lane], 0.f);
                const u64 bin1 = pack2(b1s[lane + 32], 0.f);
                const float w20 = w2ss[lane], w21 = w2ss[lane + 32];

                float myscore = 0.f;
                for (int k = 0; k < cnt; k++) {
                    int rA = __shfl_sync(0xffffffffu, rel, k);
                    float2 reA = ((const float2*)(rel_emb + rA*DIM))[lane];
                    u64 hA = pack2(de2.x*reA.x, de2.y*reA.y);
                    u64 aA0 = bin0, aA1 = bin1;
                    #pragma unroll
                    for (int ip = 0; ip < 32; ip++) {
                        ulonglong2 wv = w1pk2[ip*32 + lane];
                        u64 hb = __shfl_sync(0xffffffffu, hA, ip);
                        fma2(aA0, hb, wv.x); fma2(aA1, hb, wv.y);
                    }
                    float e0, o0, e1, o1;
                    unpack2(aA0, e0, o0); unpack2(aA1, e1, o1);
                    float pA = (1.f/(1.f+__expf(-(e0+o0))))*w20
                             + (1.f/(1.f+__expf(-(e1+o1))))*w21;
                    #pragma unroll
                    for (int o = 16; o; o >>= 1) pA += __shfl_xor_sync(0xffffffffu, pA, o);
                    if (lane == k) myscore = pA + b2s;
                }

                u64 accP = pack2(0.f, 0.f);
                for (int k = 0; k < cnt; k++) {
                    float sc = __shfl_sync(0xffffffffu, myscore, k);
                    int   t  = __shfl_sync(0xffffffffu, tail, k);
                    u64 te = ((const u64*)(tail_emb + t*DIM))[lane];
                    fma2(accP, pack2(sc, sc), te);
                }
                if (degd < SS) {
                    for (int s = 0; s < SS - degd; s++) {
                        u32 bits = rbits_stream(kLx, kLy, d*SS + s);
                        int idx = (int)((bits % 2147483647u) % (u32)degd);
                        float sc = __shfl_sync(0xffffffffu, myscore, idx);
                        int   t  = __shfl_sync(0xffffffffu, tail, idx);
                        u64 te = ((const u64*)(tail_emb + t*DIM))[lane];
                        fma2(accP, pack2(sc, sc), te);
                    }
                }
                ((u64*)(g_neigh + d*DIM))[lane] = accP;
            } else {
                ((u64*)(g_neigh + d*DIM))[lane] = 0ULL;
            }
        }
    }
    gsync();

    // ============ phase C: y = [drug_emb, neigh] @ Wc + bc ============
    {
        if (gtid == 0) { g_work = 0; g_ovfCnt = 0; }   // replay-state reset
        ulonglong2* wcp2 = (ulonglong2*)sh_raw;        // 32KB
        float* red = (float*)(sh_raw + 32768);         // 1KB
        u64*   xb  = (u64*)(sh_raw + 33792) + wid * 128;  // 1KB/warp
        for (int i = tid; i < 64*32; i += NTHR) {
            int i2 = i >> 5, o = i & 31;
            ulonglong2 v;
            v.x = pack2(Wc[(2*i2)*DIM + o],     Wc[(2*i2)*DIM + o + 32]);
            v.y = pack2(Wc[(2*i2 + 1)*DIM + o], Wc[(2*i2 + 1)*DIM + o + 32]);
            wcp2[i] = v;
        }
        __syncthreads();
        const int o = lane;
        const u64 bcv = pack2(bc[o], bc[o + 32]);
        float S0 = 0.f, S1 = 0.f, Q0 = 0.f, Q1 = 0.f;
        for (int r16 = bid; r16 < 625; r16 += NBLK) {   // 625*16 == ND exactly
            int row0 = r16*16 + wid;
            int row1 = row0 + 8;
            xb[lane]      = ((const u64*)(drug_emb + row0*DIM))[lane];
            xb[32 + lane] = ((const u64*)(g_neigh  + row0*DIM))[lane];
            xb[64 + lane] = ((const u64*)(drug_emb + row1*DIM))[lane];
            xb[96 + lane] = ((const u64*)(g_neigh  + row1*DIM))[lane];
            __syncwarp();
            u64 accR0 = bcv, accR1 = bcv;
            #pragma unroll
            for (int i2 = 0; i2 < 32; i2++) {
                ulonglong2 wv = wcp2[i2*32 + o];
                u64 dA = xb[i2];
                u64 dB = xb[64 + i2];
                float vA0, vA1, vB0, vB1;
                unpack2(dA, vA0, vA1);
                unpack2(dB, vB0, vB1);
                fma2(accR0, pack2(vA0, vA0), wv.x);
                fma2(accR0, pack2(vA1, vA1), wv.y);
                fma2(accR1, pack2(vB0, vB0), wv.x);
                fma2(accR1, pack2(vB1, vB1), wv.y);
            }
            #pragma unroll
            for (int i2 = 0; i2 < 32; i2++) {
                ulonglong2 wv = wcp2[(32 + i2)*32 + o];
                u64 dA = xb[32 + i2];
                u64 dB = xb[96 + i2];
                float vA0, vA1, vB0, vB1;
                unpack2(dA, vA0, vA1);
                unpack2(dB, vB0, vB1);
                fma2(accR0, pack2(vA0, vA0), wv.x);
                fma2(accR0, pack2(vA1, vA1), wv.y);
                fma2(accR1, pack2(vB0, vB0), wv.x);
                fma2(accR1, pack2(vB1, vB1), wv.y);
            }
            __syncwarp();
            float y00, y01, y10, y11;
            unpack2(accR0, y00, y01);
            unpack2(accR1, y10, y11);
            g_y[row0*DIM + o]      = y00;
            g_y[row0*DIM + 32 + o] = y01;
            g_y[row1*DIM + o]      = y10;
            g_y[row1*DIM + 32 + o] = y11;
            S0 += y00 + y10;
            S1 += y01 + y11;
            Q0 += y00*y00 + y10*y10;
            Q1 += y01*y01 + y11*y11;
        }
        red[tid] = S0;
        __syncthreads();
        if (tid < 32) { float s = 0.f;
            #pragma unroll
            for (int p = 0; p < 8; p++) s += red[p*32 + lane];
            g_psum[bid*DIM + lane] = s; }
        __syncthreads();
        red[tid] = S1;
        __syncthreads();
        if (tid < 32) { float s = 0.f;
            #pragma unroll
            for (int p = 0; p < 8; p++) s += red[p*32 + lane];
            g_psum[bid*DIM + 32 + lane] = s; }
        __syncthreads();
        red[tid] = Q0;
        __syncthreads();
        if (tid < 32) { float s = 0.f;
            #pragma unroll
            for (int p = 0; p < 8; p++) s += red[p*32 + lane];
            g_psq[bid*DIM + lane] = s; }
        __syncthreads();
        red[tid] = Q1;
        __syncthreads();
        if (tid < 32) { float s = 0.f;
            #pragma unroll
            for (int p = 0; p < 8; p++) s += red[p*32 + lane];
            g_psq[bid*DIM + 32 + lane] = s; }
    }
    gsync();

    // ============ phase D1: per-column BN stats (64 blocks) ============
    if (bid < DIM) {
        float* rs = (float*)sh_raw;
        float* rq = (float*)(sh_raw + 1024);
        const int col = bid;
        float s = 0.f, q = 0.f;
        for (int b = tid; b < NBLK; b += NTHR) {
            s += g_psum[b*DIM + col];
            q += g_psq[b*DIM + col];
        }
        rs[tid] = s; rq[tid] = q;
        __syncthreads();
        for (int ofs = NTHR/2; ofs > 0; ofs >>= 1) {
            if (tid < ofs) { rs[tid] += rs[tid + ofs]; rq[tid] += rq[tid + ofs]; }
            __syncthreads();
        }
        if (tid == 0) {
            float mean = rs[0] / (float)ND;
            float var  = rq[0] / (float)ND - mean * mean;
            float rstd = rsqrtf(var + 1e-5f);
            float gm = gamma[col];
            g_A[col] = gm * rstd;
            g_B[col] = beta[col] - gm * mean * rstd;
        }
    }
    gsync();

    // ============ phase D2: normalize + write + state reset ============
    {
        float* A = (float*)sh_raw;
        float* B = (float*)(sh_raw + 256);
        if (tid < DIM)        A[tid] = g_A[tid];
        else if (tid < 2*DIM) B[tid - DIM] = g_B[tid - DIM];
        __syncthreads();

        const float4* y4 = (const float4*)g_y;
        float4* o4 = (float4*)out;
        for (int t = gtid; t < ND*DIM/4; t += nth) {
            int c = (t*4) & 63;
            float4 v = y4[t];
            float4 r;
            r.x = fmaf(v.x, A[c+0], B[c+0]);
            r.y = fmaf(v.y, A[c+1], B[c+1]);
            r.z = fmaf(v.z, A[c+2], B[c+2]);
            r.w = fmaf(v.w, A[c+3], B[c+3]);
            o4[t] = r;
        }

        // replay-state reset: g_cursor must be zero for next replay's scatter
        for (int i = gtid; i < ND; i += nth) g_cursor[i] = 0;
    }
}

// ---------------------------------------------------------------- host
static void compute_keys(u32& k1x, u32& k1y, u32& kLx, u32& kLy) {
    u32 a, b, c, d, e, f;
    threefry(0u, 42u, 0u, 0u, a, b);   // k1 = split(key(42))[0]
    k1x = a; k1y = b;
    threefry(0u, 42u, 0u, 1u, c, d);   // k2 = split(key(42))[1]
    threefry(c, d, 0u, 1u, e, f);      // split(k2)[1]
    kLx = e; kLy = f;
}

extern "C" void kernel_launch(void* const* d_in, const int* in_sizes, int n_in,
                              void* d_out, int out_size) {
    const float* HF       = (const float*)d_in[0];
    const float* X        = (const float*)d_in[1];
    const float* drug_emb = (const float*)d_in[2];
    const float* rel_emb  = (const float*)d_in[3];
    const float* tail_emb = (const float*)d_in[4];
    const float* W1       = (const float*)d_in[5];
    const float* b1       = (const float*)d_in[6];
    const float* W2       = (const float*)d_in[7];
    const float* b2       = (const float*)d_in[8];
    const float* Wc       = (const float*)d_in[9];
    const float* bc       = (const float*)d_in[10];
    const float* gamma    = (const float*)d_in[11];
    const float* beta     = (const float*)d_in[12];
    const int*   DKG      = (const int*)d_in[13];
    int E    = in_sizes[13] / 3;
    int hf_n = in_sizes[0];
    int x_n  = in_sizes[1];
    float* out = (float*)d_out;

    u32 k1x, k1y, kLx, kLy;
    compute_keys(k1x, k1y, kLx, kLy);

    scatter_kernel<<<ABLK, ATHR>>>(DKG, HF, X, W2, b2, out, E, hf_n, x_n, k1x, k1y);
    mega_kernel<<<NBLK, NTHR>>>(DKG, drug_emb, rel_emb, tail_emb, W1, b1,
                                Wc, bc, gamma, beta, out + hf_n, kLx, kLy);
}